// round 2
// baseline (speedup 1.0000x reference)
#include <cuda_runtime.h>
#include <math.h>

#define Bn   4096
#define Lnn  4096
#define Hn   2048
#define Dn   128
#define D2n  256

// ---------------- scratch (static device globals; no runtime alloc) ----------------
__device__ float g_Xn[(size_t)Bn * Hn];     // LN output (reused q then r)
__device__ float g_Hb[(size_t)Bn * D2n];    // hidden after GELU (reused)
__device__ float g_Zq[(size_t)Bn * Dn];
__device__ float g_Zr[(size_t)Lnn * Dn];
__device__ float g_Rbar[(size_t)Bn * Dn];
__device__ float g_ent[Bn];

// ---------------- LayerNorm over H=2048, one row per block ----------------
__global__ void ln_kernel(const float* __restrict__ x, const float* __restrict__ g,
                          const float* __restrict__ b, float* __restrict__ out) {
    __shared__ float s[Hn];
    __shared__ float red[256];
    int row = blockIdx.x, tid = threadIdx.x;
    const float* xr = x + (size_t)row * Hn;
    float lsum = 0.f;
    for (int k = tid; k < Hn; k += 256) { float v = xr[k]; s[k] = v; lsum += v; }
    red[tid] = lsum; __syncthreads();
    for (int o = 128; o > 0; o >>= 1) { if (tid < o) red[tid] += red[tid + o]; __syncthreads(); }
    float mean = red[0] * (1.f / Hn);
    __syncthreads();
    float lsq = 0.f;
    for (int k = tid; k < Hn; k += 256) { float d = s[k] - mean; lsq += d * d; }
    red[tid] = lsq; __syncthreads();
    for (int o = 128; o > 0; o >>= 1) { if (tid < o) red[tid] += red[tid + o]; __syncthreads(); }
    float rstd = rsqrtf(red[0] * (1.f / Hn) + 1e-5f);
    float* orow = out + (size_t)row * Hn;
    for (int k = tid; k < Hn; k += 256) orow[k] = (s[k] - mean) * rstd * g[k] + b[k];
}

// ---------------- GEMM1 + GELU: C[M,256] = A[M,2048] @ W^T + bias, gelu ----------------
// BM=BN=64, BK=16, 16x16 threads, 4x4 microtile
__global__ void gemm1_gelu(const float* __restrict__ A, const float* __restrict__ W,
                           const float* __restrict__ bias, float* __restrict__ C) {
    __shared__ float As[16][64];
    __shared__ float Bs[16][64];
    int tid = threadIdx.x;
    int tx = tid & 15, ty = tid >> 4;
    int m0 = blockIdx.y * 64, n0 = blockIdx.x * 64;
    float acc[4][4] = {};
    int lr = tid >> 2, lk = (tid & 3) * 4;
    const float* Aptr = A + (size_t)(m0 + lr) * Hn + lk;
    const float* Wptr = W + (size_t)(n0 + lr) * Hn + lk;
    for (int k0 = 0; k0 < Hn; k0 += 16) {
        float4 a4 = *(const float4*)(Aptr + k0);
        float4 w4 = *(const float4*)(Wptr + k0);
        As[lk + 0][lr] = a4.x; As[lk + 1][lr] = a4.y; As[lk + 2][lr] = a4.z; As[lk + 3][lr] = a4.w;
        Bs[lk + 0][lr] = w4.x; Bs[lk + 1][lr] = w4.y; Bs[lk + 2][lr] = w4.z; Bs[lk + 3][lr] = w4.w;
        __syncthreads();
#pragma unroll
        for (int k = 0; k < 16; k++) {
            float4 av = *(const float4*)&As[k][ty * 4];
            float4 bv = *(const float4*)&Bs[k][tx * 4];
            float aa[4] = {av.x, av.y, av.z, av.w};
            float bb[4] = {bv.x, bv.y, bv.z, bv.w};
#pragma unroll
            for (int i = 0; i < 4; i++)
#pragma unroll
                for (int j = 0; j < 4; j++) acc[i][j] += aa[i] * bb[j];
        }
        __syncthreads();
    }
#pragma unroll
    for (int i = 0; i < 4; i++) {
        int m = m0 + ty * 4 + i;
#pragma unroll
        for (int j = 0; j < 4; j++) {
            int n = n0 + tx * 4 + j;
            float v = acc[i][j] + bias[n];
            v = 0.5f * v * (1.f + erff(v * 0.7071067811865475f));
            C[(size_t)m * D2n + n] = v;
        }
    }
}

// ---------------- GEMM2 + l2norm: Z[r,128] = l2n(H[r,256] @ W2^T + b2) ----------------
// 4 rows per block, 128 threads (one output column per thread)
__global__ void gemm2_l2n(const float* __restrict__ Hin, const float* __restrict__ W2,
                          const float* __restrict__ b2, float* __restrict__ Z) {
    __shared__ float hs[4][D2n];
    __shared__ float red[128];
    int r0 = blockIdx.x * 4, tid = threadIdx.x;
    for (int i = tid; i < 4 * D2n; i += 128) hs[i >> 8][i & 255] = Hin[(size_t)r0 * D2n + i];
    __syncthreads();
    float bj = b2[tid];
    float acc[4] = {bj, bj, bj, bj};
    const float* wrow = W2 + (size_t)tid * D2n;
    for (int k = 0; k < D2n; k += 4) {
        float4 w4 = *(const float4*)(wrow + k);
#pragma unroll
        for (int r = 0; r < 4; r++) {
            float4 h4 = *(const float4*)&hs[r][k];
            acc[r] += h4.x * w4.x + h4.y * w4.y + h4.z * w4.z + h4.w * w4.w;
        }
    }
    for (int r = 0; r < 4; r++) {
        __syncthreads();
        red[tid] = acc[r] * acc[r]; __syncthreads();
        for (int o = 64; o > 0; o >>= 1) { if (tid < o) red[tid] += red[tid + o]; __syncthreads(); }
        float nrm = fmaxf(sqrtf(red[0]), 1e-12f);
        Z[(size_t)(r0 + r) * Dn + tid] = acc[r] / nrm;
    }
}

// ---------------- Fused attention: softmax (no max needed, |s|<0.089), r_bar, entropy ----------------
#define BQ 16
#define BL 64
#define ZPAD 132
__global__ void attn_kernel(const float* __restrict__ Zq, const float* __restrict__ Zr,
                            float* __restrict__ Rbar, float* __restrict__ ent) {
    __shared__ float zqs[BQ][Dn];
    __shared__ float zrs[BL][ZPAD];
    __shared__ float ps[BQ][BL];
    int q0 = blockIdx.x * BQ;
    int tid = threadIdx.x;
    int q = tid >> 4;    // 0..15 query within block
    int j = tid & 15;    // 0..15 lane within q-group
    for (int i = tid; i < BQ * Dn; i += 256) zqs[i >> 7][i & 127] = Zq[(size_t)q0 * Dn + i];
    float Osum[8] = {};
    float zsum = 0.f, tsum = 0.f;
    const float scale = 0.08838834764831845f;  // 1/sqrt(128)
    for (int l0 = 0; l0 < Lnn; l0 += BL) {
        __syncthreads();
        for (int i = tid; i < BL * (Dn / 4); i += 256) {
            int lr = i >> 5;
            int c4 = (i & 31) * 4;
            float4 v = *(const float4*)&Zr[(size_t)(l0 + lr) * Dn + c4];
            zrs[lr][c4 + 0] = v.x; zrs[lr][c4 + 1] = v.y; zrs[lr][c4 + 2] = v.z; zrs[lr][c4 + 3] = v.w;
        }
        __syncthreads();
        // scores: thread computes l = j + 16*i, i = 0..3
        float sc[4] = {};
#pragma unroll 8
        for (int d = 0; d < Dn; d += 4) {
            float4 a4 = *(const float4*)&zqs[q][d];
#pragma unroll
            for (int i = 0; i < 4; i++) {
                float4 z = *(const float4*)&zrs[j + 16 * i][d];
                sc[i] += a4.x * z.x + a4.y * z.y + a4.z * z.z + a4.w * z.w;
            }
        }
#pragma unroll
        for (int i = 0; i < 4; i++) {
            float s = sc[i] * scale;
            float p = __expf(s);
            zsum += p; tsum += p * s;
            ps[q][j + 16 * i] = p;
        }
        __syncthreads();
        // PV: thread owns (q, d0 = j*8 .. +7)
        int d0 = j * 8;
#pragma unroll 8
        for (int l = 0; l < BL; l++) {
            float p = ps[q][l];
            float4 z0 = *(const float4*)&zrs[l][d0];
            float4 z1 = *(const float4*)&zrs[l][d0 + 4];
            Osum[0] += p * z0.x; Osum[1] += p * z0.y; Osum[2] += p * z0.z; Osum[3] += p * z0.w;
            Osum[4] += p * z1.x; Osum[5] += p * z1.y; Osum[6] += p * z1.z; Osum[7] += p * z1.w;
        }
    }
    // reduce zsum/tsum over the 16 lanes of this q-group
#pragma unroll
    for (int o = 1; o < 16; o <<= 1) {
        zsum += __shfl_xor_sync(0xffffffffu, zsum, o, 16);
        tsum += __shfl_xor_sync(0xffffffffu, tsum, o, 16);
    }
    if (j == 0) ent[q0 + q] = logf(zsum) - tsum / zsum;
    float sq = 0.f;
#pragma unroll
    for (int i = 0; i < 8; i++) sq += Osum[i] * Osum[i];
#pragma unroll
    for (int o = 1; o < 16; o <<= 1) sq += __shfl_xor_sync(0xffffffffu, sq, o, 16);
    float rn = 1.f / fmaxf(sqrtf(sq), 1e-12f);
    int d0 = j * 8;
#pragma unroll
    for (int i = 0; i < 8; i++) Rbar[(size_t)(q0 + q) * Dn + d0 + i] = Osum[i] * rn;
}

// ---------------- Final: dec MLP + scalar heads. 8 rows per block, 128 threads ----------------
__global__ void final_kernel(const float* __restrict__ Zq, const float* __restrict__ Rbar,
                             const float* __restrict__ ent,
                             const float* __restrict__ gd, const float* __restrict__ bd,
                             const float* __restrict__ W1d, const float* __restrict__ b1d,
                             const float* __restrict__ W2d, const float* __restrict__ b2d,
                             const float* __restrict__ beta, const float* __restrict__ Wlen,
                             const float* __restrict__ blen, float* __restrict__ out) {
    __shared__ float raw[8][D2n];
    __shared__ float nrm[8][D2n];
    __shared__ float part[8][128];
    __shared__ float coss[8];
    int r0 = blockIdx.x * 8, tid = threadIdx.x;
    for (int i = tid; i < 8 * Dn; i += 128) {
        int r = i >> 7, d = i & 127;
        raw[r][d] = Zq[(size_t)(r0 + r) * Dn + d];
        raw[r][128 + d] = Rbar[(size_t)(r0 + r) * Dn + d];
    }
    __syncthreads();
    int w = tid >> 5, lane = tid & 31;
#pragma unroll
    for (int rr = 0; rr < 2; rr++) {
        int r = 2 * w + rr;
        float cs = 0.f, sm = 0.f;
        for (int k = lane; k < D2n; k += 32) sm += raw[r][k];
        for (int k = lane; k < Dn; k += 32) cs += raw[r][k] * raw[r][128 + k];
#pragma unroll
        for (int o = 16; o > 0; o >>= 1) { sm += __shfl_xor_sync(~0u, sm, o); cs += __shfl_xor_sync(~0u, cs, o); }
        float mean = sm * (1.f / D2n);
        float vq = 0.f;
        for (int k = lane; k < D2n; k += 32) { float d = raw[r][k] - mean; vq += d * d; }
#pragma unroll
        for (int o = 16; o > 0; o >>= 1) vq += __shfl_xor_sync(~0u, vq, o);
        float rstd = rsqrtf(vq * (1.f / D2n) + 1e-5f);
        for (int k = lane; k < D2n; k += 32) nrm[r][k] = (raw[r][k] - mean) * rstd * gd[k] + bd[k];
        if (lane == 0) coss[r] = cs;
    }
    __syncthreads();
    float b1 = b1d[tid];
    float acc[8] = {b1, b1, b1, b1, b1, b1, b1, b1};
    const float* wrow = W1d + (size_t)tid * D2n;
    for (int k = 0; k < D2n; k += 4) {
        float4 w4 = *(const float4*)(wrow + k);
#pragma unroll
        for (int r = 0; r < 8; r++) {
            float4 h4 = *(const float4*)&nrm[r][k];
            acc[r] += h4.x * w4.x + h4.y * w4.y + h4.z * w4.z + h4.w * w4.w;
        }
    }
    float w2 = W2d[tid];
#pragma unroll
    for (int r = 0; r < 8; r++) {
        float v = acc[r];
        v = 0.5f * v * (1.f + erff(v * 0.7071067811865475f));
        part[r][tid] = v * w2;
    }
    __syncthreads();
#pragma unroll
    for (int rr = 0; rr < 2; rr++) {
        int r = 2 * w + rr;
        float s = 0.f;
        for (int k = lane; k < 128; k += 32) s += part[r][k];
#pragma unroll
        for (int o = 16; o > 0; o >>= 1) s += __shfl_xor_sync(~0u, s, o);
        if (lane == 0) {
            float raw_logit = s + b2d[0];
            float u = ent[r0 + r] * (1.f / logf((float)Lnn));
            float cs = coss[r];
            float dl = Wlen[0] * cs + Wlen[1] * u + blen[0];
            float lf = tanhf(dl);
            float dt = beta[0] * u + beta[1] * lf;
            dt = fminf(fmaxf(dt, -0.5f), 0.5f);
            out[r0 + r] = raw_logit;
            out[Bn + r0 + r] = dt;
        }
    }
}

// ---------------- host launcher ----------------
extern "C" void kernel_launch(void* const* d_in, const int* in_sizes, int n_in,
                              void* d_out, int out_size) {
    const float* q     = (const float*)d_in[0];
    const float* R     = (const float*)d_in[1];
    const float* lnqg  = (const float*)d_in[2];
    const float* lnqb  = (const float*)d_in[3];
    const float* W1q   = (const float*)d_in[4];
    const float* b1q   = (const float*)d_in[5];
    const float* W2q   = (const float*)d_in[6];
    const float* b2q   = (const float*)d_in[7];
    const float* lnrg  = (const float*)d_in[8];
    const float* lnrb  = (const float*)d_in[9];
    const float* W1r   = (const float*)d_in[10];
    const float* b1r   = (const float*)d_in[11];
    const float* W2r   = (const float*)d_in[12];
    const float* b2r   = (const float*)d_in[13];
    const float* lndg  = (const float*)d_in[14];
    const float* lndb  = (const float*)d_in[15];
    const float* W1d   = (const float*)d_in[16];
    const float* b1d   = (const float*)d_in[17];
    const float* W2d   = (const float*)d_in[18];
    const float* b2d   = (const float*)d_in[19];
    const float* beta  = (const float*)d_in[20];
    const float* Wlen  = (const float*)d_in[21];
    const float* blen  = (const float*)d_in[22];
    float* out = (float*)d_out;

    float *xn, *hb, *zq, *zr, *rb, *en;
    cudaGetSymbolAddress((void**)&xn, g_Xn);
    cudaGetSymbolAddress((void**)&hb, g_Hb);
    cudaGetSymbolAddress((void**)&zq, g_Zq);
    cudaGetSymbolAddress((void**)&zr, g_Zr);
    cudaGetSymbolAddress((void**)&rb, g_Rbar);
    cudaGetSymbolAddress((void**)&en, g_ent);

    dim3 g1(D2n / 64, Bn / 64);

    // q path
    ln_kernel<<<Bn, 256>>>(q, lnqg, lnqb, xn);
    gemm1_gelu<<<g1, 256>>>(xn, W1q, b1q, hb);
    gemm2_l2n<<<Bn / 4, 128>>>(hb, W2q, b2q, zq);
    // r path (reuses xn/hb scratch; same-stream ordering makes this safe)
    ln_kernel<<<Lnn, 256>>>(R, lnrg, lnrb, xn);
    gemm1_gelu<<<g1, 256>>>(xn, W1r, b1r, hb);
    gemm2_l2n<<<Lnn / 4, 128>>>(hb, W2r, b2r, zr);
    // attention + entropy + r_bar
    attn_kernel<<<Bn / BQ, 256>>>(zq, zr, rb, en);
    // decision MLP + scalar heads
    final_kernel<<<Bn / 8, 128>>>(zq, rb, en, lndg, lndb, W1d, b1d, W2d, b2d,
                                  beta, Wlen, blen, out);
}

// round 5
// speedup vs baseline: 1.9250x; 1.9250x over previous
#include <cuda_runtime.h>
#include <math.h>
#include <stdint.h>

#define Bn   4096
#define Lnn  4096
#define Hn   2048
#define Dn   128
#define D2n  256

// ---------------- scratch (static device globals; no runtime alloc) ----------------
__device__ float g_Xn[(size_t)Bn * Hn];
__device__ float g_Hb[(size_t)Bn * D2n];
__device__ float g_Zq[(size_t)Bn * Dn];
__device__ float g_Zr[(size_t)Lnn * Dn];
__device__ float g_Rbar[(size_t)Bn * Dn];
__device__ float g_ent[Bn];

// single dynamic-smem symbol shared by all kernels (cast locally)
extern __shared__ char dynsm[];

// ================= helpers =================
__device__ __forceinline__ uint32_t f2tf32(float f) {
    uint32_t r;
    asm("cvt.rna.tf32.f32 %0, %1;" : "=r"(r) : "f"(f));
    return r;
}

typedef unsigned long long u64t;
__device__ __forceinline__ u64t pack2(float x, float y) {
    u64t r;
    asm("mov.b64 %0, {%1, %2};" : "=l"(r) : "r"(__float_as_uint(x)), "r"(__float_as_uint(y)));
    return r;
}
__device__ __forceinline__ void unpack2(u64t v, float& x, float& y) {
    uint32_t a, b;
    asm("mov.b64 {%0, %1}, %2;" : "=r"(a), "=r"(b) : "l"(v));
    x = __uint_as_float(a); y = __uint_as_float(b);
}
__device__ __forceinline__ u64t fma2(u64t a, u64t b, u64t c) {
    u64t d;
    asm("fma.rn.f32x2 %0, %1, %2, %3;" : "=l"(d) : "l"(a), "l"(b), "l"(c));
    return d;
}

__device__ __forceinline__ void mma_tf32(float* c, uint32_t a0, uint32_t a1, uint32_t a2, uint32_t a3,
                                         uint32_t b0, uint32_t b1) {
    asm volatile(
        "mma.sync.aligned.m16n8k8.row.col.f32.tf32.tf32.f32 "
        "{%0,%1,%2,%3}, {%4,%5,%6,%7}, {%8,%9}, {%0,%1,%2,%3};"
        : "+f"(c[0]), "+f"(c[1]), "+f"(c[2]), "+f"(c[3])
        : "r"(a0), "r"(a1), "r"(a2), "r"(a3), "r"(b0), "r"(b1));
}

// ---------------- LayerNorm over H=2048, one row per block, float4 ----------------
__global__ void ln_kernel(const float* __restrict__ x, const float* __restrict__ g,
                          const float* __restrict__ b, float* __restrict__ out) {
    __shared__ float4 s4[Hn / 4];
    __shared__ float red[256];
    int row = blockIdx.x, tid = threadIdx.x;
    const float4* xr = (const float4*)(x + (size_t)row * Hn);
    float lsum = 0.f;
    for (int k = tid; k < Hn / 4; k += 256) {
        float4 v = xr[k]; s4[k] = v; lsum += v.x + v.y + v.z + v.w;
    }
    red[tid] = lsum; __syncthreads();
    for (int o = 128; o > 0; o >>= 1) { if (tid < o) red[tid] += red[tid + o]; __syncthreads(); }
    float mean = red[0] * (1.f / Hn);
    __syncthreads();
    float lsq = 0.f;
    for (int k = tid; k < Hn / 4; k += 256) {
        float4 v = s4[k];
        float d0 = v.x - mean, d1 = v.y - mean, d2 = v.z - mean, d3 = v.w - mean;
        lsq += d0 * d0 + d1 * d1 + d2 * d2 + d3 * d3;
    }
    red[tid] = lsq; __syncthreads();
    for (int o = 128; o > 0; o >>= 1) { if (tid < o) red[tid] += red[tid + o]; __syncthreads(); }
    float rstd = rsqrtf(red[0] * (1.f / Hn) + 1e-5f);
    float4* orow = (float4*)(out + (size_t)row * Hn);
    const float4* g4 = (const float4*)g;
    const float4* b4 = (const float4*)b;
    for (int k = tid; k < Hn / 4; k += 256) {
        float4 v = s4[k], gg = g4[k], bb = b4[k], r;
        r.x = (v.x - mean) * rstd * gg.x + bb.x;
        r.y = (v.y - mean) * rstd * gg.y + bb.y;
        r.z = (v.z - mean) * rstd * gg.z + bb.z;
        r.w = (v.w - mean) * rstd * gg.w + bb.w;
        orow[k] = r;
    }
}

// ---------------- GEMM1 via mma.sync tf32 + GELU ----------------
// C[M,256] = gelu(A[M,2048] @ W[256,2048]^T + bias)
// BM=128, BN=64, BK=32; 256 threads = 8 warps (4 along M x 2 along N), warptile 32x32.
#define G1_LDA 136
#define G1_LDB 72
#define G1_AS  (32 * G1_LDA)     // 4352 u32 per A buffer
#define G1_BS  (32 * G1_LDB)     // 2304 u32 per B buffer
#define G1_SMEMF (2 * G1_AS + 2 * G1_BS)
#define G1_SMEM  (G1_SMEMF * 4)  // 53248 bytes

__global__ void __launch_bounds__(256, 1) gemm1_mma(const float* __restrict__ A, const float* __restrict__ W,
                                                    const float* __restrict__ bias, float* __restrict__ C) {
    uint32_t* sm = (uint32_t*)dynsm;
    uint32_t* As[2] = { sm, sm + G1_AS };
    uint32_t* Bs[2] = { sm + 2 * G1_AS, sm + 2 * G1_AS + G1_BS };

    int tid = threadIdx.x;
    int wid = tid >> 5, lane = tid & 31;
    int wm = wid & 3, wn = wid >> 2;
    int g = lane >> 2, tig = lane & 3;
    int m0 = blockIdx.y * 128, n0 = blockIdx.x * 64;

    // staging: A rows m0 + (tid&127), half h=(tid>>7) handles k-floats [h*16, h*16+16)
    int am = tid & 127, h = tid >> 7;
    const float4* Ag = (const float4*)(A + (size_t)(m0 + am) * Hn);
    // B rows n0 + (tid&63), quarter bh=(tid>>6) handles 2 float4
    int bn = tid & 63, bh = tid >> 6;
    const float4* Wg = (const float4*)(W + (size_t)(n0 + bn) * Hn);

    float acc[2][4][4] = {};
    float4 stA[4], stB[2];

    const int NT = Hn / 32;  // 64

    // load tile 0
#pragma unroll
    for (int j = 0; j < 4; j++) stA[j] = Ag[h * 4 + j];
#pragma unroll
    for (int j = 0; j < 2; j++) stB[j] = Wg[bh * 2 + j];
    // store tile 0
#pragma unroll
    for (int j = 0; j < 4; j++) {
        int k4 = h * 16 + j * 4;
        const float* f = (const float*)&stA[j];
#pragma unroll
        for (int u = 0; u < 4; u++) As[0][(k4 + u) * G1_LDA + am] = f2tf32(f[u]);
    }
#pragma unroll
    for (int j = 0; j < 2; j++) {
        int k4 = (bh * 2 + j) * 4;
        const float* f = (const float*)&stB[j];
#pragma unroll
        for (int u = 0; u < 4; u++) Bs[0][(k4 + u) * G1_LDB + bn] = f2tf32(f[u]);
    }
    __syncthreads();

    for (int t = 0; t < NT; t++) {
        int cur = t & 1;
        if (t + 1 < NT) {
#pragma unroll
            for (int j = 0; j < 4; j++) stA[j] = Ag[(t + 1) * 8 + h * 4 + j];
#pragma unroll
            for (int j = 0; j < 2; j++) stB[j] = Wg[(t + 1) * 8 + bh * 2 + j];
        }
        const uint32_t* Ab = As[cur];
        const uint32_t* Bb = Bs[cur];
#pragma unroll
        for (int ks = 0; ks < 4; ks++) {
            int k = ks * 8;
            uint32_t bf[4][2];
#pragma unroll
            for (int nt = 0; nt < 4; nt++) {
                int nc = wn * 32 + nt * 8 + g;
                bf[nt][0] = Bb[(k + tig) * G1_LDB + nc];
                bf[nt][1] = Bb[(k + tig + 4) * G1_LDB + nc];
            }
#pragma unroll
            for (int mt = 0; mt < 2; mt++) {
                int mr = wm * 32 + mt * 16 + g;
                uint32_t a0 = Ab[(k + tig) * G1_LDA + mr];
                uint32_t a1 = Ab[(k + tig) * G1_LDA + mr + 8];
                uint32_t a2 = Ab[(k + tig + 4) * G1_LDA + mr];
                uint32_t a3 = Ab[(k + tig + 4) * G1_LDA + mr + 8];
#pragma unroll
                for (int nt = 0; nt < 4; nt++)
                    mma_tf32(acc[mt][nt], a0, a1, a2, a3, bf[nt][0], bf[nt][1]);
            }
        }
        if (t + 1 < NT) {
            int nxt = cur ^ 1;
#pragma unroll
            for (int j = 0; j < 4; j++) {
                int k4 = h * 16 + j * 4;
                const float* f = (const float*)&stA[j];
#pragma unroll
                for (int u = 0; u < 4; u++) As[nxt][(k4 + u) * G1_LDA + am] = f2tf32(f[u]);
            }
#pragma unroll
            for (int j = 0; j < 2; j++) {
                int k4 = (bh * 2 + j) * 4;
                const float* f = (const float*)&stB[j];
#pragma unroll
                for (int u = 0; u < 4; u++) Bs[nxt][(k4 + u) * G1_LDB + bn] = f2tf32(f[u]);
            }
        }
        __syncthreads();
    }

    // epilogue: fragment c0:(g, 2tig), c1:(g, 2tig+1), c2:(g+8, 2tig), c3:(g+8, 2tig+1)
#pragma unroll
    for (int mt = 0; mt < 2; mt++) {
#pragma unroll
        for (int nt = 0; nt < 4; nt++) {
            int n = n0 + wn * 32 + nt * 8 + 2 * tig;
            float bv0 = bias[n], bv1 = bias[n + 1];
#pragma unroll
            for (int rr = 0; rr < 2; rr++) {
                int m = m0 + wm * 32 + mt * 16 + g + rr * 8;
                float v0 = acc[mt][nt][rr * 2 + 0] + bv0;
                float v1 = acc[mt][nt][rr * 2 + 1] + bv1;
                v0 = 0.5f * v0 * (1.f + erff(v0 * 0.7071067811865475f));
                v1 = 0.5f * v1 * (1.f + erff(v1 * 0.7071067811865475f));
                float2 o = {v0, v1};
                *(float2*)(C + (size_t)m * D2n + n) = o;
            }
        }
    }
}

// ---------------- GEMM2 + l2norm: Z[r,128] = l2n(H[r,256] @ W2^T + b2) ----------------
__global__ void gemm2_l2n(const float* __restrict__ Hin, const float* __restrict__ W2,
                          const float* __restrict__ b2, float* __restrict__ Z) {
    __shared__ float hs[4][D2n];
    __shared__ float red[128];
    int r0 = blockIdx.x * 4, tid = threadIdx.x;
    for (int i = tid; i < 4 * D2n; i += 128) hs[i >> 8][i & 255] = Hin[(size_t)r0 * D2n + i];
    __syncthreads();
    float bj = b2[tid];
    float acc[4] = {bj, bj, bj, bj};
    const float* wrow = W2 + (size_t)tid * D2n;
    for (int k = 0; k < D2n; k += 4) {
        float4 w4 = *(const float4*)(wrow + k);
#pragma unroll
        for (int r = 0; r < 4; r++) {
            float4 h4 = *(const float4*)&hs[r][k];
            acc[r] += h4.x * w4.x + h4.y * w4.y + h4.z * w4.z + h4.w * w4.w;
        }
    }
    for (int r = 0; r < 4; r++) {
        __syncthreads();
        red[tid] = acc[r] * acc[r]; __syncthreads();
        for (int o = 64; o > 0; o >>= 1) { if (tid < o) red[tid] += red[tid + o]; __syncthreads(); }
        float nrm = fmaxf(sqrtf(red[0]), 1e-12f);
        Z[(size_t)(r0 + r) * Dn + tid] = acc[r] / nrm;
    }
}

// ---------------- Attention v2: BQ=32, BL=64, 128 threads, 4q x 4l microtile, f32x2 FMA ----------------
#define AQ 32
#define AL 64
#define ZST 132
#define ATTN_SMEM ((AQ * Dn + AL * ZST + AQ * AL) * 4)
__global__ void __launch_bounds__(128, 1) attn_kernel(const float* __restrict__ Zq, const float* __restrict__ Zr,
                                                      float* __restrict__ Rbar, float* __restrict__ ent) {
    float* smf = (float*)dynsm;
    float* zq_s = smf;                  // 32 x 128
    float* zr_s = smf + AQ * Dn;        // 64 x 132
    float* ps   = zr_s + AL * ZST;      // 32 x 64
    int tid = threadIdx.x;
    int q0 = blockIdx.x * AQ;
    int qb = (tid >> 4) * 4;
    int jj = tid & 15;

    for (int i = tid; i < AQ * Dn / 4; i += 128)
        ((float4*)zq_s)[i] = ((const float4*)(Zq + (size_t)q0 * Dn))[i];

    u64t O2[4][4] = {};
    float zs[4] = {}, ts[4] = {};
    const float scale = 0.08838834764831845f;  // 1/sqrt(128)

    for (int l0 = 0; l0 < Lnn; l0 += AL) {
        __syncthreads();
        for (int i = tid; i < AL * (Dn / 4); i += 128) {
            int lr = i >> 5, c4 = i & 31;
            *(float4*)&zr_s[lr * ZST + c4 * 4] = ((const float4*)(Zr + (size_t)(l0 + lr) * Dn))[c4];
        }
        __syncthreads();
        u64t acc[4][4] = {};
#pragma unroll 4
        for (int d = 0; d < Dn; d += 4) {
            u64t alo[4], ahi[4];
#pragma unroll
            for (int i = 0; i < 4; i++) {
                float4 av = *(const float4*)&zq_s[(qb + i) * Dn + d];
                alo[i] = pack2(av.x, av.y); ahi[i] = pack2(av.z, av.w);
            }
#pragma unroll
            for (int j = 0; j < 4; j++) {
                float4 zv = *(const float4*)&zr_s[(jj + 16 * j) * ZST + d];
                u64t zlo = pack2(zv.x, zv.y), zhi = pack2(zv.z, zv.w);
#pragma unroll
                for (int i = 0; i < 4; i++) {
                    acc[i][j] = fma2(alo[i], zlo, acc[i][j]);
                    acc[i][j] = fma2(ahi[i], zhi, acc[i][j]);
                }
            }
        }
#pragma unroll
        for (int i = 0; i < 4; i++)
#pragma unroll
            for (int j = 0; j < 4; j++) {
                float lo, hi; unpack2(acc[i][j], lo, hi);
                float s = (lo + hi) * scale;
                float p = __expf(s);
                zs[i] += p; ts[i] += p * s;
                ps[(qb + i) * AL + jj + 16 * j] = p;
            }
        __syncthreads();
        int d0 = jj * 8;
#pragma unroll 4
        for (int l = 0; l < AL; l++) {
            float4 z0 = *(const float4*)&zr_s[l * ZST + d0];
            float4 z1 = *(const float4*)&zr_s[l * ZST + d0 + 4];
            u64t za = pack2(z0.x, z0.y), zb = pack2(z0.z, z0.w);
            u64t zc = pack2(z1.x, z1.y), zd = pack2(z1.z, z1.w);
#pragma unroll
            for (int i = 0; i < 4; i++) {
                float p = ps[(qb + i) * AL + l];
                u64t pp = pack2(p, p);
                O2[i][0] = fma2(pp, za, O2[i][0]);
                O2[i][1] = fma2(pp, zb, O2[i][1]);
                O2[i][2] = fma2(pp, zc, O2[i][2]);
                O2[i][3] = fma2(pp, zd, O2[i][3]);
            }
        }
    }
#pragma unroll
    for (int i = 0; i < 4; i++) {
#pragma unroll
        for (int o = 1; o < 16; o <<= 1) {
            zs[i] += __shfl_xor_sync(0xffffffffu, zs[i], o, 16);
            ts[i] += __shfl_xor_sync(0xffffffffu, ts[i], o, 16);
        }
    }
    if (jj == 0) {
#pragma unroll
        for (int i = 0; i < 4; i++) ent[q0 + qb + i] = logf(zs[i]) - ts[i] / zs[i];
    }
#pragma unroll
    for (int i = 0; i < 4; i++) {
        float o[8];
        unpack2(O2[i][0], o[0], o[1]); unpack2(O2[i][1], o[2], o[3]);
        unpack2(O2[i][2], o[4], o[5]); unpack2(O2[i][3], o[6], o[7]);
        float sq = 0.f;
#pragma unroll
        for (int k = 0; k < 8; k++) sq += o[k] * o[k];
#pragma unroll
        for (int os = 1; os < 16; os <<= 1) sq += __shfl_xor_sync(0xffffffffu, sq, os, 16);
        float rn = 1.f / fmaxf(sqrtf(sq), 1e-12f);
        float* dst = Rbar + (size_t)(q0 + qb + i) * Dn + jj * 8;
        float4 v0 = {o[0] * rn, o[1] * rn, o[2] * rn, o[3] * rn};
        float4 v1 = {o[4] * rn, o[5] * rn, o[6] * rn, o[7] * rn};
        *(float4*)dst = v0;
        *(float4*)(dst + 4) = v1;
    }
}

// ---------------- Final: dec MLP + scalar heads. 8 rows per block, 128 threads ----------------
__global__ void final_kernel(const float* __restrict__ Zq, const float* __restrict__ Rbar,
                             const float* __restrict__ ent,
                             const float* __restrict__ gd, const float* __restrict__ bd,
                             const float* __restrict__ W1d, const float* __restrict__ b1d,
                             const float* __restrict__ W2d, const float* __restrict__ b2d,
                             const float* __restrict__ beta, const float* __restrict__ Wlen,
                             const float* __restrict__ blen, float* __restrict__ out) {
    __shared__ float raw[8][D2n];
    __shared__ float nrm[8][D2n];
    __shared__ float part[8][128];
    __shared__ float coss[8];
    int r0 = blockIdx.x * 8, tid = threadIdx.x;
    for (int i = tid; i < 8 * Dn; i += 128) {
        int r = i >> 7, d = i & 127;
        raw[r][d] = Zq[(size_t)(r0 + r) * Dn + d];
        raw[r][128 + d] = Rbar[(size_t)(r0 + r) * Dn + d];
    }
    __syncthreads();
    int w = tid >> 5, lane = tid & 31;
#pragma unroll
    for (int rr = 0; rr < 2; rr++) {
        int r = 2 * w + rr;
        float cs = 0.f, smv = 0.f;
        for (int k = lane; k < D2n; k += 32) smv += raw[r][k];
        for (int k = lane; k < Dn; k += 32) cs += raw[r][k] * raw[r][128 + k];
#pragma unroll
        for (int o = 16; o > 0; o >>= 1) { smv += __shfl_xor_sync(~0u, smv, o); cs += __shfl_xor_sync(~0u, cs, o); }
        float mean = smv * (1.f / D2n);
        float vq = 0.f;
        for (int k = lane; k < D2n; k += 32) { float d = raw[r][k] - mean; vq += d * d; }
#pragma unroll
        for (int o = 16; o > 0; o >>= 1) vq += __shfl_xor_sync(~0u, vq, o);
        float rstd = rsqrtf(vq * (1.f / D2n) + 1e-5f);
        for (int k = lane; k < D2n; k += 32) nrm[r][k] = (raw[r][k] - mean) * rstd * gd[k] + bd[k];
        if (lane == 0) coss[r] = cs;
    }
    __syncthreads();
    float b1 = b1d[tid];
    float acc[8] = {b1, b1, b1, b1, b1, b1, b1, b1};
    const float* wrow = W1d + (size_t)tid * D2n;
    for (int k = 0; k < D2n; k += 4) {
        float4 w4 = *(const float4*)(wrow + k);
#pragma unroll
        for (int r = 0; r < 8; r++) {
            float4 h4 = *(const float4*)&nrm[r][k];
            acc[r] += h4.x * w4.x + h4.y * w4.y + h4.z * w4.z + h4.w * w4.w;
        }
    }
    float w2 = W2d[tid];
#pragma unroll
    for (int r = 0; r < 8; r++) {
        float v = acc[r];
        v = 0.5f * v * (1.f + erff(v * 0.7071067811865475f));
        part[r][tid] = v * w2;
    }
    __syncthreads();
#pragma unroll
    for (int rr = 0; rr < 2; rr++) {
        int r = 2 * w + rr;
        float s = 0.f;
        for (int k = lane; k < 128; k += 32) s += part[r][k];
#pragma unroll
        for (int o = 16; o > 0; o >>= 1) s += __shfl_xor_sync(~0u, s, o);
        if (lane == 0) {
            float raw_logit = s + b2d[0];
            float u = ent[r0 + r] * (1.f / logf((float)Lnn));
            float cs = coss[r];
            float dl = Wlen[0] * cs + Wlen[1] * u + blen[0];
            float lf = tanhf(dl);
            float dt = beta[0] * u + beta[1] * lf;
            dt = fminf(fmaxf(dt, -0.5f), 0.5f);
            out[r0 + r] = raw_logit;
            out[Bn + r0 + r] = dt;
        }
    }
}

// ---------------- host launcher ----------------
extern "C" void kernel_launch(void* const* d_in, const int* in_sizes, int n_in,
                              void* d_out, int out_size) {
    const float* q    = (const float*)d_in[0];
    const float* R    = (const float*)d_in[1];
    const float* lnqg = (const float*)d_in[2];
    const float* lnqb = (const float*)d_in[3];
    const float* W1q  = (const float*)d_in[4];
    const float* b1q  = (const float*)d_in[5];
    const float* W2q  = (const float*)d_in[6];
    const float* b2q  = (const float*)d_in[7];
    const float* lnrg = (const float*)d_in[8];
    const float* lnrb = (const float*)d_in[9];
    const float* W1r  = (const float*)d_in[10];
    const float* b1r  = (const float*)d_in[11];
    const float* W2r  = (const float*)d_in[12];
    const float* b2r  = (const float*)d_in[13];
    const float* lndg = (const float*)d_in[14];
    const float* lndb = (const float*)d_in[15];
    const float* W1d  = (const float*)d_in[16];
    const float* b1d  = (const float*)d_in[17];
    const float* W2d  = (const float*)d_in[18];
    const float* b2d  = (const float*)d_in[19];
    const float* beta = (const float*)d_in[20];
    const float* Wlen = (const float*)d_in[21];
    const float* blen = (const float*)d_in[22];
    float* out = (float*)d_out;

    float *xn, *hb, *zq, *zr, *rb, *en;
    cudaGetSymbolAddress((void**)&xn, g_Xn);
    cudaGetSymbolAddress((void**)&hb, g_Hb);
    cudaGetSymbolAddress((void**)&zq, g_Zq);
    cudaGetSymbolAddress((void**)&zr, g_Zr);
    cudaGetSymbolAddress((void**)&rb, g_Rbar);
    cudaGetSymbolAddress((void**)&en, g_ent);

    cudaFuncSetAttribute(gemm1_mma, cudaFuncAttributeMaxDynamicSharedMemorySize, G1_SMEM);
    cudaFuncSetAttribute(attn_kernel, cudaFuncAttributeMaxDynamicSharedMemorySize, ATTN_SMEM);

    dim3 gg(D2n / 64, Bn / 128);  // (4, 32)

    // q path
    ln_kernel<<<Bn, 256>>>(q, lnqg, lnqb, xn);
    gemm1_mma<<<gg, 256, G1_SMEM>>>(xn, W1q, b1q, hb);
    gemm2_l2n<<<Bn / 4, 128>>>(hb, W2q, b2q, zq);
    // r path (reuses xn/hb scratch; same-stream ordering makes this safe)
    ln_kernel<<<Lnn, 256>>>(R, lnrg, lnrb, xn);
    gemm1_mma<<<gg, 256, G1_SMEM>>>(xn, W1r, b1r, hb);
    gemm2_l2n<<<Lnn / 4, 128>>>(hb, W2r, b2r, zr);
    // attention + entropy + r_bar
    attn_kernel<<<Bn / AQ, 128, ATTN_SMEM>>>(zq, zr, rb, en);
    // decision MLP + scalar heads
    final_kernel<<<Bn / 8, 128>>>(zq, rb, en, lndg, lndb, W1d, b1d, W2d, b2d,
                                  beta, Wlen, blen, out);
}

// round 6
// speedup vs baseline: 2.5987x; 1.3500x over previous
#include <cuda_runtime.h>
#include <math.h>
#include <stdint.h>

#define Bn   4096
#define Lnn  4096
#define Hn   2048
#define Dn   128
#define D2n  256

// ---------------- scratch (static device globals; no runtime alloc) ----------------
__device__ float g_Xn[(size_t)Bn * Hn];
__device__ float g_Hb[(size_t)Bn * D2n];
__device__ float g_Zq[(size_t)Bn * Dn];
__device__ float g_Zr[(size_t)Lnn * Dn];
__device__ float g_Rbar[(size_t)Bn * Dn];
__device__ float g_ent[Bn];

// single dynamic-smem symbol shared by kernels that use dynamic smem
extern __shared__ char dynsm[];

// ================= helpers =================
__device__ __forceinline__ uint32_t f2tf32(float f) {
    uint32_t r;
    asm("cvt.rna.tf32.f32 %0, %1;" : "=r"(r) : "f"(f));
    return r;
}

__device__ __forceinline__ void mma_tf32(float* c, uint32_t a0, uint32_t a1, uint32_t a2, uint32_t a3,
                                         uint32_t b0, uint32_t b1) {
    asm volatile(
        "mma.sync.aligned.m16n8k8.row.col.f32.tf32.tf32.f32 "
        "{%0,%1,%2,%3}, {%4,%5,%6,%7}, {%8,%9}, {%0,%1,%2,%3};"
        : "+f"(c[0]), "+f"(c[1]), "+f"(c[2]), "+f"(c[3])
        : "r"(a0), "r"(a1), "r"(a2), "r"(a3), "r"(b0), "r"(b1));
}

// ---------------- LayerNorm over H=2048, one row per block, float4 ----------------
__global__ void ln_kernel(const float* __restrict__ x, const float* __restrict__ g,
                          const float* __restrict__ b, float* __restrict__ out) {
    __shared__ float4 s4[Hn / 4];
    __shared__ float red[256];
    int row = blockIdx.x, tid = threadIdx.x;
    const float4* xr = (const float4*)(x + (size_t)row * Hn);
    float lsum = 0.f;
    for (int k = tid; k < Hn / 4; k += 256) {
        float4 v = xr[k]; s4[k] = v; lsum += v.x + v.y + v.z + v.w;
    }
    red[tid] = lsum; __syncthreads();
    for (int o = 128; o > 0; o >>= 1) { if (tid < o) red[tid] += red[tid + o]; __syncthreads(); }
    float mean = red[0] * (1.f / Hn);
    __syncthreads();
    float lsq = 0.f;
    for (int k = tid; k < Hn / 4; k += 256) {
        float4 v = s4[k];
        float d0 = v.x - mean, d1 = v.y - mean, d2 = v.z - mean, d3 = v.w - mean;
        lsq += d0 * d0 + d1 * d1 + d2 * d2 + d3 * d3;
    }
    red[tid] = lsq; __syncthreads();
    for (int o = 128; o > 0; o >>= 1) { if (tid < o) red[tid] += red[tid + o]; __syncthreads(); }
    float rstd = rsqrtf(red[0] * (1.f / Hn) + 1e-5f);
    float4* orow = (float4*)(out + (size_t)row * Hn);
    const float4* g4 = (const float4*)g;
    const float4* b4 = (const float4*)b;
    for (int k = tid; k < Hn / 4; k += 256) {
        float4 v = s4[k], gg = g4[k], bb = b4[k], r;
        r.x = (v.x - mean) * rstd * gg.x + bb.x;
        r.y = (v.y - mean) * rstd * gg.y + bb.y;
        r.z = (v.z - mean) * rstd * gg.z + bb.z;
        r.w = (v.w - mean) * rstd * gg.w + bb.w;
        orow[k] = r;
    }
}

// ---------------- GEMM1 via mma.sync tf32 + GELU ----------------
// C[M,256] = gelu(A[M,2048] @ W[256,2048]^T + bias)
// BM=128, BN=64, BK=32; 256 threads = 8 warps (4 along M x 2 along N), warptile 32x32.
#define G1_LDA 136
#define G1_LDB 72
#define G1_AS  (32 * G1_LDA)
#define G1_BS  (32 * G1_LDB)
#define G1_SMEMF (2 * G1_AS + 2 * G1_BS)
#define G1_SMEM  (G1_SMEMF * 4)

__global__ void __launch_bounds__(256, 1) gemm1_mma(const float* __restrict__ A, const float* __restrict__ W,
                                                    const float* __restrict__ bias, float* __restrict__ C) {
    uint32_t* sm = (uint32_t*)dynsm;
    uint32_t* As[2] = { sm, sm + G1_AS };
    uint32_t* Bs[2] = { sm + 2 * G1_AS, sm + 2 * G1_AS + G1_BS };

    int tid = threadIdx.x;
    int wid = tid >> 5, lane = tid & 31;
    int wm = wid & 3, wn = wid >> 2;
    int g = lane >> 2, tig = lane & 3;
    int m0 = blockIdx.y * 128, n0 = blockIdx.x * 64;

    int am = tid & 127, h = tid >> 7;
    const float4* Ag = (const float4*)(A + (size_t)(m0 + am) * Hn);
    int bn = tid & 63, bh = tid >> 6;
    const float4* Wg = (const float4*)(W + (size_t)(n0 + bn) * Hn);

    float acc[2][4][4] = {};
    float4 stA[4], stB[2];

    const int NT = Hn / 32;  // 64

#pragma unroll
    for (int j = 0; j < 4; j++) stA[j] = Ag[h * 4 + j];
#pragma unroll
    for (int j = 0; j < 2; j++) stB[j] = Wg[bh * 2 + j];
#pragma unroll
    for (int j = 0; j < 4; j++) {
        int k4 = h * 16 + j * 4;
        const float* f = (const float*)&stA[j];
#pragma unroll
        for (int u = 0; u < 4; u++) As[0][(k4 + u) * G1_LDA + am] = f2tf32(f[u]);
    }
#pragma unroll
    for (int j = 0; j < 2; j++) {
        int k4 = (bh * 2 + j) * 4;
        const float* f = (const float*)&stB[j];
#pragma unroll
        for (int u = 0; u < 4; u++) Bs[0][(k4 + u) * G1_LDB + bn] = f2tf32(f[u]);
    }
    __syncthreads();

    for (int t = 0; t < NT; t++) {
        int cur = t & 1;
        if (t + 1 < NT) {
#pragma unroll
            for (int j = 0; j < 4; j++) stA[j] = Ag[(t + 1) * 8 + h * 4 + j];
#pragma unroll
            for (int j = 0; j < 2; j++) stB[j] = Wg[(t + 1) * 8 + bh * 2 + j];
        }
        const uint32_t* Ab = As[cur];
        const uint32_t* Bb = Bs[cur];
#pragma unroll
        for (int ks = 0; ks < 4; ks++) {
            int k = ks * 8;
            uint32_t bf[4][2];
#pragma unroll
            for (int nt = 0; nt < 4; nt++) {
                int nc = wn * 32 + nt * 8 + g;
                bf[nt][0] = Bb[(k + tig) * G1_LDB + nc];
                bf[nt][1] = Bb[(k + tig + 4) * G1_LDB + nc];
            }
#pragma unroll
            for (int mt = 0; mt < 2; mt++) {
                int mr = wm * 32 + mt * 16 + g;
                uint32_t a0 = Ab[(k + tig) * G1_LDA + mr];
                uint32_t a1 = Ab[(k + tig) * G1_LDA + mr + 8];
                uint32_t a2 = Ab[(k + tig + 4) * G1_LDA + mr];
                uint32_t a3 = Ab[(k + tig + 4) * G1_LDA + mr + 8];
#pragma unroll
                for (int nt = 0; nt < 4; nt++)
                    mma_tf32(acc[mt][nt], a0, a1, a2, a3, bf[nt][0], bf[nt][1]);
            }
        }
        if (t + 1 < NT) {
            int nxt = cur ^ 1;
#pragma unroll
            for (int j = 0; j < 4; j++) {
                int k4 = h * 16 + j * 4;
                const float* f = (const float*)&stA[j];
#pragma unroll
                for (int u = 0; u < 4; u++) As[nxt][(k4 + u) * G1_LDA + am] = f2tf32(f[u]);
            }
#pragma unroll
            for (int j = 0; j < 2; j++) {
                int k4 = (bh * 2 + j) * 4;
                const float* f = (const float*)&stB[j];
#pragma unroll
                for (int u = 0; u < 4; u++) Bs[nxt][(k4 + u) * G1_LDB + bn] = f2tf32(f[u]);
            }
        }
        __syncthreads();
    }

#pragma unroll
    for (int mt = 0; mt < 2; mt++) {
#pragma unroll
        for (int nt = 0; nt < 4; nt++) {
            int n = n0 + wn * 32 + nt * 8 + 2 * tig;
            float bv0 = bias[n], bv1 = bias[n + 1];
#pragma unroll
            for (int rr = 0; rr < 2; rr++) {
                int m = m0 + wm * 32 + mt * 16 + g + rr * 8;
                float v0 = acc[mt][nt][rr * 2 + 0] + bv0;
                float v1 = acc[mt][nt][rr * 2 + 1] + bv1;
                v0 = 0.5f * v0 * (1.f + erff(v0 * 0.7071067811865475f));
                v1 = 0.5f * v1 * (1.f + erff(v1 * 0.7071067811865475f));
                float2 o = {v0, v1};
                *(float2*)(C + (size_t)m * D2n + n) = o;
            }
        }
    }
}

// ---------------- GEMM2 + l2norm: Z[r,128] = l2n(H[r,256] @ W2^T + b2) ----------------
__global__ void gemm2_l2n(const float* __restrict__ Hin, const float* __restrict__ W2,
                          const float* __restrict__ b2, float* __restrict__ Z) {
    __shared__ float hs[4][D2n];
    __shared__ float red[128];
    int r0 = blockIdx.x * 4, tid = threadIdx.x;
    for (int i = tid; i < 4 * D2n; i += 128) hs[i >> 8][i & 255] = Hin[(size_t)r0 * D2n + i];
    __syncthreads();
    float bj = b2[tid];
    float acc[4] = {bj, bj, bj, bj};
    const float* wrow = W2 + (size_t)tid * D2n;
    for (int k = 0; k < D2n; k += 4) {
        float4 w4 = *(const float4*)(wrow + k);
#pragma unroll
        for (int r = 0; r < 4; r++) {
            float4 h4 = *(const float4*)&hs[r][k];
            acc[r] += h4.x * w4.x + h4.y * w4.y + h4.z * w4.z + h4.w * w4.w;
        }
    }
    for (int r = 0; r < 4; r++) {
        __syncthreads();
        red[tid] = acc[r] * acc[r]; __syncthreads();
        for (int o = 64; o > 0; o >>= 1) { if (tid < o) red[tid] += red[tid + o]; __syncthreads(); }
        float nrm = fmaxf(sqrtf(red[0]), 1e-12f);
        Z[(size_t)(r0 + r) * Dn + tid] = acc[r] / nrm;
    }
}

// ---------------- Attention via tf32 mma.sync ----------------
// BQ=32 q rows per block, BL=64 l per tile. 128 threads = 4 warps:
// wq = wid>>1 selects q-group (16 rows), wl = wid&1 splits l (scores) / d (PV).
// Zr tile lives once in smem (stride 136 words): scores read it [l][d],
// PV reads it "transposed" [d][l] by swapped indexing — both conflict-free.
#define A_LDZ 136
#define A_LDP 72
__global__ void __launch_bounds__(128, 1) attn_mma(const float* __restrict__ Zq, const float* __restrict__ Zr,
                                                   float* __restrict__ Rbar, float* __restrict__ ent) {
    __shared__ uint32_t zr_s[64 * A_LDZ];   // 34816 B, also reused for zq staging & O output
    __shared__ uint32_t ps_s[32 * A_LDP];   // P tile (tf32)
    __shared__ float zpart[2][32];
    __shared__ float tpart[2][32];

    int tid = threadIdx.x;
    int wid = tid >> 5, lane = tid & 31;
    int wq = wid >> 1, wl = wid & 1;
    int g = lane >> 2, tig = lane & 3;
    int q0 = blockIdx.x * 32;
    const float scale = 0.08838834764831845f;  // 1/sqrt(128)

    // stage Zq tile (32x128) into zr_s rows 0..31 (tf32, stride 136)
    for (int i = tid; i < 32 * 32; i += 128) {
        int r = i >> 5, c4 = (i & 31) * 4;
        float4 v = *(const float4*)(Zq + (size_t)(q0 + r) * Dn + c4);
        uint32_t* dst = &zr_s[r * A_LDZ + c4];
        dst[0] = f2tf32(v.x); dst[1] = f2tf32(v.y); dst[2] = f2tf32(v.z); dst[3] = f2tf32(v.w);
    }
    __syncthreads();

    // preload A fragments for scores: 16 k-steps x 4 regs
    uint32_t aq[16][4];
    int qr = wq * 16;
#pragma unroll
    for (int kt = 0; kt < 16; kt++) {
        aq[kt][0] = zr_s[(qr + g) * A_LDZ + kt * 8 + tig];
        aq[kt][1] = zr_s[(qr + g + 8) * A_LDZ + kt * 8 + tig];
        aq[kt][2] = zr_s[(qr + g) * A_LDZ + kt * 8 + tig + 4];
        aq[kt][3] = zr_s[(qr + g + 8) * A_LDZ + kt * 8 + tig + 4];
    }
    __syncthreads();

    float O[8][4] = {};
    float zs0 = 0.f, zs1 = 0.f, ts0 = 0.f, ts1 = 0.f;

    for (int l0 = 0; l0 < Lnn; l0 += 64) {
        // stage Zr tile (64x128) tf32, stride 136
        for (int i = tid; i < 64 * 32; i += 128) {
            int r = i >> 5, c4 = (i & 31) * 4;
            float4 v = *(const float4*)(Zr + (size_t)(l0 + r) * Dn + c4);
            uint32_t* dst = &zr_s[r * A_LDZ + c4];
            dst[0] = f2tf32(v.x); dst[1] = f2tf32(v.y); dst[2] = f2tf32(v.z); dst[3] = f2tf32(v.w);
        }
        __syncthreads();

        // scores: warp covers l cols [wl*32, wl*32+32): 4 n-tiles, 16 k-steps
        float sc[4][4] = {};
#pragma unroll
        for (int kt = 0; kt < 16; kt++) {
#pragma unroll
            for (int nt = 0; nt < 4; nt++) {
                int lb = wl * 32 + nt * 8 + g;
                uint32_t b0 = zr_s[lb * A_LDZ + kt * 8 + tig];
                uint32_t b1 = zr_s[lb * A_LDZ + kt * 8 + tig + 4];
                mma_tf32(sc[nt], aq[kt][0], aq[kt][1], aq[kt][2], aq[kt][3], b0, b1);
            }
        }

        // exp + entropy accum + store P (tf32) to smem
        int r0w = qr + g, r1w = qr + g + 8;
#pragma unroll
        for (int nt = 0; nt < 4; nt++) {
            int c0 = wl * 32 + nt * 8 + 2 * tig;
            float s0 = sc[nt][0] * scale, s1 = sc[nt][1] * scale;
            float s2 = sc[nt][2] * scale, s3 = sc[nt][3] * scale;
            float p0 = __expf(s0), p1 = __expf(s1), p2 = __expf(s2), p3 = __expf(s3);
            zs0 += p0 + p1; ts0 += p0 * s0 + p1 * s1;
            zs1 += p2 + p3; ts1 += p2 * s2 + p3 * s3;
            ps_s[r0w * A_LDP + c0] = f2tf32(p0);
            ps_s[r0w * A_LDP + c0 + 1] = f2tf32(p1);
            ps_s[r1w * A_LDP + c0] = f2tf32(p2);
            ps_s[r1w * A_LDP + c0 + 1] = f2tf32(p3);
        }
        __syncthreads();

        // PV: A = P (8 k-steps over l), B = Zr read transposed; warp covers d [wl*64, wl*64+64)
        uint32_t ap[8][4];
#pragma unroll
        for (int kt = 0; kt < 8; kt++) {
            ap[kt][0] = ps_s[(qr + g) * A_LDP + kt * 8 + tig];
            ap[kt][1] = ps_s[(qr + g + 8) * A_LDP + kt * 8 + tig];
            ap[kt][2] = ps_s[(qr + g) * A_LDP + kt * 8 + tig + 4];
            ap[kt][3] = ps_s[(qr + g + 8) * A_LDP + kt * 8 + tig + 4];
        }
#pragma unroll
        for (int kt = 0; kt < 8; kt++) {
#pragma unroll
            for (int nt = 0; nt < 8; nt++) {
                int db = wl * 64 + nt * 8 + g;
                uint32_t b0 = zr_s[(kt * 8 + tig) * A_LDZ + db];
                uint32_t b1 = zr_s[(kt * 8 + tig + 4) * A_LDZ + db];
                mma_tf32(O[nt], ap[kt][0], ap[kt][1], ap[kt][2], ap[kt][3], b0, b1);
            }
        }
        __syncthreads();
    }

    // reduce zs/ts over the tig quad (lanes g*4 + tig)
    zs0 += __shfl_xor_sync(~0u, zs0, 1); zs0 += __shfl_xor_sync(~0u, zs0, 2);
    zs1 += __shfl_xor_sync(~0u, zs1, 1); zs1 += __shfl_xor_sync(~0u, zs1, 2);
    ts0 += __shfl_xor_sync(~0u, ts0, 1); ts0 += __shfl_xor_sync(~0u, ts0, 2);
    ts1 += __shfl_xor_sync(~0u, ts1, 1); ts1 += __shfl_xor_sync(~0u, ts1, 2);
    if (tig == 0) {
        zpart[wl][qr + g] = zs0; zpart[wl][qr + g + 8] = zs1;
        tpart[wl][qr + g] = ts0; tpart[wl][qr + g + 8] = ts1;
    }

    // dump O fragments to smem (reuse zr_s as float [32][132])
    float* Os = (float*)zr_s;
#pragma unroll
    for (int nt = 0; nt < 8; nt++) {
        int dc = wl * 64 + nt * 8 + 2 * tig;
        Os[(qr + g) * 132 + dc] = O[nt][0];
        Os[(qr + g) * 132 + dc + 1] = O[nt][1];
        Os[(qr + g + 8) * 132 + dc] = O[nt][2];
        Os[(qr + g + 8) * 132 + dc + 1] = O[nt][3];
    }
    __syncthreads();

    // final: 4 threads per q row; l2-normalize O, write Rbar; lane0 of quad writes entropy
    int row = tid >> 2, quar = tid & 3;
    float4 v[8];
    float sq = 0.f;
#pragma unroll
    for (int j = 0; j < 8; j++) {
        v[j] = *(float4*)&Os[row * 132 + quar * 32 + j * 4];
        sq += v[j].x * v[j].x + v[j].y * v[j].y + v[j].z * v[j].z + v[j].w * v[j].w;
    }
    sq += __shfl_xor_sync(~0u, sq, 1); sq += __shfl_xor_sync(~0u, sq, 2);
    float rn = 1.f / fmaxf(sqrtf(sq), 1e-12f);
    float* dst = Rbar + (size_t)(q0 + row) * Dn + quar * 32;
#pragma unroll
    for (int j = 0; j < 8; j++) {
        float4 o = {v[j].x * rn, v[j].y * rn, v[j].z * rn, v[j].w * rn};
        *(float4*)(dst + j * 4) = o;
    }
    if (quar == 0) {
        float zsum = zpart[0][row] + zpart[1][row];
        float tsum = tpart[0][row] + tpart[1][row];
        ent[q0 + row] = logf(zsum) - tsum / zsum;
    }
}

// ---------------- Final: dec MLP + scalar heads. 8 rows per block, 128 threads ----------------
__global__ void final_kernel(const float* __restrict__ Zq, const float* __restrict__ Rbar,
                             const float* __restrict__ ent,
                             const float* __restrict__ gd, const float* __restrict__ bd,
                             const float* __restrict__ W1d, const float* __restrict__ b1d,
                             const float* __restrict__ W2d, const float* __restrict__ b2d,
                             const float* __restrict__ beta, const float* __restrict__ Wlen,
                             const float* __restrict__ blen, float* __restrict__ out) {
    __shared__ float raw[8][D2n];
    __shared__ float nrm[8][D2n];
    __shared__ float part[8][128];
    __shared__ float coss[8];
    int r0 = blockIdx.x * 8, tid = threadIdx.x;
    for (int i = tid; i < 8 * Dn; i += 128) {
        int r = i >> 7, d = i & 127;
        raw[r][d] = Zq[(size_t)(r0 + r) * Dn + d];
        raw[r][128 + d] = Rbar[(size_t)(r0 + r) * Dn + d];
    }
    __syncthreads();
    int w = tid >> 5, lane = tid & 31;
#pragma unroll
    for (int rr = 0; rr < 2; rr++) {
        int r = 2 * w + rr;
        float cs = 0.f, smv = 0.f;
        for (int k = lane; k < D2n; k += 32) smv += raw[r][k];
        for (int k = lane; k < Dn; k += 32) cs += raw[r][k] * raw[r][128 + k];
#pragma unroll
        for (int o = 16; o > 0; o >>= 1) { smv += __shfl_xor_sync(~0u, smv, o); cs += __shfl_xor_sync(~0u, cs, o); }
        float mean = smv * (1.f / D2n);
        float vq = 0.f;
        for (int k = lane; k < D2n; k += 32) { float d = raw[r][k] - mean; vq += d * d; }
#pragma unroll
        for (int o = 16; o > 0; o >>= 1) vq += __shfl_xor_sync(~0u, vq, o);
        float rstd = rsqrtf(vq * (1.f / D2n) + 1e-5f);
        for (int k = lane; k < D2n; k += 32) nrm[r][k] = (raw[r][k] - mean) * rstd * gd[k] + bd[k];
        if (lane == 0) coss[r] = cs;
    }
    __syncthreads();
    float b1 = b1d[tid];
    float acc[8] = {b1, b1, b1, b1, b1, b1, b1, b1};
    const float* wrow = W1d + (size_t)tid * D2n;
    for (int k = 0; k < D2n; k += 4) {
        float4 w4 = *(const float4*)(wrow + k);
#pragma unroll
        for (int r = 0; r < 8; r++) {
            float4 h4 = *(const float4*)&nrm[r][k];
            acc[r] += h4.x * w4.x + h4.y * w4.y + h4.z * w4.z + h4.w * w4.w;
        }
    }
    float w2 = W2d[tid];
#pragma unroll
    for (int r = 0; r < 8; r++) {
        float v = acc[r];
        v = 0.5f * v * (1.f + erff(v * 0.7071067811865475f));
        part[r][tid] = v * w2;
    }
    __syncthreads();
#pragma unroll
    for (int rr = 0; rr < 2; rr++) {
        int r = 2 * w + rr;
        float s = 0.f;
        for (int k = lane; k < 128; k += 32) s += part[r][k];
#pragma unroll
        for (int o = 16; o > 0; o >>= 1) s += __shfl_xor_sync(~0u, s, o);
        if (lane == 0) {
            float raw_logit = s + b2d[0];
            float u = ent[r0 + r] * (1.f / logf((float)Lnn));
            float cs = coss[r];
            float dl = Wlen[0] * cs + Wlen[1] * u + blen[0];
            float lf = tanhf(dl);
            float dt = beta[0] * u + beta[1] * lf;
            dt = fminf(fmaxf(dt, -0.5f), 0.5f);
            out[r0 + r] = raw_logit;
            out[Bn + r0 + r] = dt;
        }
    }
}

// ---------------- host launcher ----------------
extern "C" void kernel_launch(void* const* d_in, const int* in_sizes, int n_in,
                              void* d_out, int out_size) {
    const float* q    = (const float*)d_in[0];
    const float* R    = (const float*)d_in[1];
    const float* lnqg = (const float*)d_in[2];
    const float* lnqb = (const float*)d_in[3];
    const float* W1q  = (const float*)d_in[4];
    const float* b1q  = (const float*)d_in[5];
    const float* W2q  = (const float*)d_in[6];
    const float* b2q  = (const float*)d_in[7];
    const float* lnrg = (const float*)d_in[8];
    const float* lnrb = (const float*)d_in[9];
    const float* W1r  = (const float*)d_in[10];
    const float* b1r  = (const float*)d_in[11];
    const float* W2r  = (const float*)d_in[12];
    const float* b2r  = (const float*)d_in[13];
    const float* lndg = (const float*)d_in[14];
    const float* lndb = (const float*)d_in[15];
    const float* W1d  = (const float*)d_in[16];
    const float* b1d  = (const float*)d_in[17];
    const float* W2d  = (const float*)d_in[18];
    const float* b2d  = (const float*)d_in[19];
    const float* beta = (const float*)d_in[20];
    const float* Wlen = (const float*)d_in[21];
    const float* blen = (const float*)d_in[22];
    float* out = (float*)d_out;

    float *xn, *hb, *zq, *zr, *rb, *en;
    cudaGetSymbolAddress((void**)&xn, g_Xn);
    cudaGetSymbolAddress((void**)&hb, g_Hb);
    cudaGetSymbolAddress((void**)&zq, g_Zq);
    cudaGetSymbolAddress((void**)&zr, g_Zr);
    cudaGetSymbolAddress((void**)&rb, g_Rbar);
    cudaGetSymbolAddress((void**)&en, g_ent);

    cudaFuncSetAttribute(gemm1_mma, cudaFuncAttributeMaxDynamicSharedMemorySize, G1_SMEM);

    dim3 gg(D2n / 64, Bn / 128);  // (4, 32)

    // q path
    ln_kernel<<<Bn, 256>>>(q, lnqg, lnqb, xn);
    gemm1_mma<<<gg, 256, G1_SMEM>>>(xn, W1q, b1q, hb);
    gemm2_l2n<<<Bn / 4, 128>>>(hb, W2q, b2q, zq);
    // r path (reuses xn/hb scratch; same-stream ordering makes this safe)
    ln_kernel<<<Lnn, 256>>>(R, lnrg, lnrb, xn);
    gemm1_mma<<<gg, 256, G1_SMEM>>>(xn, W1r, b1r, hb);
    gemm2_l2n<<<Lnn / 4, 128>>>(hb, W2r, b2r, zr);
    // attention + entropy + r_bar (tensor-core path)
    attn_mma<<<Bn / 32, 128>>>(zq, zr, rb, en);
    // decision MLP + scalar heads
    final_kernel<<<Bn / 8, 128>>>(zq, rb, en, lndg, lndb, W1d, b1d, W2d, b2d,
                                  beta, Wlen, blen, out);
}

// round 7
// speedup vs baseline: 2.9683x; 1.1422x over previous
#include <cuda_runtime.h>
#include <math.h>
#include <stdint.h>

#define Bn   4096
#define Lnn  4096
#define Hn   2048
#define Dn   128
#define D2n  256

// ---------------- scratch (static device globals; no runtime alloc) ----------------
__device__ float g_Hb[(size_t)Bn * D2n];
__device__ float g_Zq[(size_t)Bn * Dn];
__device__ float g_Zr[(size_t)Lnn * Dn];
__device__ float g_Rbar[(size_t)Bn * Dn];
__device__ float g_ent[Bn];
__device__ float g_mu[Bn];
__device__ float g_rs[Bn];

// single dynamic-smem symbol
extern __shared__ char dynsm[];

// ================= helpers =================
__device__ __forceinline__ uint32_t f2tf32(float f) {
    uint32_t r;
    asm("cvt.rna.tf32.f32 %0, %1;" : "=r"(r) : "f"(f));
    return r;
}

__device__ __forceinline__ void mma_tf32(float* c, uint32_t a0, uint32_t a1, uint32_t a2, uint32_t a3,
                                         uint32_t b0, uint32_t b1) {
    asm volatile(
        "mma.sync.aligned.m16n8k8.row.col.f32.tf32.tf32.f32 "
        "{%0,%1,%2,%3}, {%4,%5,%6,%7}, {%8,%9}, {%0,%1,%2,%3};"
        : "+f"(c[0]), "+f"(c[1]), "+f"(c[2]), "+f"(c[3])
        : "r"(a0), "r"(a1), "r"(a2), "r"(a3), "r"(b0), "r"(b1));
}

// ---------------- per-row mean/rstd for LayerNorm (fused into gemm1) ----------------
__global__ void row_stats(const float* __restrict__ x, float* __restrict__ mu, float* __restrict__ rs) {
    int wid = threadIdx.x >> 5, lane = threadIdx.x & 31;
    int row = blockIdx.x * 8 + wid;
    const float4* xr = (const float4*)(x + (size_t)row * Hn);
    float s = 0.f, sq = 0.f;
    for (int k = lane; k < Hn / 4; k += 32) {
        float4 v = xr[k];
        s += v.x + v.y + v.z + v.w;
        sq += v.x * v.x + v.y * v.y + v.z * v.z + v.w * v.w;
    }
#pragma unroll
    for (int o = 16; o > 0; o >>= 1) {
        s += __shfl_xor_sync(~0u, s, o);
        sq += __shfl_xor_sync(~0u, sq, o);
    }
    if (lane == 0) {
        float m = s * (1.f / Hn);
        float var = sq * (1.f / Hn) - m * m;
        mu[row] = m;
        rs[row] = rsqrtf(var + 1e-5f);
    }
}

// ---------------- GEMM1 (mma.sync tf32) with fused LayerNorm + GELU ----------------
// C[M,256] = gelu(LN(A)[M,2048] @ W[256,2048]^T + bias)
// BM=128, BN=64, BK=32; 256 threads = 8 warps (4 M x 2 N), warptile 32x32.
// smem layout: [m][k], stride 40 words (32 k + 4 pad*... 8 pad) — conflict-free STS.128 and frag LDS.
#define G1_LD 40
#define G1_AS (128 * G1_LD)
#define G1_BS (64 * G1_LD)
#define G1_SMEM ((2 * G1_AS + 2 * G1_BS) * 4)

__global__ void __launch_bounds__(256, 1) gemm1_mma(
        const float* __restrict__ A, const float* __restrict__ W,
        const float* __restrict__ mean, const float* __restrict__ rstd,
        const float* __restrict__ gamma, const float* __restrict__ beta,
        const float* __restrict__ bias, float* __restrict__ C) {
    uint32_t* sm = (uint32_t*)dynsm;
    uint32_t* Asm[2] = { sm, sm + G1_AS };
    uint32_t* Bsm[2] = { sm + 2 * G1_AS, sm + 2 * G1_AS + G1_BS };

    int tid = threadIdx.x;
    int wid = tid >> 5, lane = tid & 31;
    int wm = wid & 3, wn = wid >> 2;
    int g = lane >> 2, tig = lane & 3;
    int m0 = blockIdx.y * 128, n0 = blockIdx.x * 64;
    int q = tid >> 3, f4 = tid & 7;

    const float4* Arow[4];
    float mu[4], rsd[4];
#pragma unroll
    for (int j = 0; j < 4; j++) {
        int r = m0 + q + 32 * j;
        Arow[j] = (const float4*)(A + (size_t)r * Hn);
        mu[j] = mean[r];
        rsd[j] = rstd[r];
    }
    const float4* Brow[2];
#pragma unroll
    for (int j = 0; j < 2; j++) Brow[j] = (const float4*)(W + (size_t)(n0 + q + 32 * j) * Hn);
    const float4* g4p = (const float4*)gamma;
    const float4* b4p = (const float4*)beta;

    float acc[2][4][4] = {};
    float4 pA[4], pB[2], pG, pBt;

    const int NT = Hn / 32;  // 64

    // prefetch tile 0
    pG = g4p[f4]; pBt = b4p[f4];
#pragma unroll
    for (int j = 0; j < 4; j++) pA[j] = Arow[j][f4];
#pragma unroll
    for (int j = 0; j < 2; j++) pB[j] = Brow[j][f4];
    // commit tile 0
#pragma unroll
    for (int j = 0; j < 4; j++) {
        float x0 = (pA[j].x - mu[j]) * rsd[j] * pG.x + pBt.x;
        float x1 = (pA[j].y - mu[j]) * rsd[j] * pG.y + pBt.y;
        float x2 = (pA[j].z - mu[j]) * rsd[j] * pG.z + pBt.z;
        float x3 = (pA[j].w - mu[j]) * rsd[j] * pG.w + pBt.w;
        uint4 u = { f2tf32(x0), f2tf32(x1), f2tf32(x2), f2tf32(x3) };
        *(uint4*)&Asm[0][(q + 32 * j) * G1_LD + f4 * 4] = u;
    }
#pragma unroll
    for (int j = 0; j < 2; j++) {
        uint4 u = { f2tf32(pB[j].x), f2tf32(pB[j].y), f2tf32(pB[j].z), f2tf32(pB[j].w) };
        *(uint4*)&Bsm[0][(q + 32 * j) * G1_LD + f4 * 4] = u;
    }
    __syncthreads();

    for (int t = 0; t < NT; t++) {
        int cur = t & 1;
        if (t + 1 < NT) {
            pG = g4p[(t + 1) * 8 + f4]; pBt = b4p[(t + 1) * 8 + f4];
#pragma unroll
            for (int j = 0; j < 4; j++) pA[j] = Arow[j][(t + 1) * 8 + f4];
#pragma unroll
            for (int j = 0; j < 2; j++) pB[j] = Brow[j][(t + 1) * 8 + f4];
        }
        const uint32_t* Ab = Asm[cur];
        const uint32_t* Bb = Bsm[cur];
#pragma unroll
        for (int ks = 0; ks < 4; ks++) {
            int k = ks * 8;
            uint32_t bf[4][2];
#pragma unroll
            for (int nt = 0; nt < 4; nt++) {
                int nc = wn * 32 + nt * 8 + g;
                bf[nt][0] = Bb[nc * G1_LD + k + tig];
                bf[nt][1] = Bb[nc * G1_LD + k + tig + 4];
            }
#pragma unroll
            for (int mt = 0; mt < 2; mt++) {
                int mr = wm * 32 + mt * 16 + g;
                uint32_t a0 = Ab[mr * G1_LD + k + tig];
                uint32_t a1 = Ab[(mr + 8) * G1_LD + k + tig];
                uint32_t a2 = Ab[mr * G1_LD + k + tig + 4];
                uint32_t a3 = Ab[(mr + 8) * G1_LD + k + tig + 4];
#pragma unroll
                for (int nt = 0; nt < 4; nt++)
                    mma_tf32(acc[mt][nt], a0, a1, a2, a3, bf[nt][0], bf[nt][1]);
            }
        }
        if (t + 1 < NT) {
            int nxt = cur ^ 1;
#pragma unroll
            for (int j = 0; j < 4; j++) {
                float x0 = (pA[j].x - mu[j]) * rsd[j] * pG.x + pBt.x;
                float x1 = (pA[j].y - mu[j]) * rsd[j] * pG.y + pBt.y;
                float x2 = (pA[j].z - mu[j]) * rsd[j] * pG.z + pBt.z;
                float x3 = (pA[j].w - mu[j]) * rsd[j] * pG.w + pBt.w;
                uint4 u = { f2tf32(x0), f2tf32(x1), f2tf32(x2), f2tf32(x3) };
                *(uint4*)&Asm[nxt][(q + 32 * j) * G1_LD + f4 * 4] = u;
            }
#pragma unroll
            for (int j = 0; j < 2; j++) {
                uint4 u = { f2tf32(pB[j].x), f2tf32(pB[j].y), f2tf32(pB[j].z), f2tf32(pB[j].w) };
                *(uint4*)&Bsm[nxt][(q + 32 * j) * G1_LD + f4 * 4] = u;
            }
        }
        __syncthreads();
    }

    // epilogue
#pragma unroll
    for (int mt = 0; mt < 2; mt++) {
#pragma unroll
        for (int nt = 0; nt < 4; nt++) {
            int n = n0 + wn * 32 + nt * 8 + 2 * tig;
            float bv0 = bias[n], bv1 = bias[n + 1];
#pragma unroll
            for (int rr = 0; rr < 2; rr++) {
                int m = m0 + wm * 32 + mt * 16 + g + rr * 8;
                float v0 = acc[mt][nt][rr * 2 + 0] + bv0;
                float v1 = acc[mt][nt][rr * 2 + 1] + bv1;
                v0 = 0.5f * v0 * (1.f + erff(v0 * 0.7071067811865475f));
                v1 = 0.5f * v1 * (1.f + erff(v1 * 0.7071067811865475f));
                float2 o = {v0, v1};
                *(float2*)(C + (size_t)m * D2n + n) = o;
            }
        }
    }
}

// ---------------- GEMM2 + l2norm: Z[r,128] = l2n(H[r,256] @ W2^T + b2) ----------------
__global__ void gemm2_l2n(const float* __restrict__ Hin, const float* __restrict__ W2,
                          const float* __restrict__ b2, float* __restrict__ Z) {
    __shared__ float hs[4][D2n];
    __shared__ float red[128];
    int r0 = blockIdx.x * 4, tid = threadIdx.x;
    for (int i = tid; i < 4 * D2n; i += 128) hs[i >> 8][i & 255] = Hin[(size_t)r0 * D2n + i];
    __syncthreads();
    float bj = b2[tid];
    float acc[4] = {bj, bj, bj, bj};
    const float* wrow = W2 + (size_t)tid * D2n;
    for (int k = 0; k < D2n; k += 4) {
        float4 w4 = *(const float4*)(wrow + k);
#pragma unroll
        for (int r = 0; r < 4; r++) {
            float4 h4 = *(const float4*)&hs[r][k];
            acc[r] += h4.x * w4.x + h4.y * w4.y + h4.z * w4.z + h4.w * w4.w;
        }
    }
    for (int r = 0; r < 4; r++) {
        __syncthreads();
        red[tid] = acc[r] * acc[r]; __syncthreads();
        for (int o = 64; o > 0; o >>= 1) { if (tid < o) red[tid] += red[tid + o]; __syncthreads(); }
        float nrm = fmaxf(sqrtf(red[0]), 1e-12f);
        Z[(size_t)(r0 + r) * Dn + tid] = acc[r] / nrm;
    }
}

// ---------------- Attention via tf32 mma.sync, 8 warps ----------------
// BQ=32 q rows/block, BL=64 l/tile. 256 threads = 8 warps:
// wq = wid>>2 (q-group of 16), ws = wid&3 (4-way l split in scores, d split in PV).
#define A_LDZ 136
#define A_LDP 68
__global__ void __launch_bounds__(256, 1) attn_mma(const float* __restrict__ Zq, const float* __restrict__ Zr,
                                                   float* __restrict__ Rbar, float* __restrict__ ent) {
    __shared__ uint32_t zr_s[64 * A_LDZ];   // 34816 B; reused for zq staging & O output
    __shared__ uint32_t ps_s[32 * A_LDP];   // P tile (tf32), 8704 B
    __shared__ float zpart[4][32];
    __shared__ float tpart[4][32];

    int tid = threadIdx.x;
    int wid = tid >> 5, lane = tid & 31;
    int wq = wid >> 2, ws = wid & 3;
    int g = lane >> 2, tig = lane & 3;
    int q0 = blockIdx.x * 32;
    int qr = wq * 16;
    const float scale = 0.08838834764831845f;  // 1/sqrt(128)

    // stage Zq tile (32x128) into zr_s rows 0..31
    for (int i = tid; i < 32 * 32; i += 256) {
        int r = i >> 5, c4 = (i & 31) * 4;
        float4 v = *(const float4*)(Zq + (size_t)(q0 + r) * Dn + c4);
        uint32_t* dst = &zr_s[r * A_LDZ + c4];
        dst[0] = f2tf32(v.x); dst[1] = f2tf32(v.y); dst[2] = f2tf32(v.z); dst[3] = f2tf32(v.w);
    }
    __syncthreads();

    // preload A fragments for scores
    uint32_t aq[16][4];
#pragma unroll
    for (int kt = 0; kt < 16; kt++) {
        aq[kt][0] = zr_s[(qr + g) * A_LDZ + kt * 8 + tig];
        aq[kt][1] = zr_s[(qr + g + 8) * A_LDZ + kt * 8 + tig];
        aq[kt][2] = zr_s[(qr + g) * A_LDZ + kt * 8 + tig + 4];
        aq[kt][3] = zr_s[(qr + g + 8) * A_LDZ + kt * 8 + tig + 4];
    }
    __syncthreads();

    float O[4][4] = {};
    float zs0 = 0.f, zs1 = 0.f, ts0 = 0.f, ts1 = 0.f;

    for (int l0 = 0; l0 < Lnn; l0 += 64) {
        // stage Zr tile (64x128)
        for (int i = tid; i < 64 * 32; i += 256) {
            int r = i >> 5, c4 = (i & 31) * 4;
            float4 v = *(const float4*)(Zr + (size_t)(l0 + r) * Dn + c4);
            uint32_t* dst = &zr_s[r * A_LDZ + c4];
            dst[0] = f2tf32(v.x); dst[1] = f2tf32(v.y); dst[2] = f2tf32(v.z); dst[3] = f2tf32(v.w);
        }
        __syncthreads();

        // scores: warp covers l cols [ws*16, ws*16+16): 2 n-tiles, 16 k-steps
        float sc[2][4] = {};
#pragma unroll
        for (int kt = 0; kt < 16; kt++) {
#pragma unroll
            for (int nt = 0; nt < 2; nt++) {
                int lb = ws * 16 + nt * 8 + g;
                uint32_t b0 = zr_s[lb * A_LDZ + kt * 8 + tig];
                uint32_t b1 = zr_s[lb * A_LDZ + kt * 8 + tig + 4];
                mma_tf32(sc[nt], aq[kt][0], aq[kt][1], aq[kt][2], aq[kt][3], b0, b1);
            }
        }

        // exp + entropy accum + store P (tf32)
        int r0w = qr + g, r1w = qr + g + 8;
#pragma unroll
        for (int nt = 0; nt < 2; nt++) {
            int c0 = ws * 16 + nt * 8 + 2 * tig;
            float s0 = sc[nt][0] * scale, s1 = sc[nt][1] * scale;
            float s2 = sc[nt][2] * scale, s3 = sc[nt][3] * scale;
            float p0 = __expf(s0), p1 = __expf(s1), p2 = __expf(s2), p3 = __expf(s3);
            zs0 += p0 + p1; ts0 += p0 * s0 + p1 * s1;
            zs1 += p2 + p3; ts1 += p2 * s2 + p3 * s3;
            ps_s[r0w * A_LDP + c0] = f2tf32(p0);
            ps_s[r0w * A_LDP + c0 + 1] = f2tf32(p1);
            ps_s[r1w * A_LDP + c0] = f2tf32(p2);
            ps_s[r1w * A_LDP + c0 + 1] = f2tf32(p3);
        }
        __syncthreads();

        // PV: A = P (8 k-steps over l), B = Zr transposed; warp covers d [ws*32, ws*32+32)
        uint32_t ap[8][4];
#pragma unroll
        for (int kt = 0; kt < 8; kt++) {
            ap[kt][0] = ps_s[(qr + g) * A_LDP + kt * 8 + tig];
            ap[kt][1] = ps_s[(qr + g + 8) * A_LDP + kt * 8 + tig];
            ap[kt][2] = ps_s[(qr + g) * A_LDP + kt * 8 + tig + 4];
            ap[kt][3] = ps_s[(qr + g + 8) * A_LDP + kt * 8 + tig + 4];
        }
#pragma unroll
        for (int kt = 0; kt < 8; kt++) {
#pragma unroll
            for (int nt = 0; nt < 4; nt++) {
                int db = ws * 32 + nt * 8 + g;
                uint32_t b0 = zr_s[(kt * 8 + tig) * A_LDZ + db];
                uint32_t b1 = zr_s[(kt * 8 + tig + 4) * A_LDZ + db];
                mma_tf32(O[nt], ap[kt][0], ap[kt][1], ap[kt][2], ap[kt][3], b0, b1);
            }
        }
        __syncthreads();
    }

    // reduce zs/ts over the tig quad
    zs0 += __shfl_xor_sync(~0u, zs0, 1); zs0 += __shfl_xor_sync(~0u, zs0, 2);
    zs1 += __shfl_xor_sync(~0u, zs1, 1); zs1 += __shfl_xor_sync(~0u, zs1, 2);
    ts0 += __shfl_xor_sync(~0u, ts0, 1); ts0 += __shfl_xor_sync(~0u, ts0, 2);
    ts1 += __shfl_xor_sync(~0u, ts1, 1); ts1 += __shfl_xor_sync(~0u, ts1, 2);
    if (tig == 0) {
        zpart[ws][qr + g] = zs0; zpart[ws][qr + g + 8] = zs1;
        tpart[ws][qr + g] = ts0; tpart[ws][qr + g + 8] = ts1;
    }

    // dump O fragments to smem (float [32][132])
    float* Os = (float*)zr_s;
#pragma unroll
    for (int nt = 0; nt < 4; nt++) {
        int dc = ws * 32 + nt * 8 + 2 * tig;
        Os[(qr + g) * 132 + dc] = O[nt][0];
        Os[(qr + g) * 132 + dc + 1] = O[nt][1];
        Os[(qr + g + 8) * 132 + dc] = O[nt][2];
        Os[(qr + g + 8) * 132 + dc + 1] = O[nt][3];
    }
    __syncthreads();

    // final: 8 threads per q row; l2-normalize O, write Rbar; entropy
    int row = tid >> 3, oct = tid & 7;
    float4 v[4];
    float sq = 0.f;
#pragma unroll
    for (int j = 0; j < 4; j++) {
        v[j] = *(float4*)&Os[row * 132 + oct * 16 + j * 4];
        sq += v[j].x * v[j].x + v[j].y * v[j].y + v[j].z * v[j].z + v[j].w * v[j].w;
    }
    sq += __shfl_xor_sync(~0u, sq, 1);
    sq += __shfl_xor_sync(~0u, sq, 2);
    sq += __shfl_xor_sync(~0u, sq, 4);
    float rn = 1.f / fmaxf(sqrtf(sq), 1e-12f);
    float* dst = Rbar + (size_t)(q0 + row) * Dn + oct * 16;
#pragma unroll
    for (int j = 0; j < 4; j++) {
        float4 o = {v[j].x * rn, v[j].y * rn, v[j].z * rn, v[j].w * rn};
        *(float4*)(dst + j * 4) = o;
    }
    if (oct == 0) {
        float zsum = zpart[0][row] + zpart[1][row] + zpart[2][row] + zpart[3][row];
        float tsum = tpart[0][row] + tpart[1][row] + tpart[2][row] + tpart[3][row];
        ent[q0 + row] = logf(zsum) - tsum / zsum;
    }
}

// ---------------- Final: dec MLP + scalar heads. 8 rows per block, 128 threads ----------------
__global__ void final_kernel(const float* __restrict__ Zq, const float* __restrict__ Rbar,
                             const float* __restrict__ ent,
                             const float* __restrict__ gd, const float* __restrict__ bd,
                             const float* __restrict__ W1d, const float* __restrict__ b1d,
                             const float* __restrict__ W2d, const float* __restrict__ b2d,
                             const float* __restrict__ beta, const float* __restrict__ Wlen,
                             const float* __restrict__ blen, float* __restrict__ out) {
    __shared__ float raw[8][D2n];
    __shared__ float nrm[8][D2n];
    __shared__ float part[8][128];
    __shared__ float coss[8];
    int r0 = blockIdx.x * 8, tid = threadIdx.x;
    for (int i = tid; i < 8 * Dn; i += 128) {
        int r = i >> 7, d = i & 127;
        raw[r][d] = Zq[(size_t)(r0 + r) * Dn + d];
        raw[r][128 + d] = Rbar[(size_t)(r0 + r) * Dn + d];
    }
    __syncthreads();
    int w = tid >> 5, lane = tid & 31;
#pragma unroll
    for (int rr = 0; rr < 2; rr++) {
        int r = 2 * w + rr;
        float cs = 0.f, smv = 0.f;
        for (int k = lane; k < D2n; k += 32) smv += raw[r][k];
        for (int k = lane; k < Dn; k += 32) cs += raw[r][k] * raw[r][128 + k];
#pragma unroll
        for (int o = 16; o > 0; o >>= 1) { smv += __shfl_xor_sync(~0u, smv, o); cs += __shfl_xor_sync(~0u, cs, o); }
        float mean = smv * (1.f / D2n);
        float vq = 0.f;
        for (int k = lane; k < D2n; k += 32) { float d = raw[r][k] - mean; vq += d * d; }
#pragma unroll
        for (int o = 16; o > 0; o >>= 1) vq += __shfl_xor_sync(~0u, vq, o);
        float rstd = rsqrtf(vq * (1.f / D2n) + 1e-5f);
        for (int k = lane; k < D2n; k += 32) nrm[r][k] = (raw[r][k] - mean) * rstd * gd[k] + bd[k];
        if (lane == 0) coss[r] = cs;
    }
    __syncthreads();
    float b1 = b1d[tid];
    float acc[8] = {b1, b1, b1, b1, b1, b1, b1, b1};
    const float* wrow = W1d + (size_t)tid * D2n;
    for (int k = 0; k < D2n; k += 4) {
        float4 w4 = *(const float4*)(wrow + k);
#pragma unroll
        for (int r = 0; r < 8; r++) {
            float4 h4 = *(const float4*)&nrm[r][k];
            acc[r] += h4.x * w4.x + h4.y * w4.y + h4.z * w4.z + h4.w * w4.w;
        }
    }
    float w2 = W2d[tid];
#pragma unroll
    for (int r = 0; r < 8; r++) {
        float v = acc[r];
        v = 0.5f * v * (1.f + erff(v * 0.7071067811865475f));
        part[r][tid] = v * w2;
    }
    __syncthreads();
#pragma unroll
    for (int rr = 0; rr < 2; rr++) {
        int r = 2 * w + rr;
        float s = 0.f;
        for (int k = lane; k < 128; k += 32) s += part[r][k];
#pragma unroll
        for (int o = 16; o > 0; o >>= 1) s += __shfl_xor_sync(~0u, s, o);
        if (lane == 0) {
            float raw_logit = s + b2d[0];
            float u = ent[r0 + r] * (1.f / logf((float)Lnn));
            float cs = coss[r];
            float dl = Wlen[0] * cs + Wlen[1] * u + blen[0];
            float lf = tanhf(dl);
            float dt = beta[0] * u + beta[1] * lf;
            dt = fminf(fmaxf(dt, -0.5f), 0.5f);
            out[r0 + r] = raw_logit;
            out[Bn + r0 + r] = dt;
        }
    }
}

// ---------------- host launcher ----------------
extern "C" void kernel_launch(void* const* d_in, const int* in_sizes, int n_in,
                              void* d_out, int out_size) {
    const float* q    = (const float*)d_in[0];
    const float* R    = (const float*)d_in[1];
    const float* lnqg = (const float*)d_in[2];
    const float* lnqb = (const float*)d_in[3];
    const float* W1q  = (const float*)d_in[4];
    const float* b1q  = (const float*)d_in[5];
    const float* W2q  = (const float*)d_in[6];
    const float* b2q  = (const float*)d_in[7];
    const float* lnrg = (const float*)d_in[8];
    const float* lnrb = (const float*)d_in[9];
    const float* W1r  = (const float*)d_in[10];
    const float* b1r  = (const float*)d_in[11];
    const float* W2r  = (const float*)d_in[12];
    const float* b2r  = (const float*)d_in[13];
    const float* lndg = (const float*)d_in[14];
    const float* lndb = (const float*)d_in[15];
    const float* W1d  = (const float*)d_in[16];
    const float* b1d  = (const float*)d_in[17];
    const float* W2d  = (const float*)d_in[18];
    const float* b2d  = (const float*)d_in[19];
    const float* beta = (const float*)d_in[20];
    const float* Wlen = (const float*)d_in[21];
    const float* blen = (const float*)d_in[22];
    float* out = (float*)d_out;

    float *hb, *zq, *zr, *rb, *en, *mu, *rs;
    cudaGetSymbolAddress((void**)&hb, g_Hb);
    cudaGetSymbolAddress((void**)&zq, g_Zq);
    cudaGetSymbolAddress((void**)&zr, g_Zr);
    cudaGetSymbolAddress((void**)&rb, g_Rbar);
    cudaGetSymbolAddress((void**)&en, g_ent);
    cudaGetSymbolAddress((void**)&mu, g_mu);
    cudaGetSymbolAddress((void**)&rs, g_rs);

    cudaFuncSetAttribute(gemm1_mma, cudaFuncAttributeMaxDynamicSharedMemorySize, G1_SMEM);

    dim3 gg(D2n / 64, Bn / 128);  // (4, 32)

    // q path (LN fused into gemm1 A-staging)
    row_stats<<<Bn / 8, 256>>>(q, mu, rs);
    gemm1_mma<<<gg, 256, G1_SMEM>>>(q, W1q, mu, rs, lnqg, lnqb, b1q, hb);
    gemm2_l2n<<<Bn / 4, 128>>>(hb, W2q, b2q, zq);
    // r path (reuses mu/rs/hb scratch; same-stream ordering makes this safe)
    row_stats<<<Lnn / 8, 256>>>(R, mu, rs);
    gemm1_mma<<<gg, 256, G1_SMEM>>>(R, W1r, mu, rs, lnrg, lnrb, b1r, hb);
    gemm2_l2n<<<Lnn / 4, 128>>>(hb, W2r, b2r, zr);
    // attention + entropy + r_bar
    attn_mma<<<Bn / 32, 256>>>(zq, zr, rb, en);
    // decision MLP + scalar heads
    final_kernel<<<Bn / 8, 128>>>(zq, rb, en, lndg, lndb, W1d, b1d, W2d, b2d,
                                  beta, Wlen, blen, out);
}

// round 8
// speedup vs baseline: 3.1407x; 1.0581x over previous
#include <cuda_runtime.h>
#include <math.h>
#include <stdint.h>

#define Bn   4096
#define Lnn  4096
#define Hn   2048
#define Dn   128
#define D2n  256

// ---------------- scratch ----------------
__device__ float g_Hb[(size_t)2 * Bn * D2n];
__device__ float g_Zq[(size_t)Bn * Dn];
__device__ float g_Zr[(size_t)Lnn * Dn];
__device__ float g_Rbar[(size_t)Bn * Dn];
__device__ float g_ent[Bn];
__device__ float g_mu[2 * Bn];
__device__ float g_rs[2 * Bn];

extern __shared__ char dynsm[];

// ================= helpers =================
__device__ __forceinline__ uint32_t f2tf32(float f) {
    uint32_t r;
    asm("cvt.rna.tf32.f32 %0, %1;" : "=r"(r) : "f"(f));
    return r;
}

__device__ __forceinline__ void mma_tf32(float* c, uint32_t a0, uint32_t a1, uint32_t a2, uint32_t a3,
                                         uint32_t b0, uint32_t b1) {
    asm volatile(
        "mma.sync.aligned.m16n8k8.row.col.f32.tf32.tf32.f32 "
        "{%0,%1,%2,%3}, {%4,%5,%6,%7}, {%8,%9}, {%0,%1,%2,%3};"
        : "+f"(c[0]), "+f"(c[1]), "+f"(c[2]), "+f"(c[3])
        : "r"(a0), "r"(a1), "r"(a2), "r"(a3), "r"(b0), "r"(b1));
}

// ---------------- per-row mean/rstd, both inputs in one launch ----------------
__global__ void row_stats_both(const float* __restrict__ xq, const float* __restrict__ xr,
                               float* __restrict__ mu, float* __restrict__ rs) {
    int z = blockIdx.y;
    const float* x = z ? xr : xq;
    int wid = threadIdx.x >> 5, lane = threadIdx.x & 31;
    int row = blockIdx.x * 8 + wid;
    const float4* xrow = (const float4*)(x + (size_t)row * Hn);
    float s = 0.f, sq = 0.f;
    for (int k = lane; k < Hn / 4; k += 32) {
        float4 v = xrow[k];
        s += v.x + v.y + v.z + v.w;
        sq += v.x * v.x + v.y * v.y + v.z * v.z + v.w * v.w;
    }
#pragma unroll
    for (int o = 16; o > 0; o >>= 1) {
        s += __shfl_xor_sync(~0u, s, o);
        sq += __shfl_xor_sync(~0u, sq, o);
    }
    if (lane == 0) {
        float m = s * (1.f / Hn);
        float var = sq * (1.f / Hn) - m * m;
        mu[z * Bn + row] = m;
        rs[z * Bn + row] = rsqrtf(var + 1e-5f);
    }
}

// ---------------- GEMM1 (tf32 mma) + fused LN + GELU, both paths via blockIdx.z ----------------
// BM=128, BN=64, BK=32; 256 threads = 8 warps (4 M x 2 N), warptile 32x32. stride 36: conflict-free.
#define G1_LD 36
#define G1_AS (128 * G1_LD)
#define G1_BS (64 * G1_LD)
#define G1_SMEM ((2 * G1_AS + 2 * G1_BS) * 4)

__global__ void __launch_bounds__(256, 1) gemm1_both(
        const float* __restrict__ Aq, const float* __restrict__ Ar,
        const float* __restrict__ Wq, const float* __restrict__ Wr,
        const float* __restrict__ gq, const float* __restrict__ gr,
        const float* __restrict__ bq, const float* __restrict__ br,
        const float* __restrict__ biasq, const float* __restrict__ biasr,
        const float* __restrict__ mean, const float* __restrict__ rstd,
        float* __restrict__ Cb) {
    int z = blockIdx.z;
    const float* A = z ? Ar : Aq;
    const float* W = z ? Wr : Wq;
    const float* gamma = z ? gr : gq;
    const float* beta = z ? br : bq;
    const float* bias = z ? biasr : biasq;
    float* C = Cb + (size_t)z * Bn * D2n;
    const float* mub = mean + z * Bn;
    const float* rsb = rstd + z * Bn;

    uint32_t* sm = (uint32_t*)dynsm;
    uint32_t* Asm[2] = { sm, sm + G1_AS };
    uint32_t* Bsm[2] = { sm + 2 * G1_AS, sm + 2 * G1_AS + G1_BS };

    int tid = threadIdx.x;
    int wid = tid >> 5, lane = tid & 31;
    int wm = wid & 3, wn = wid >> 2;
    int g = lane >> 2, tig = lane & 3;
    int m0 = blockIdx.y * 128, n0 = blockIdx.x * 64;
    int q = tid >> 3, f4 = tid & 7;

    const float4* Arow[4];
    float mu[4], rsd[4];
#pragma unroll
    for (int j = 0; j < 4; j++) {
        int r = m0 + q + 32 * j;
        Arow[j] = (const float4*)(A + (size_t)r * Hn);
        mu[j] = mub[r];
        rsd[j] = rsb[r];
    }
    const float4* Brow[2];
#pragma unroll
    for (int j = 0; j < 2; j++) Brow[j] = (const float4*)(W + (size_t)(n0 + q + 32 * j) * Hn);
    const float4* g4p = (const float4*)gamma;
    const float4* b4p = (const float4*)beta;

    float acc[2][4][4] = {};
    float4 pA[4], pB[2], pG, pBt;

    const int NT = Hn / 32;  // 64

    pG = g4p[f4]; pBt = b4p[f4];
#pragma unroll
    for (int j = 0; j < 4; j++) pA[j] = Arow[j][f4];
#pragma unroll
    for (int j = 0; j < 2; j++) pB[j] = Brow[j][f4];
#pragma unroll
    for (int j = 0; j < 4; j++) {
        float x0 = (pA[j].x - mu[j]) * rsd[j] * pG.x + pBt.x;
        float x1 = (pA[j].y - mu[j]) * rsd[j] * pG.y + pBt.y;
        float x2 = (pA[j].z - mu[j]) * rsd[j] * pG.z + pBt.z;
        float x3 = (pA[j].w - mu[j]) * rsd[j] * pG.w + pBt.w;
        uint4 u = { f2tf32(x0), f2tf32(x1), f2tf32(x2), f2tf32(x3) };
        *(uint4*)&Asm[0][(q + 32 * j) * G1_LD + f4 * 4] = u;
    }
#pragma unroll
    for (int j = 0; j < 2; j++) {
        uint4 u = { f2tf32(pB[j].x), f2tf32(pB[j].y), f2tf32(pB[j].z), f2tf32(pB[j].w) };
        *(uint4*)&Bsm[0][(q + 32 * j) * G1_LD + f4 * 4] = u;
    }
    __syncthreads();

    for (int t = 0; t < NT; t++) {
        int cur = t & 1;
        if (t + 1 < NT) {
            pG = g4p[(t + 1) * 8 + f4]; pBt = b4p[(t + 1) * 8 + f4];
#pragma unroll
            for (int j = 0; j < 4; j++) pA[j] = Arow[j][(t + 1) * 8 + f4];
#pragma unroll
            for (int j = 0; j < 2; j++) pB[j] = Brow[j][(t + 1) * 8 + f4];
        }
        const uint32_t* Ab = Asm[cur];
        const uint32_t* Bb = Bsm[cur];
#pragma unroll
        for (int ks = 0; ks < 4; ks++) {
            int k = ks * 8;
            uint32_t bf[4][2];
#pragma unroll
            for (int nt = 0; nt < 4; nt++) {
                int nc = wn * 32 + nt * 8 + g;
                bf[nt][0] = Bb[nc * G1_LD + k + tig];
                bf[nt][1] = Bb[nc * G1_LD + k + tig + 4];
            }
#pragma unroll
            for (int mt = 0; mt < 2; mt++) {
                int mr = wm * 32 + mt * 16 + g;
                uint32_t a0 = Ab[mr * G1_LD + k + tig];
                uint32_t a1 = Ab[(mr + 8) * G1_LD + k + tig];
                uint32_t a2 = Ab[mr * G1_LD + k + tig + 4];
                uint32_t a3 = Ab[(mr + 8) * G1_LD + k + tig + 4];
#pragma unroll
                for (int nt = 0; nt < 4; nt++)
                    mma_tf32(acc[mt][nt], a0, a1, a2, a3, bf[nt][0], bf[nt][1]);
            }
        }
        if (t + 1 < NT) {
            int nxt = cur ^ 1;
#pragma unroll
            for (int j = 0; j < 4; j++) {
                float x0 = (pA[j].x - mu[j]) * rsd[j] * pG.x + pBt.x;
                float x1 = (pA[j].y - mu[j]) * rsd[j] * pG.y + pBt.y;
                float x2 = (pA[j].z - mu[j]) * rsd[j] * pG.z + pBt.z;
                float x3 = (pA[j].w - mu[j]) * rsd[j] * pG.w + pBt.w;
                uint4 u = { f2tf32(x0), f2tf32(x1), f2tf32(x2), f2tf32(x3) };
                *(uint4*)&Asm[nxt][(q + 32 * j) * G1_LD + f4 * 4] = u;
            }
#pragma unroll
            for (int j = 0; j < 2; j++) {
                uint4 u = { f2tf32(pB[j].x), f2tf32(pB[j].y), f2tf32(pB[j].z), f2tf32(pB[j].w) };
                *(uint4*)&Bsm[nxt][(q + 32 * j) * G1_LD + f4 * 4] = u;
            }
        }
        __syncthreads();
    }

#pragma unroll
    for (int mt = 0; mt < 2; mt++) {
#pragma unroll
        for (int nt = 0; nt < 4; nt++) {
            int n = n0 + wn * 32 + nt * 8 + 2 * tig;
            float bv0 = bias[n], bv1 = bias[n + 1];
#pragma unroll
            for (int rr = 0; rr < 2; rr++) {
                int m = m0 + wm * 32 + mt * 16 + g + rr * 8;
                float v0 = acc[mt][nt][rr * 2 + 0] + bv0;
                float v1 = acc[mt][nt][rr * 2 + 1] + bv1;
                v0 = 0.5f * v0 * (1.f + erff(v0 * 0.7071067811865475f));
                v1 = 0.5f * v1 * (1.f + erff(v1 * 0.7071067811865475f));
                float2 o = {v0, v1};
                *(float2*)(C + (size_t)m * D2n + n) = o;
            }
        }
    }
}

// ---------------- GEMM2 + l2norm, both paths via blockIdx.y ----------------
__global__ void gemm2_both(const float* __restrict__ Hb,
                           const float* __restrict__ W2q, const float* __restrict__ W2r,
                           const float* __restrict__ b2q, const float* __restrict__ b2r,
                           float* __restrict__ Zq, float* __restrict__ Zr) {
    int z = blockIdx.y;
    const float* Hin = Hb + (size_t)z * Bn * D2n;
    const float* W2 = z ? W2r : W2q;
    const float* b2 = z ? b2r : b2q;
    float* Z = z ? Zr : Zq;

    __shared__ float hs[4][D2n];
    __shared__ float red[128];
    int r0 = blockIdx.x * 4, tid = threadIdx.x;
    for (int i = tid; i < 4 * D2n; i += 128) hs[i >> 8][i & 255] = Hin[(size_t)r0 * D2n + i];
    __syncthreads();
    float bj = b2[tid];
    float acc[4] = {bj, bj, bj, bj};
    const float* wrow = W2 + (size_t)tid * D2n;
    for (int k = 0; k < D2n; k += 4) {
        float4 w4 = *(const float4*)(wrow + k);
#pragma unroll
        for (int r = 0; r < 4; r++) {
            float4 h4 = *(const float4*)&hs[r][k];
            acc[r] += h4.x * w4.x + h4.y * w4.y + h4.z * w4.z + h4.w * w4.w;
        }
    }
    for (int r = 0; r < 4; r++) {
        __syncthreads();
        red[tid] = acc[r] * acc[r]; __syncthreads();
        for (int o = 64; o > 0; o >>= 1) { if (tid < o) red[tid] += red[tid + o]; __syncthreads(); }
        float nrm = fmaxf(sqrtf(red[0]), 1e-12f);
        Z[(size_t)(r0 + r) * Dn + tid] = acc[r] / nrm;
    }
}

// ---------------- Attention (tf32 mma, double-buffered Zr staging) ----------------
// BQ=32, BL=64, 256 threads = 8 warps: wq = wid>>2 (q-group), ws = wid&3 (l/d split).
#define A_LDZ 136
#define A_LDP 68
#define A_ZBUF (64 * A_LDZ)
#define ATTN_SMEM ((2 * A_ZBUF + 32 * A_LDP) * 4)
__global__ void __launch_bounds__(256, 1) attn_mma(const float* __restrict__ Zq, const float* __restrict__ Zr,
                                                   float* __restrict__ Rbar, float* __restrict__ ent) {
    uint32_t* smw = (uint32_t*)dynsm;
    uint32_t* zbuf[2] = { smw, smw + A_ZBUF };
    uint32_t* ps_s = smw + 2 * A_ZBUF;
    __shared__ float zpart[4][32];
    __shared__ float tpart[4][32];

    int tid = threadIdx.x;
    int wid = tid >> 5, lane = tid & 31;
    int wq = wid >> 2, ws = wid & 3;
    int g = lane >> 2, tig = lane & 3;
    int q0 = blockIdx.x * 32;
    int qr = wq * 16;
    const float scale = 0.08838834764831845f;  // 1/sqrt(128)

    // each thread's 8 staging slots: i = tid + j*256 -> row = i>>5, c4 = (i&31)*4
    int srow[8], sc4[8];
#pragma unroll
    for (int j = 0; j < 8; j++) {
        int i = tid + j * 256;
        srow[j] = i >> 5;
        sc4[j] = (i & 31) * 4;
    }

    // prefetch tile 0 (independent of zq staging)
    float4 pf[8];
#pragma unroll
    for (int j = 0; j < 8; j++)
        pf[j] = *(const float4*)(Zr + (size_t)srow[j] * Dn + sc4[j]);

    // stage Zq (32x128) into zbuf0 rows 0..31
    for (int i = tid; i < 32 * 32; i += 256) {
        int r = i >> 5, c4 = (i & 31) * 4;
        float4 v = *(const float4*)(Zq + (size_t)(q0 + r) * Dn + c4);
        uint32_t* dst = &zbuf[0][r * A_LDZ + c4];
        dst[0] = f2tf32(v.x); dst[1] = f2tf32(v.y); dst[2] = f2tf32(v.z); dst[3] = f2tf32(v.w);
    }
    __syncthreads();

    uint32_t aq[16][4];
#pragma unroll
    for (int kt = 0; kt < 16; kt++) {
        aq[kt][0] = zbuf[0][(qr + g) * A_LDZ + kt * 8 + tig];
        aq[kt][1] = zbuf[0][(qr + g + 8) * A_LDZ + kt * 8 + tig];
        aq[kt][2] = zbuf[0][(qr + g) * A_LDZ + kt * 8 + tig + 4];
        aq[kt][3] = zbuf[0][(qr + g + 8) * A_LDZ + kt * 8 + tig + 4];
    }
    __syncthreads();

    // commit tile 0 into zbuf0
#pragma unroll
    for (int j = 0; j < 8; j++) {
        uint4 u = { f2tf32(pf[j].x), f2tf32(pf[j].y), f2tf32(pf[j].z), f2tf32(pf[j].w) };
        *(uint4*)&zbuf[0][srow[j] * A_LDZ + sc4[j]] = u;
    }
    __syncthreads();

    float O[4][4] = {};
    float zs0 = 0.f, zs1 = 0.f, ts0 = 0.f, ts1 = 0.f;
    const int NT = Lnn / 64;  // 64

    for (int t = 0; t < NT; t++) {
        int cur = t & 1;
        if (t + 1 < NT) {
            const float* src = Zr + (size_t)(t + 1) * 64 * Dn;
#pragma unroll
            for (int j = 0; j < 8; j++)
                pf[j] = *(const float4*)(src + (size_t)srow[j] * Dn + sc4[j]);
        }
        const uint32_t* zb = zbuf[cur];

        // scores: warp covers l cols [ws*16, ws*16+16)
        float sc[2][4] = {};
#pragma unroll
        for (int kt = 0; kt < 16; kt++) {
#pragma unroll
            for (int nt = 0; nt < 2; nt++) {
                int lb = ws * 16 + nt * 8 + g;
                uint32_t b0 = zb[lb * A_LDZ + kt * 8 + tig];
                uint32_t b1 = zb[lb * A_LDZ + kt * 8 + tig + 4];
                mma_tf32(sc[nt], aq[kt][0], aq[kt][1], aq[kt][2], aq[kt][3], b0, b1);
            }
        }

        int r0w = qr + g, r1w = qr + g + 8;
#pragma unroll
        for (int nt = 0; nt < 2; nt++) {
            int c0 = ws * 16 + nt * 8 + 2 * tig;
            float s0 = sc[nt][0] * scale, s1 = sc[nt][1] * scale;
            float s2 = sc[nt][2] * scale, s3 = sc[nt][3] * scale;
            float p0 = __expf(s0), p1 = __expf(s1), p2 = __expf(s2), p3 = __expf(s3);
            zs0 += p0 + p1; ts0 += p0 * s0 + p1 * s1;
            zs1 += p2 + p3; ts1 += p2 * s2 + p3 * s3;
            ps_s[r0w * A_LDP + c0] = f2tf32(p0);
            ps_s[r0w * A_LDP + c0 + 1] = f2tf32(p1);
            ps_s[r1w * A_LDP + c0] = f2tf32(p2);
            ps_s[r1w * A_LDP + c0 + 1] = f2tf32(p3);
        }
        __syncthreads();

        // PV: A = P, B = zb transposed; warp covers d [ws*32, ws*32+32)
        uint32_t ap[8][4];
#pragma unroll
        for (int kt = 0; kt < 8; kt++) {
            ap[kt][0] = ps_s[(qr + g) * A_LDP + kt * 8 + tig];
            ap[kt][1] = ps_s[(qr + g + 8) * A_LDP + kt * 8 + tig];
            ap[kt][2] = ps_s[(qr + g) * A_LDP + kt * 8 + tig + 4];
            ap[kt][3] = ps_s[(qr + g + 8) * A_LDP + kt * 8 + tig + 4];
        }
#pragma unroll
        for (int kt = 0; kt < 8; kt++) {
#pragma unroll
            for (int nt = 0; nt < 4; nt++) {
                int db = ws * 32 + nt * 8 + g;
                uint32_t b0 = zb[(kt * 8 + tig) * A_LDZ + db];
                uint32_t b1 = zb[(kt * 8 + tig + 4) * A_LDZ + db];
                mma_tf32(O[nt], ap[kt][0], ap[kt][1], ap[kt][2], ap[kt][3], b0, b1);
            }
        }
        if (t + 1 < NT) {
            uint32_t* nb = zbuf[cur ^ 1];
#pragma unroll
            for (int j = 0; j < 8; j++) {
                uint4 u = { f2tf32(pf[j].x), f2tf32(pf[j].y), f2tf32(pf[j].z), f2tf32(pf[j].w) };
                *(uint4*)&nb[srow[j] * A_LDZ + sc4[j]] = u;
            }
        }
        __syncthreads();
    }

    // reduce zs/ts over the tig quad
    zs0 += __shfl_xor_sync(~0u, zs0, 1); zs0 += __shfl_xor_sync(~0u, zs0, 2);
    zs1 += __shfl_xor_sync(~0u, zs1, 1); zs1 += __shfl_xor_sync(~0u, zs1, 2);
    ts0 += __shfl_xor_sync(~0u, ts0, 1); ts0 += __shfl_xor_sync(~0u, ts0, 2);
    ts1 += __shfl_xor_sync(~0u, ts1, 1); ts1 += __shfl_xor_sync(~0u, ts1, 2);
    if (tig == 0) {
        zpart[ws][qr + g] = zs0; zpart[ws][qr + g + 8] = zs1;
        tpart[ws][qr + g] = ts0; tpart[ws][qr + g + 8] = ts1;
    }

    // dump O fragments to smem (float [32][132])
    float* Os = (float*)zbuf[0];
#pragma unroll
    for (int nt = 0; nt < 4; nt++) {
        int dc = ws * 32 + nt * 8 + 2 * tig;
        Os[(qr + g) * 132 + dc] = O[nt][0];
        Os[(qr + g) * 132 + dc + 1] = O[nt][1];
        Os[(qr + g + 8) * 132 + dc] = O[nt][2];
        Os[(qr + g + 8) * 132 + dc + 1] = O[nt][3];
    }
    __syncthreads();

    int row = tid >> 3, oct = tid & 7;
    float4 v[4];
    float sq = 0.f;
#pragma unroll
    for (int j = 0; j < 4; j++) {
        v[j] = *(float4*)&Os[row * 132 + oct * 16 + j * 4];
        sq += v[j].x * v[j].x + v[j].y * v[j].y + v[j].z * v[j].z + v[j].w * v[j].w;
    }
    sq += __shfl_xor_sync(~0u, sq, 1);
    sq += __shfl_xor_sync(~0u, sq, 2);
    sq += __shfl_xor_sync(~0u, sq, 4);
    float rn = 1.f / fmaxf(sqrtf(sq), 1e-12f);
    float* dst = Rbar + (size_t)(q0 + row) * Dn + oct * 16;
#pragma unroll
    for (int j = 0; j < 4; j++) {
        float4 o = {v[j].x * rn, v[j].y * rn, v[j].z * rn, v[j].w * rn};
        *(float4*)(dst + j * 4) = o;
    }
    if (oct == 0) {
        float zsum = zpart[0][row] + zpart[1][row] + zpart[2][row] + zpart[3][row];
        float tsum = tpart[0][row] + tpart[1][row] + tpart[2][row] + tpart[3][row];
        ent[q0 + row] = logf(zsum) - tsum / zsum;
    }
}

// ---------------- Final: dec MLP + scalar heads ----------------
__global__ void final_kernel(const float* __restrict__ Zq, const float* __restrict__ Rbar,
                             const float* __restrict__ ent,
                             const float* __restrict__ gd, const float* __restrict__ bd,
                             const float* __restrict__ W1d, const float* __restrict__ b1d,
                             const float* __restrict__ W2d, const float* __restrict__ b2d,
                             const float* __restrict__ beta, const float* __restrict__ Wlen,
                             const float* __restrict__ blen, float* __restrict__ out) {
    __shared__ float raw[8][D2n];
    __shared__ float nrm[8][D2n];
    __shared__ float part[8][128];
    __shared__ float coss[8];
    int r0 = blockIdx.x * 8, tid = threadIdx.x;
    for (int i = tid; i < 8 * Dn; i += 128) {
        int r = i >> 7, d = i & 127;
        raw[r][d] = Zq[(size_t)(r0 + r) * Dn + d];
        raw[r][128 + d] = Rbar[(size_t)(r0 + r) * Dn + d];
    }
    __syncthreads();
    int w = tid >> 5, lane = tid & 31;
#pragma unroll
    for (int rr = 0; rr < 2; rr++) {
        int r = 2 * w + rr;
        float cs = 0.f, smv = 0.f;
        for (int k = lane; k < D2n; k += 32) smv += raw[r][k];
        for (int k = lane; k < Dn; k += 32) cs += raw[r][k] * raw[r][128 + k];
#pragma unroll
        for (int o = 16; o > 0; o >>= 1) { smv += __shfl_xor_sync(~0u, smv, o); cs += __shfl_xor_sync(~0u, cs, o); }
        float mean = smv * (1.f / D2n);
        float vq = 0.f;
        for (int k = lane; k < D2n; k += 32) { float d = raw[r][k] - mean; vq += d * d; }
#pragma unroll
        for (int o = 16; o > 0; o >>= 1) vq += __shfl_xor_sync(~0u, vq, o);
        float rstd = rsqrtf(vq * (1.f / D2n) + 1e-5f);
        for (int k = lane; k < D2n; k += 32) nrm[r][k] = (raw[r][k] - mean) * rstd * gd[k] + bd[k];
        if (lane == 0) coss[r] = cs;
    }
    __syncthreads();
    float b1 = b1d[tid];
    float acc[8] = {b1, b1, b1, b1, b1, b1, b1, b1};
    const float* wrow = W1d + (size_t)tid * D2n;
    for (int k = 0; k < D2n; k += 4) {
        float4 w4 = *(const float4*)(wrow + k);
#pragma unroll
        for (int r = 0; r < 8; r++) {
            float4 h4 = *(const float4*)&nrm[r][k];
            acc[r] += h4.x * w4.x + h4.y * w4.y + h4.z * w4.z + h4.w * w4.w;
        }
    }
    float w2 = W2d[tid];
#pragma unroll
    for (int r = 0; r < 8; r++) {
        float v = acc[r];
        v = 0.5f * v * (1.f + erff(v * 0.7071067811865475f));
        part[r][tid] = v * w2;
    }
    __syncthreads();
#pragma unroll
    for (int rr = 0; rr < 2; rr++) {
        int r = 2 * w + rr;
        float s = 0.f;
        for (int k = lane; k < 128; k += 32) s += part[r][k];
#pragma unroll
        for (int o = 16; o > 0; o >>= 1) s += __shfl_xor_sync(~0u, s, o);
        if (lane == 0) {
            float raw_logit = s + b2d[0];
            float u = ent[r0 + r] * (1.f / logf((float)Lnn));
            float cs = coss[r];
            float dl = Wlen[0] * cs + Wlen[1] * u + blen[0];
            float lf = tanhf(dl);
            float dt = beta[0] * u + beta[1] * lf;
            dt = fminf(fmaxf(dt, -0.5f), 0.5f);
            out[r0 + r] = raw_logit;
            out[Bn + r0 + r] = dt;
        }
    }
}

// ---------------- host launcher ----------------
extern "C" void kernel_launch(void* const* d_in, const int* in_sizes, int n_in,
                              void* d_out, int out_size) {
    const float* q    = (const float*)d_in[0];
    const float* R    = (const float*)d_in[1];
    const float* lnqg = (const float*)d_in[2];
    const float* lnqb = (const float*)d_in[3];
    const float* W1q  = (const float*)d_in[4];
    const float* b1q  = (const float*)d_in[5];
    const float* W2q  = (const float*)d_in[6];
    const float* b2q  = (const float*)d_in[7];
    const float* lnrg = (const float*)d_in[8];
    const float* lnrb = (const float*)d_in[9];
    const float* W1r  = (const float*)d_in[10];
    const float* b1r  = (const float*)d_in[11];
    const float* W2r  = (const float*)d_in[12];
    const float* b2r  = (const float*)d_in[13];
    const float* lndg = (const float*)d_in[14];
    const float* lndb = (const float*)d_in[15];
    const float* W1d  = (const float*)d_in[16];
    const float* b1d  = (const float*)d_in[17];
    const float* W2d  = (const float*)d_in[18];
    const float* b2d  = (const float*)d_in[19];
    const float* beta = (const float*)d_in[20];
    const float* Wlen = (const float*)d_in[21];
    const float* blen = (const float*)d_in[22];
    float* out = (float*)d_out;

    float *hb, *zq, *zr, *rb, *en, *mu, *rs;
    cudaGetSymbolAddress((void**)&hb, g_Hb);
    cudaGetSymbolAddress((void**)&zq, g_Zq);
    cudaGetSymbolAddress((void**)&zr, g_Zr);
    cudaGetSymbolAddress((void**)&rb, g_Rbar);
    cudaGetSymbolAddress((void**)&en, g_ent);
    cudaGetSymbolAddress((void**)&mu, g_mu);
    cudaGetSymbolAddress((void**)&rs, g_rs);

    cudaFuncSetAttribute(gemm1_both, cudaFuncAttributeMaxDynamicSharedMemorySize, G1_SMEM);
    cudaFuncSetAttribute(attn_mma, cudaFuncAttributeMaxDynamicSharedMemorySize, ATTN_SMEM);

    // LN stats for q and R in one launch
    row_stats_both<<<dim3(Bn / 8, 2), 256>>>(q, R, mu, rs);
    // both GEMM1s in one launch
    gemm1_both<<<dim3(D2n / 64, Bn / 128, 2), 256, G1_SMEM>>>(
        q, R, W1q, W1r, lnqg, lnrg, lnqb, lnrb, b1q, b1r, mu, rs, hb);
    // both GEMM2s in one launch
    gemm2_both<<<dim3(Bn / 4, 2), 128>>>(hb, W2q, W2r, b2q, b2r, zq, zr);
    // attention + entropy + r_bar
    attn_mma<<<Bn / 32, 256, ATTN_SMEM>>>(zq, zr, rb, en);
    // decision MLP + scalar heads
    final_kernel<<<Bn / 8, 128>>>(zq, rb, en, lndg, lndb, W1d, b1d, W2d, b2d,
                                  beta, Wlen, blen, out);
}

// round 9
// speedup vs baseline: 3.2124x; 1.0228x over previous
#include <cuda_runtime.h>
#include <math.h>
#include <stdint.h>

#define Bn   4096
#define Lnn  4096
#define Hn   2048
#define Dn   128
#define D2n  256

// ---------------- scratch ----------------
__device__ float g_Hb[(size_t)2 * Bn * D2n];
__device__ float g_Zq[(size_t)Bn * Dn];
__device__ float g_Zr[(size_t)Lnn * Dn];
__device__ float g_Rbar[(size_t)Bn * Dn];
__device__ float g_ent[Bn];
__device__ float g_mu[2 * Bn];
__device__ float g_rs[2 * Bn];

extern __shared__ char dynsm[];

// ================= helpers =================
__device__ __forceinline__ uint32_t f2tf32(float f) {
    uint32_t r;
    asm("cvt.rna.tf32.f32 %0, %1;" : "=r"(r) : "f"(f));
    return r;
}

__device__ __forceinline__ void mma_tf32(float* c, uint32_t a0, uint32_t a1, uint32_t a2, uint32_t a3,
                                         uint32_t b0, uint32_t b1) {
    asm volatile(
        "mma.sync.aligned.m16n8k8.row.col.f32.tf32.tf32.f32 "
        "{%0,%1,%2,%3}, {%4,%5,%6,%7}, {%8,%9}, {%0,%1,%2,%3};"
        : "+f"(c[0]), "+f"(c[1]), "+f"(c[2]), "+f"(c[3])
        : "r"(a0), "r"(a1), "r"(a2), "r"(a3), "r"(b0), "r"(b1));
}

__device__ __forceinline__ void cpa16(uint32_t dst, const void* src) {
    asm volatile("cp.async.cg.shared.global [%0], [%1], 16;" :: "r"(dst), "l"(src));
}
#define CP_COMMIT() asm volatile("cp.async.commit_group;" ::: "memory")
#define CP_WAIT1()  asm volatile("cp.async.wait_group 1;" ::: "memory")

// ---------------- per-row mean/rstd, both inputs in one launch ----------------
__global__ void row_stats_both(const float* __restrict__ xq, const float* __restrict__ xr,
                               float* __restrict__ mu, float* __restrict__ rs) {
    int z = blockIdx.y;
    const float* x = z ? xr : xq;
    int wid = threadIdx.x >> 5, lane = threadIdx.x & 31;
    int row = blockIdx.x * 8 + wid;
    const float4* xrow = (const float4*)(x + (size_t)row * Hn);
    float s = 0.f, sq = 0.f;
    for (int k = lane; k < Hn / 4; k += 32) {
        float4 v = xrow[k];
        s += v.x + v.y + v.z + v.w;
        sq += v.x * v.x + v.y * v.y + v.z * v.z + v.w * v.w;
    }
#pragma unroll
    for (int o = 16; o > 0; o >>= 1) {
        s += __shfl_xor_sync(~0u, s, o);
        sq += __shfl_xor_sync(~0u, sq, o);
    }
    if (lane == 0) {
        float m = s * (1.f / Hn);
        float var = sq * (1.f / Hn) - m * m;
        mu[z * Bn + row] = m;
        rs[z * Bn + row] = rsqrtf(var + 1e-5f);
    }
}

// ---------------- GEMM1 (tf32 mma) + fused LN + GELU, both paths via blockIdx.z ----------------
#define G1_LD 36
#define G1_AS (128 * G1_LD)
#define G1_BS (64 * G1_LD)
#define G1_SMEM ((2 * G1_AS + 2 * G1_BS) * 4)

__global__ void __launch_bounds__(256, 1) gemm1_both(
        const float* __restrict__ Aq, const float* __restrict__ Ar,
        const float* __restrict__ Wq, const float* __restrict__ Wr,
        const float* __restrict__ gq, const float* __restrict__ gr,
        const float* __restrict__ bq, const float* __restrict__ br,
        const float* __restrict__ biasq, const float* __restrict__ biasr,
        const float* __restrict__ mean, const float* __restrict__ rstd,
        float* __restrict__ Cb) {
    int z = blockIdx.z;
    const float* A = z ? Ar : Aq;
    const float* W = z ? Wr : Wq;
    const float* gamma = z ? gr : gq;
    const float* beta = z ? br : bq;
    const float* bias = z ? biasr : biasq;
    float* C = Cb + (size_t)z * Bn * D2n;
    const float* mub = mean + z * Bn;
    const float* rsb = rstd + z * Bn;

    uint32_t* sm = (uint32_t*)dynsm;
    uint32_t* Asm[2] = { sm, sm + G1_AS };
    uint32_t* Bsm[2] = { sm + 2 * G1_AS, sm + 2 * G1_AS + G1_BS };

    int tid = threadIdx.x;
    int wid = tid >> 5, lane = tid & 31;
    int wm = wid & 3, wn = wid >> 2;
    int g = lane >> 2, tig = lane & 3;
    int m0 = blockIdx.y * 128, n0 = blockIdx.x * 64;
    int q = tid >> 3, f4 = tid & 7;

    const float4* Arow[4];
    float mu[4], rsd[4];
#pragma unroll
    for (int j = 0; j < 4; j++) {
        int r = m0 + q + 32 * j;
        Arow[j] = (const float4*)(A + (size_t)r * Hn);
        mu[j] = mub[r];
        rsd[j] = rsb[r];
    }
    const float4* Brow[2];
#pragma unroll
    for (int j = 0; j < 2; j++) Brow[j] = (const float4*)(W + (size_t)(n0 + q + 32 * j) * Hn);
    const float4* g4p = (const float4*)gamma;
    const float4* b4p = (const float4*)beta;

    float acc[2][4][4] = {};
    float4 pA[4], pB[2], pG, pBt;

    const int NT = Hn / 32;  // 64

    pG = g4p[f4]; pBt = b4p[f4];
#pragma unroll
    for (int j = 0; j < 4; j++) pA[j] = Arow[j][f4];
#pragma unroll
    for (int j = 0; j < 2; j++) pB[j] = Brow[j][f4];
#pragma unroll
    for (int j = 0; j < 4; j++) {
        float x0 = (pA[j].x - mu[j]) * rsd[j] * pG.x + pBt.x;
        float x1 = (pA[j].y - mu[j]) * rsd[j] * pG.y + pBt.y;
        float x2 = (pA[j].z - mu[j]) * rsd[j] * pG.z + pBt.z;
        float x3 = (pA[j].w - mu[j]) * rsd[j] * pG.w + pBt.w;
        uint4 u = { f2tf32(x0), f2tf32(x1), f2tf32(x2), f2tf32(x3) };
        *(uint4*)&Asm[0][(q + 32 * j) * G1_LD + f4 * 4] = u;
    }
#pragma unroll
    for (int j = 0; j < 2; j++) {
        uint4 u = { f2tf32(pB[j].x), f2tf32(pB[j].y), f2tf32(pB[j].z), f2tf32(pB[j].w) };
        *(uint4*)&Bsm[0][(q + 32 * j) * G1_LD + f4 * 4] = u;
    }
    __syncthreads();

    for (int t = 0; t < NT; t++) {
        int cur = t & 1;
        if (t + 1 < NT) {
            pG = g4p[(t + 1) * 8 + f4]; pBt = b4p[(t + 1) * 8 + f4];
#pragma unroll
            for (int j = 0; j < 4; j++) pA[j] = Arow[j][(t + 1) * 8 + f4];
#pragma unroll
            for (int j = 0; j < 2; j++) pB[j] = Brow[j][(t + 1) * 8 + f4];
        }
        const uint32_t* Ab = Asm[cur];
        const uint32_t* Bb = Bsm[cur];
#pragma unroll
        for (int ks = 0; ks < 4; ks++) {
            int k = ks * 8;
            uint32_t bf[4][2];
#pragma unroll
            for (int nt = 0; nt < 4; nt++) {
                int nc = wn * 32 + nt * 8 + g;
                bf[nt][0] = Bb[nc * G1_LD + k + tig];
                bf[nt][1] = Bb[nc * G1_LD + k + tig + 4];
            }
#pragma unroll
            for (int mt = 0; mt < 2; mt++) {
                int mr = wm * 32 + mt * 16 + g;
                uint32_t a0 = Ab[mr * G1_LD + k + tig];
                uint32_t a1 = Ab[(mr + 8) * G1_LD + k + tig];
                uint32_t a2 = Ab[mr * G1_LD + k + tig + 4];
                uint32_t a3 = Ab[(mr + 8) * G1_LD + k + tig + 4];
#pragma unroll
                for (int nt = 0; nt < 4; nt++)
                    mma_tf32(acc[mt][nt], a0, a1, a2, a3, bf[nt][0], bf[nt][1]);
            }
        }
        if (t + 1 < NT) {
            int nxt = cur ^ 1;
#pragma unroll
            for (int j = 0; j < 4; j++) {
                float x0 = (pA[j].x - mu[j]) * rsd[j] * pG.x + pBt.x;
                float x1 = (pA[j].y - mu[j]) * rsd[j] * pG.y + pBt.y;
                float x2 = (pA[j].z - mu[j]) * rsd[j] * pG.z + pBt.z;
                float x3 = (pA[j].w - mu[j]) * rsd[j] * pG.w + pBt.w;
                uint4 u = { f2tf32(x0), f2tf32(x1), f2tf32(x2), f2tf32(x3) };
                *(uint4*)&Asm[nxt][(q + 32 * j) * G1_LD + f4 * 4] = u;
            }
#pragma unroll
            for (int j = 0; j < 2; j++) {
                uint4 u = { f2tf32(pB[j].x), f2tf32(pB[j].y), f2tf32(pB[j].z), f2tf32(pB[j].w) };
                *(uint4*)&Bsm[nxt][(q + 32 * j) * G1_LD + f4 * 4] = u;
            }
        }
        __syncthreads();
    }

#pragma unroll
    for (int mt = 0; mt < 2; mt++) {
#pragma unroll
        for (int nt = 0; nt < 4; nt++) {
            int n = n0 + wn * 32 + nt * 8 + 2 * tig;
            float bv0 = bias[n], bv1 = bias[n + 1];
#pragma unroll
            for (int rr = 0; rr < 2; rr++) {
                int m = m0 + wm * 32 + mt * 16 + g + rr * 8;
                float v0 = acc[mt][nt][rr * 2 + 0] + bv0;
                float v1 = acc[mt][nt][rr * 2 + 1] + bv1;
                v0 = 0.5f * v0 * (1.f + erff(v0 * 0.7071067811865475f));
                v1 = 0.5f * v1 * (1.f + erff(v1 * 0.7071067811865475f));
                float2 o = {v0, v1};
                *(float2*)(C + (size_t)m * D2n + n) = o;
            }
        }
    }
}

// ---------------- GEMM2 + l2norm, both paths; outputs tf32-rounded Z ----------------
__global__ void gemm2_both(const float* __restrict__ Hb,
                           const float* __restrict__ W2q, const float* __restrict__ W2r,
                           const float* __restrict__ b2q, const float* __restrict__ b2r,
                           float* __restrict__ Zq, float* __restrict__ Zr) {
    int z = blockIdx.y;
    const float* Hin = Hb + (size_t)z * Bn * D2n;
    const float* W2 = z ? W2r : W2q;
    const float* b2 = z ? b2r : b2q;
    float* Z = z ? Zr : Zq;

    __shared__ float hs[4][D2n];
    __shared__ float red[128];
    int r0 = blockIdx.x * 4, tid = threadIdx.x;
    for (int i = tid; i < 4 * D2n; i += 128) hs[i >> 8][i & 255] = Hin[(size_t)r0 * D2n + i];
    __syncthreads();
    float bj = b2[tid];
    float acc[4] = {bj, bj, bj, bj};
    const float* wrow = W2 + (size_t)tid * D2n;
    for (int k = 0; k < D2n; k += 4) {
        float4 w4 = *(const float4*)(wrow + k);
#pragma unroll
        for (int r = 0; r < 4; r++) {
            float4 h4 = *(const float4*)&hs[r][k];
            acc[r] += h4.x * w4.x + h4.y * w4.y + h4.z * w4.z + h4.w * w4.w;
        }
    }
    for (int r = 0; r < 4; r++) {
        __syncthreads();
        red[tid] = acc[r] * acc[r]; __syncthreads();
        for (int o = 64; o > 0; o >>= 1) { if (tid < o) red[tid] += red[tid + o]; __syncthreads(); }
        float nrm = fmaxf(sqrtf(red[0]), 1e-12f);
        // pre-round to tf32 so attention can stage raw bits with cp.async
        Z[(size_t)(r0 + r) * Dn + tid] = __uint_as_float(f2tf32(acc[r] / nrm));
    }
}

// ---------------- Attention: tf32 mma + cp.async double-buffered staging ----------------
// BQ=32, BL=64, 256 threads = 8 warps: wq = wid>>2 (q-group of 16), ws = wid&3 (l/d split).
#define A_LDZ 136
#define A_LDP 68
#define A_ZQW (32 * A_LDZ)          // zq buffer words
#define A_ZBW (64 * A_LDZ)          // one zr buffer words
#define ATTN_SMEM ((A_ZQW + 2 * A_ZBW + 32 * A_LDP) * 4)
__global__ void __launch_bounds__(256, 1) attn_mma(const float* __restrict__ Zq, const float* __restrict__ Zr,
                                                   float* __restrict__ Rbar, float* __restrict__ ent) {
    uint32_t* smw = (uint32_t*)dynsm;
    uint32_t* zqb = smw;
    uint32_t* zbuf[2] = { smw + A_ZQW, smw + A_ZQW + A_ZBW };
    uint32_t* ps_s = smw + A_ZQW + 2 * A_ZBW;
    __shared__ float zpart[4][32];
    __shared__ float tpart[4][32];

    int tid = threadIdx.x;
    int wid = tid >> 5, lane = tid & 31;
    int wq = wid >> 2, ws = wid & 3;
    int g = lane >> 2, tig = lane & 3;
    int q0 = blockIdx.x * 32;
    int qr = wq * 16;
    const float scale = 0.08838834764831845f;  // 1/sqrt(128)

    uint32_t zq_sb = (uint32_t)__cvta_generic_to_shared(zqb);
    uint32_t zb_sb[2] = { (uint32_t)__cvta_generic_to_shared(zbuf[0]),
                          (uint32_t)__cvta_generic_to_shared(zbuf[1]) };

    // group0: zq tile (32x128) + Zr tile0 ; group1: Zr tile1
#pragma unroll
    for (int j = 0; j < 4; j++) {
        int i = tid + j * 256, r = i >> 5, c4 = (i & 31) * 4;
        cpa16(zq_sb + (r * A_LDZ + c4) * 4, Zq + (size_t)(q0 + r) * Dn + c4);
    }
#pragma unroll
    for (int j = 0; j < 8; j++) {
        int i = tid + j * 256, r = i >> 5, c4 = (i & 31) * 4;
        cpa16(zb_sb[0] + (r * A_LDZ + c4) * 4, Zr + (size_t)r * Dn + c4);
    }
    CP_COMMIT();
#pragma unroll
    for (int j = 0; j < 8; j++) {
        int i = tid + j * 256, r = i >> 5, c4 = (i & 31) * 4;
        cpa16(zb_sb[1] + (r * A_LDZ + c4) * 4, Zr + (size_t)(64 + r) * Dn + c4);
    }
    CP_COMMIT();
    CP_WAIT1();              // group0 (zq + tile0) complete
    __syncthreads();

    // preload A fragments for scores (one-time)
    uint32_t aq[16][4];
#pragma unroll
    for (int kt = 0; kt < 16; kt++) {
        aq[kt][0] = zqb[(qr + g) * A_LDZ + kt * 8 + tig];
        aq[kt][1] = zqb[(qr + g + 8) * A_LDZ + kt * 8 + tig];
        aq[kt][2] = zqb[(qr + g) * A_LDZ + kt * 8 + tig + 4];
        aq[kt][3] = zqb[(qr + g + 8) * A_LDZ + kt * 8 + tig + 4];
    }

    float O[4][4] = {};
    float zs0 = 0.f, zs1 = 0.f, ts0 = 0.f, ts1 = 0.f;
    const int NT = Lnn / 64;  // 64

    for (int t = 0; t < NT; t++) {
        int cur = t & 1;
        if (t > 0) {
            CP_WAIT1();      // tile t complete (all older groups drained)
            __syncthreads();
        }
        const uint32_t* zb = zbuf[cur];

        // scores: kt-parity-split accumulators (4 independent chains/warp)
        float sc[2][2][4] = {};
#pragma unroll
        for (int kt = 0; kt < 16; kt++) {
            int par = kt & 1;
#pragma unroll
            for (int nt = 0; nt < 2; nt++) {
                int lb = ws * 16 + nt * 8 + g;
                uint32_t b0 = zb[lb * A_LDZ + kt * 8 + tig];
                uint32_t b1 = zb[lb * A_LDZ + kt * 8 + tig + 4];
                mma_tf32(sc[nt][par], aq[kt][0], aq[kt][1], aq[kt][2], aq[kt][3], b0, b1);
            }
        }

        int r0w = qr + g, r1w = qr + g + 8;
#pragma unroll
        for (int nt = 0; nt < 2; nt++) {
            int c0 = ws * 16 + nt * 8 + 2 * tig;
            float s0 = (sc[nt][0][0] + sc[nt][1][0]) * scale;
            float s1 = (sc[nt][0][1] + sc[nt][1][1]) * scale;
            float s2 = (sc[nt][0][2] + sc[nt][1][2]) * scale;
            float s3 = (sc[nt][0][3] + sc[nt][1][3]) * scale;
            float p0 = __expf(s0), p1 = __expf(s1), p2 = __expf(s2), p3 = __expf(s3);
            zs0 += p0 + p1; ts0 += p0 * s0 + p1 * s1;
            zs1 += p2 + p3; ts1 += p2 * s2 + p3 * s3;
            ps_s[r0w * A_LDP + c0] = f2tf32(p0);
            ps_s[r0w * A_LDP + c0 + 1] = f2tf32(p1);
            ps_s[r1w * A_LDP + c0] = f2tf32(p2);
            ps_s[r1w * A_LDP + c0 + 1] = f2tf32(p3);
        }
        __syncthreads();

        // PV: A = P, B = zb transposed; warp covers d [ws*32, ws*32+32)
        uint32_t ap[8][4];
#pragma unroll
        for (int kt = 0; kt < 8; kt++) {
            ap[kt][0] = ps_s[(qr + g) * A_LDP + kt * 8 + tig];
            ap[kt][1] = ps_s[(qr + g + 8) * A_LDP + kt * 8 + tig];
            ap[kt][2] = ps_s[(qr + g) * A_LDP + kt * 8 + tig + 4];
            ap[kt][3] = ps_s[(qr + g + 8) * A_LDP + kt * 8 + tig + 4];
        }
#pragma unroll
        for (int kt = 0; kt < 8; kt++) {
#pragma unroll
            for (int nt = 0; nt < 4; nt++) {
                int db = ws * 32 + nt * 8 + g;
                uint32_t b0 = zb[(kt * 8 + tig) * A_LDZ + db];
                uint32_t b1 = zb[(kt * 8 + tig + 4) * A_LDZ + db];
                mma_tf32(O[nt], ap[kt][0], ap[kt][1], ap[kt][2], ap[kt][3], b0, b1);
            }
        }
        __syncthreads();     // zbuf[cur] free for restaging

        if (t + 2 < NT) {
            const float* src = Zr + (size_t)(t + 2) * 64 * Dn;
#pragma unroll
            for (int j = 0; j < 8; j++) {
                int i = tid + j * 256, r = i >> 5, c4 = (i & 31) * 4;
                cpa16(zb_sb[cur] + (r * A_LDZ + c4) * 4, src + (size_t)r * Dn + c4);
            }
        }
        CP_COMMIT();         // always commit (possibly empty) to keep group count consistent
    }

    // reduce zs/ts over the tig quad
    zs0 += __shfl_xor_sync(~0u, zs0, 1); zs0 += __shfl_xor_sync(~0u, zs0, 2);
    zs1 += __shfl_xor_sync(~0u, zs1, 1); zs1 += __shfl_xor_sync(~0u, zs1, 2);
    ts0 += __shfl_xor_sync(~0u, ts0, 1); ts0 += __shfl_xor_sync(~0u, ts0, 2);
    ts1 += __shfl_xor_sync(~0u, ts1, 1); ts1 += __shfl_xor_sync(~0u, ts1, 2);
    if (tig == 0) {
        zpart[ws][qr + g] = zs0; zpart[ws][qr + g + 8] = zs1;
        tpart[ws][qr + g] = ts0; tpart[ws][qr + g + 8] = ts1;
    }

    // dump O fragments to smem (float [32][132])
    float* Os = (float*)zbuf[0];
#pragma unroll
    for (int nt = 0; nt < 4; nt++) {
        int dc = ws * 32 + nt * 8 + 2 * tig;
        Os[(qr + g) * 132 + dc] = O[nt][0];
        Os[(qr + g) * 132 + dc + 1] = O[nt][1];
        Os[(qr + g + 8) * 132 + dc] = O[nt][2];
        Os[(qr + g + 8) * 132 + dc + 1] = O[nt][3];
    }
    __syncthreads();

    int row = tid >> 3, oct = tid & 7;
    float4 v[4];
    float sq = 0.f;
#pragma unroll
    for (int j = 0; j < 4; j++) {
        v[j] = *(float4*)&Os[row * 132 + oct * 16 + j * 4];
        sq += v[j].x * v[j].x + v[j].y * v[j].y + v[j].z * v[j].z + v[j].w * v[j].w;
    }
    sq += __shfl_xor_sync(~0u, sq, 1);
    sq += __shfl_xor_sync(~0u, sq, 2);
    sq += __shfl_xor_sync(~0u, sq, 4);
    float rn = 1.f / fmaxf(sqrtf(sq), 1e-12f);
    float* dst = Rbar + (size_t)(q0 + row) * Dn + oct * 16;
#pragma unroll
    for (int j = 0; j < 4; j++) {
        float4 o = {v[j].x * rn, v[j].y * rn, v[j].z * rn, v[j].w * rn};
        *(float4*)(dst + j * 4) = o;
    }
    if (oct == 0) {
        float zsum = zpart[0][row] + zpart[1][row] + zpart[2][row] + zpart[3][row];
        float tsum = tpart[0][row] + tpart[1][row] + tpart[2][row] + tpart[3][row];
        ent[q0 + row] = logf(zsum) - tsum / zsum;
    }
}

// ---------------- Final: dec MLP + scalar heads ----------------
__global__ void final_kernel(const float* __restrict__ Zq, const float* __restrict__ Rbar,
                             const float* __restrict__ ent,
                             const float* __restrict__ gd, const float* __restrict__ bd,
                             const float* __restrict__ W1d, const float* __restrict__ b1d,
                             const float* __restrict__ W2d, const float* __restrict__ b2d,
                             const float* __restrict__ beta, const float* __restrict__ Wlen,
                             const float* __restrict__ blen, float* __restrict__ out) {
    __shared__ float raw[8][D2n];
    __shared__ float nrm[8][D2n];
    __shared__ float part[8][128];
    __shared__ float coss[8];
    int r0 = blockIdx.x * 8, tid = threadIdx.x;
    for (int i = tid; i < 8 * Dn; i += 128) {
        int r = i >> 7, d = i & 127;
        raw[r][d] = Zq[(size_t)(r0 + r) * Dn + d];
        raw[r][128 + d] = Rbar[(size_t)(r0 + r) * Dn + d];
    }
    __syncthreads();
    int w = tid >> 5, lane = tid & 31;
#pragma unroll
    for (int rr = 0; rr < 2; rr++) {
        int r = 2 * w + rr;
        float cs = 0.f, smv = 0.f;
        for (int k = lane; k < D2n; k += 32) smv += raw[r][k];
        for (int k = lane; k < Dn; k += 32) cs += raw[r][k] * raw[r][128 + k];
#pragma unroll
        for (int o = 16; o > 0; o >>= 1) { smv += __shfl_xor_sync(~0u, smv, o); cs += __shfl_xor_sync(~0u, cs, o); }
        float mean = smv * (1.f / D2n);
        float vq = 0.f;
        for (int k = lane; k < D2n; k += 32) { float d = raw[r][k] - mean; vq += d * d; }
#pragma unroll
        for (int o = 16; o > 0; o >>= 1) vq += __shfl_xor_sync(~0u, vq, o);
        float rstd = rsqrtf(vq * (1.f / D2n) + 1e-5f);
        for (int k = lane; k < D2n; k += 32) nrm[r][k] = (raw[r][k] - mean) * rstd * gd[k] + bd[k];
        if (lane == 0) coss[r] = cs;
    }
    __syncthreads();
    float b1 = b1d[tid];
    float acc[8] = {b1, b1, b1, b1, b1, b1, b1, b1};
    const float* wrow = W1d + (size_t)tid * D2n;
    for (int k = 0; k < D2n; k += 4) {
        float4 w4 = *(const float4*)(wrow + k);
#pragma unroll
        for (int r = 0; r < 8; r++) {
            float4 h4 = *(const float4*)&nrm[r][k];
            acc[r] += h4.x * w4.x + h4.y * w4.y + h4.z * w4.z + h4.w * w4.w;
        }
    }
    float w2 = W2d[tid];
#pragma unroll
    for (int r = 0; r < 8; r++) {
        float v = acc[r];
        v = 0.5f * v * (1.f + erff(v * 0.7071067811865475f));
        part[r][tid] = v * w2;
    }
    __syncthreads();
#pragma unroll
    for (int rr = 0; rr < 2; rr++) {
        int r = 2 * w + rr;
        float s = 0.f;
        for (int k = lane; k < 128; k += 32) s += part[r][k];
#pragma unroll
        for (int o = 16; o > 0; o >>= 1) s += __shfl_xor_sync(~0u, s, o);
        if (lane == 0) {
            float raw_logit = s + b2d[0];
            float u = ent[r0 + r] * (1.f / logf((float)Lnn));
            float cs = coss[r];
            float dl = Wlen[0] * cs + Wlen[1] * u + blen[0];
            float lf = tanhf(dl);
            float dt = beta[0] * u + beta[1] * lf;
            dt = fminf(fmaxf(dt, -0.5f), 0.5f);
            out[r0 + r] = raw_logit;
            out[Bn + r0 + r] = dt;
        }
    }
}

// ---------------- host launcher ----------------
extern "C" void kernel_launch(void* const* d_in, const int* in_sizes, int n_in,
                              void* d_out, int out_size) {
    const float* q    = (const float*)d_in[0];
    const float* R    = (const float*)d_in[1];
    const float* lnqg = (const float*)d_in[2];
    const float* lnqb = (const float*)d_in[3];
    const float* W1q  = (const float*)d_in[4];
    const float* b1q  = (const float*)d_in[5];
    const float* W2q  = (const float*)d_in[6];
    const float* b2q  = (const float*)d_in[7];
    const float* lnrg = (const float*)d_in[8];
    const float* lnrb = (const float*)d_in[9];
    const float* W1r  = (const float*)d_in[10];
    const float* b1r  = (const float*)d_in[11];
    const float* W2r  = (const float*)d_in[12];
    const float* b2r  = (const float*)d_in[13];
    const float* lndg = (const float*)d_in[14];
    const float* lndb = (const float*)d_in[15];
    const float* W1d  = (const float*)d_in[16];
    const float* b1d  = (const float*)d_in[17];
    const float* W2d  = (const float*)d_in[18];
    const float* b2d  = (const float*)d_in[19];
    const float* beta = (const float*)d_in[20];
    const float* Wlen = (const float*)d_in[21];
    const float* blen = (const float*)d_in[22];
    float* out = (float*)d_out;

    float *hb, *zq, *zr, *rb, *en, *mu, *rs;
    cudaGetSymbolAddress((void**)&hb, g_Hb);
    cudaGetSymbolAddress((void**)&zq, g_Zq);
    cudaGetSymbolAddress((void**)&zr, g_Zr);
    cudaGetSymbolAddress((void**)&rb, g_Rbar);
    cudaGetSymbolAddress((void**)&en, g_ent);
    cudaGetSymbolAddress((void**)&mu, g_mu);
    cudaGetSymbolAddress((void**)&rs, g_rs);

    cudaFuncSetAttribute(gemm1_both, cudaFuncAttributeMaxDynamicSharedMemorySize, G1_SMEM);
    cudaFuncSetAttribute(attn_mma, cudaFuncAttributeMaxDynamicSharedMemorySize, ATTN_SMEM);

    // LN stats for q and R in one launch
    row_stats_both<<<dim3(Bn / 8, 2), 256>>>(q, R, mu, rs);
    // both GEMM1s in one launch
    gemm1_both<<<dim3(D2n / 64, Bn / 128, 2), 256, G1_SMEM>>>(
        q, R, W1q, W1r, lnqg, lnrg, lnqb, lnrb, b1q, b1r, mu, rs, hb);
    // both GEMM2s in one launch (outputs tf32-rounded Z)
    gemm2_both<<<dim3(Bn / 4, 2), 128>>>(hb, W2q, W2r, b2q, b2r, zq, zr);
    // attention + entropy + r_bar
    attn_mma<<<Bn / 32, 256, ATTN_SMEM>>>(zq, zr, rb, en);
    // decision MLP + scalar heads
    final_kernel<<<Bn / 8, 128>>>(zq, rb, en, lndg, lndb, W1d, b1d, W2d, b2d,
                                  beta, Wlen, blen, out);
}

// round 10
// speedup vs baseline: 4.7141x; 1.4675x over previous
#include <cuda_runtime.h>
#include <math.h>
#include <stdint.h>

#define Bn   4096
#define Lnn  4096
#define Hn   2048
#define Dn   128
#define D2n  256

// ---------------- scratch ----------------
__device__ float g_Hb[(size_t)2 * Bn * D2n];
__device__ float g_Zq[(size_t)Bn * Dn];
__device__ float g_Zr[(size_t)Lnn * Dn];
__device__ float g_Rbar[(size_t)Bn * Dn];
__device__ float g_ent[Bn];
__device__ float g_mu[2 * Bn];
__device__ float g_rs[2 * Bn];
__device__ float g_W1T[128 * 256];   // W1d transposed: [k][j]

extern __shared__ char dynsm[];

// ================= helpers =================
__device__ __forceinline__ uint32_t f2tf32(float f) {
    uint32_t r;
    asm("cvt.rna.tf32.f32 %0, %1;" : "=r"(r) : "f"(f));
    return r;
}

__device__ __forceinline__ void mma_tf32(float* c, uint32_t a0, uint32_t a1, uint32_t a2, uint32_t a3,
                                         uint32_t b0, uint32_t b1) {
    asm volatile(
        "mma.sync.aligned.m16n8k8.row.col.f32.tf32.tf32.f32 "
        "{%0,%1,%2,%3}, {%4,%5,%6,%7}, {%8,%9}, {%0,%1,%2,%3};"
        : "+f"(c[0]), "+f"(c[1]), "+f"(c[2]), "+f"(c[3])
        : "r"(a0), "r"(a1), "r"(a2), "r"(a3), "r"(b0), "r"(b1));
}

__device__ __forceinline__ void cpa16(uint32_t dst, const void* src) {
    asm volatile("cp.async.cg.shared.global [%0], [%1], 16;" :: "r"(dst), "l"(src));
}
#define CP_COMMIT() asm volatile("cp.async.commit_group;" ::: "memory")
#define CP_WAIT1()  asm volatile("cp.async.wait_group 1;" ::: "memory")

// ---------------- per-row mean/rstd, both inputs in one launch ----------------
__global__ void row_stats_both(const float* __restrict__ xq, const float* __restrict__ xr,
                               float* __restrict__ mu, float* __restrict__ rs) {
    int z = blockIdx.y;
    const float* x = z ? xr : xq;
    int wid = threadIdx.x >> 5, lane = threadIdx.x & 31;
    int row = blockIdx.x * 8 + wid;
    const float4* xrow = (const float4*)(x + (size_t)row * Hn);
    float s = 0.f, sq = 0.f;
    for (int k = lane; k < Hn / 4; k += 32) {
        float4 v = xrow[k];
        s += v.x + v.y + v.z + v.w;
        sq += v.x * v.x + v.y * v.y + v.z * v.z + v.w * v.w;
    }
#pragma unroll
    for (int o = 16; o > 0; o >>= 1) {
        s += __shfl_xor_sync(~0u, s, o);
        sq += __shfl_xor_sync(~0u, sq, o);
    }
    if (lane == 0) {
        float m = s * (1.f / Hn);
        float var = sq * (1.f / Hn) - m * m;
        mu[z * Bn + row] = m;
        rs[z * Bn + row] = rsqrtf(var + 1e-5f);
    }
}

// ---------------- W1d transpose (128x256 -> 256x128) ----------------
__global__ void transpose_w1(const float* __restrict__ W1d, float* __restrict__ W1T) {
    __shared__ float tsm[32][33];
    int bx = blockIdx.x, by = blockIdx.y;
    int x = threadIdx.x, y = threadIdx.y;
#pragma unroll
    for (int i = 0; i < 32; i += 8)
        tsm[y + i][x] = W1d[(by * 32 + y + i) * 256 + bx * 32 + x];
    __syncthreads();
#pragma unroll
    for (int i = 0; i < 32; i += 8)
        W1T[(bx * 32 + y + i) * 128 + by * 32 + x] = tsm[x][y + i];
}

// ---------------- GEMM1 (tf32 mma) + fused LN + GELU, both paths via blockIdx.z ----------------
#define G1_LD 36
#define G1_AS (128 * G1_LD)
#define G1_BS (64 * G1_LD)
#define G1_SMEM ((2 * G1_AS + 2 * G1_BS) * 4)

__global__ void __launch_bounds__(256, 2) gemm1_both(
        const float* __restrict__ Aq, const float* __restrict__ Ar,
        const float* __restrict__ Wq, const float* __restrict__ Wr,
        const float* __restrict__ gq, const float* __restrict__ gr,
        const float* __restrict__ bq, const float* __restrict__ br,
        const float* __restrict__ biasq, const float* __restrict__ biasr,
        const float* __restrict__ mean, const float* __restrict__ rstd,
        float* __restrict__ Cb) {
    int z = blockIdx.z;
    const float* A = z ? Ar : Aq;
    const float* W = z ? Wr : Wq;
    const float* gamma = z ? gr : gq;
    const float* beta = z ? br : bq;
    const float* bias = z ? biasr : biasq;
    float* C = Cb + (size_t)z * Bn * D2n;
    const float* mub = mean + z * Bn;
    const float* rsb = rstd + z * Bn;

    uint32_t* sm = (uint32_t*)dynsm;
    uint32_t* Asm[2] = { sm, sm + G1_AS };
    uint32_t* Bsm[2] = { sm + 2 * G1_AS, sm + 2 * G1_AS + G1_BS };

    int tid = threadIdx.x;
    int wid = tid >> 5, lane = tid & 31;
    int wm = wid & 3, wn = wid >> 2;
    int g = lane >> 2, tig = lane & 3;
    int m0 = blockIdx.y * 128, n0 = blockIdx.x * 64;
    int q = tid >> 3, f4 = tid & 7;

    const float4* Arow[4];
    float mu[4], rsd[4];
#pragma unroll
    for (int j = 0; j < 4; j++) {
        int r = m0 + q + 32 * j;
        Arow[j] = (const float4*)(A + (size_t)r * Hn);
        mu[j] = mub[r];
        rsd[j] = rsb[r];
    }
    const float4* Brow[2];
#pragma unroll
    for (int j = 0; j < 2; j++) Brow[j] = (const float4*)(W + (size_t)(n0 + q + 32 * j) * Hn);
    const float4* g4p = (const float4*)gamma;
    const float4* b4p = (const float4*)beta;

    float acc[2][4][4] = {};
    float4 pA[4], pB[2], pG, pBt;

    const int NT = Hn / 32;  // 64

    pG = g4p[f4]; pBt = b4p[f4];
#pragma unroll
    for (int j = 0; j < 4; j++) pA[j] = Arow[j][f4];
#pragma unroll
    for (int j = 0; j < 2; j++) pB[j] = Brow[j][f4];
#pragma unroll
    for (int j = 0; j < 4; j++) {
        float x0 = (pA[j].x - mu[j]) * rsd[j] * pG.x + pBt.x;
        float x1 = (pA[j].y - mu[j]) * rsd[j] * pG.y + pBt.y;
        float x2 = (pA[j].z - mu[j]) * rsd[j] * pG.z + pBt.z;
        float x3 = (pA[j].w - mu[j]) * rsd[j] * pG.w + pBt.w;
        uint4 u = { f2tf32(x0), f2tf32(x1), f2tf32(x2), f2tf32(x3) };
        *(uint4*)&Asm[0][(q + 32 * j) * G1_LD + f4 * 4] = u;
    }
#pragma unroll
    for (int j = 0; j < 2; j++) {
        uint4 u = { f2tf32(pB[j].x), f2tf32(pB[j].y), f2tf32(pB[j].z), f2tf32(pB[j].w) };
        *(uint4*)&Bsm[0][(q + 32 * j) * G1_LD + f4 * 4] = u;
    }
    __syncthreads();

    for (int t = 0; t < NT; t++) {
        int cur = t & 1;
        if (t + 1 < NT) {
            pG = g4p[(t + 1) * 8 + f4]; pBt = b4p[(t + 1) * 8 + f4];
#pragma unroll
            for (int j = 0; j < 4; j++) pA[j] = Arow[j][(t + 1) * 8 + f4];
#pragma unroll
            for (int j = 0; j < 2; j++) pB[j] = Brow[j][(t + 1) * 8 + f4];
        }
        const uint32_t* Ab = Asm[cur];
        const uint32_t* Bb = Bsm[cur];
#pragma unroll
        for (int ks = 0; ks < 4; ks++) {
            int k = ks * 8;
            uint32_t bf[4][2];
#pragma unroll
            for (int nt = 0; nt < 4; nt++) {
                int nc = wn * 32 + nt * 8 + g;
                bf[nt][0] = Bb[nc * G1_LD + k + tig];
                bf[nt][1] = Bb[nc * G1_LD + k + tig + 4];
            }
#pragma unroll
            for (int mt = 0; mt < 2; mt++) {
                int mr = wm * 32 + mt * 16 + g;
                uint32_t a0 = Ab[mr * G1_LD + k + tig];
                uint32_t a1 = Ab[(mr + 8) * G1_LD + k + tig];
                uint32_t a2 = Ab[mr * G1_LD + k + tig + 4];
                uint32_t a3 = Ab[(mr + 8) * G1_LD + k + tig + 4];
#pragma unroll
                for (int nt = 0; nt < 4; nt++)
                    mma_tf32(acc[mt][nt], a0, a1, a2, a3, bf[nt][0], bf[nt][1]);
            }
        }
        if (t + 1 < NT) {
            int nxt = cur ^ 1;
#pragma unroll
            for (int j = 0; j < 4; j++) {
                float x0 = (pA[j].x - mu[j]) * rsd[j] * pG.x + pBt.x;
                float x1 = (pA[j].y - mu[j]) * rsd[j] * pG.y + pBt.y;
                float x2 = (pA[j].z - mu[j]) * rsd[j] * pG.z + pBt.z;
                float x3 = (pA[j].w - mu[j]) * rsd[j] * pG.w + pBt.w;
                uint4 u = { f2tf32(x0), f2tf32(x1), f2tf32(x2), f2tf32(x3) };
                *(uint4*)&Asm[nxt][(q + 32 * j) * G1_LD + f4 * 4] = u;
            }
#pragma unroll
            for (int j = 0; j < 2; j++) {
                uint4 u = { f2tf32(pB[j].x), f2tf32(pB[j].y), f2tf32(pB[j].z), f2tf32(pB[j].w) };
                *(uint4*)&Bsm[nxt][(q + 32 * j) * G1_LD + f4 * 4] = u;
            }
        }
        __syncthreads();
    }

#pragma unroll
    for (int mt = 0; mt < 2; mt++) {
#pragma unroll
        for (int nt = 0; nt < 4; nt++) {
            int n = n0 + wn * 32 + nt * 8 + 2 * tig;
            float bv0 = bias[n], bv1 = bias[n + 1];
#pragma unroll
            for (int rr = 0; rr < 2; rr++) {
                int m = m0 + wm * 32 + mt * 16 + g + rr * 8;
                float v0 = acc[mt][nt][rr * 2 + 0] + bv0;
                float v1 = acc[mt][nt][rr * 2 + 1] + bv1;
                v0 = 0.5f * v0 * (1.f + erff(v0 * 0.7071067811865475f));
                v1 = 0.5f * v1 * (1.f + erff(v1 * 0.7071067811865475f));
                float2 o = {v0, v1};
                *(float2*)(C + (size_t)m * D2n + n) = o;
            }
        }
    }
}

// ---------------- GEMM2 via tf32 mma + fused bias + l2norm ----------------
// Z[m, 0..127] = l2n(H[m, 0..255] @ W2^T + b2). BM=128, BN=128(=D), BK=32, NT=8.
// 256 threads = 8 warps: wm=wid&3 (32 rows), wn=wid>>2 (64 cols).
#define G2_LD 36
#define G2_TS (128 * G2_LD)
#define G2_SMEM (4 * G2_TS * 4)

__global__ void __launch_bounds__(256, 1) gemm2_mma(
        const float* __restrict__ Hb,
        const float* __restrict__ W2q, const float* __restrict__ W2r,
        const float* __restrict__ b2q, const float* __restrict__ b2r,
        float* __restrict__ Zq, float* __restrict__ Zr) {
    int z = blockIdx.y;
    const float* Hin = Hb + (size_t)z * Bn * D2n;
    const float* W2 = z ? W2r : W2q;
    const float* b2 = z ? b2r : b2q;
    float* Z = z ? Zr : Zq;

    uint32_t* sm = (uint32_t*)dynsm;
    uint32_t* Asm[2] = { sm, sm + G2_TS };
    uint32_t* Bsm[2] = { sm + 2 * G2_TS, sm + 3 * G2_TS };

    int tid = threadIdx.x;
    int wid = tid >> 5, lane = tid & 31;
    int wm = wid & 3, wn = wid >> 2;
    int g = lane >> 2, tig = lane & 3;
    int m0 = blockIdx.x * 128;
    int q8 = tid >> 3, f4 = tid & 7;

    const float4* Arow[4];
    const float4* Brow[4];
#pragma unroll
    for (int j = 0; j < 4; j++) {
        Arow[j] = (const float4*)(Hin + (size_t)(m0 + q8 + 32 * j) * D2n);
        Brow[j] = (const float4*)(W2 + (size_t)(q8 + 32 * j) * D2n);
    }

    float acc[2][8][4] = {};
    float4 pA[4], pB[4];
    const int NT = D2n / 32;  // 8

#pragma unroll
    for (int j = 0; j < 4; j++) { pA[j] = Arow[j][f4]; pB[j] = Brow[j][f4]; }
#pragma unroll
    for (int j = 0; j < 4; j++) {
        uint4 ua = { f2tf32(pA[j].x), f2tf32(pA[j].y), f2tf32(pA[j].z), f2tf32(pA[j].w) };
        uint4 ub = { f2tf32(pB[j].x), f2tf32(pB[j].y), f2tf32(pB[j].z), f2tf32(pB[j].w) };
        *(uint4*)&Asm[0][(q8 + 32 * j) * G2_LD + f4 * 4] = ua;
        *(uint4*)&Bsm[0][(q8 + 32 * j) * G2_LD + f4 * 4] = ub;
    }
    __syncthreads();

    for (int t = 0; t < NT; t++) {
        int cur = t & 1;
        if (t + 1 < NT) {
#pragma unroll
            for (int j = 0; j < 4; j++) {
                pA[j] = Arow[j][(t + 1) * 8 + f4];
                pB[j] = Brow[j][(t + 1) * 8 + f4];
            }
        }
        const uint32_t* Ab = Asm[cur];
        const uint32_t* Bb = Bsm[cur];
#pragma unroll
        for (int ks = 0; ks < 4; ks++) {
            int k = ks * 8;
            uint32_t bf[8][2];
#pragma unroll
            for (int nt = 0; nt < 8; nt++) {
                int nc = wn * 64 + nt * 8 + g;
                bf[nt][0] = Bb[nc * G2_LD + k + tig];
                bf[nt][1] = Bb[nc * G2_LD + k + tig + 4];
            }
#pragma unroll
            for (int mt = 0; mt < 2; mt++) {
                int mr = wm * 32 + mt * 16 + g;
                uint32_t a0 = Ab[mr * G2_LD + k + tig];
                uint32_t a1 = Ab[(mr + 8) * G2_LD + k + tig];
                uint32_t a2 = Ab[mr * G2_LD + k + tig + 4];
                uint32_t a3 = Ab[(mr + 8) * G2_LD + k + tig + 4];
#pragma unroll
                for (int nt = 0; nt < 8; nt++)
                    mma_tf32(acc[mt][nt], a0, a1, a2, a3, bf[nt][0], bf[nt][1]);
            }
        }
        if (t + 1 < NT) {
            int nxt = cur ^ 1;
#pragma unroll
            for (int j = 0; j < 4; j++) {
                uint4 ua = { f2tf32(pA[j].x), f2tf32(pA[j].y), f2tf32(pA[j].z), f2tf32(pA[j].w) };
                uint4 ub = { f2tf32(pB[j].x), f2tf32(pB[j].y), f2tf32(pB[j].z), f2tf32(pB[j].w) };
                *(uint4*)&Asm[nxt][(q8 + 32 * j) * G2_LD + f4 * 4] = ua;
                *(uint4*)&Bsm[nxt][(q8 + 32 * j) * G2_LD + f4 * 4] = ub;
            }
        }
        __syncthreads();
    }

    // epilogue: bias, row sum-of-squares, l2-normalize, write tf32-rounded Z
    float bv[8][2];
#pragma unroll
    for (int nt = 0; nt < 8; nt++) {
        int c = wn * 64 + nt * 8 + 2 * tig;
        bv[nt][0] = b2[c]; bv[nt][1] = b2[c + 1];
    }
    float p[2][2] = {};
#pragma unroll
    for (int mt = 0; mt < 2; mt++)
#pragma unroll
        for (int nt = 0; nt < 8; nt++) {
            acc[mt][nt][0] += bv[nt][0]; acc[mt][nt][1] += bv[nt][1];
            acc[mt][nt][2] += bv[nt][0]; acc[mt][nt][3] += bv[nt][1];
            p[mt][0] += acc[mt][nt][0] * acc[mt][nt][0] + acc[mt][nt][1] * acc[mt][nt][1];
            p[mt][1] += acc[mt][nt][2] * acc[mt][nt][2] + acc[mt][nt][3] * acc[mt][nt][3];
        }
#pragma unroll
    for (int mt = 0; mt < 2; mt++)
#pragma unroll
        for (int rr = 0; rr < 2; rr++) {
            p[mt][rr] += __shfl_xor_sync(~0u, p[mt][rr], 1);
            p[mt][rr] += __shfl_xor_sync(~0u, p[mt][rr], 2);
        }
    float* norms = (float*)sm;  // 256 floats: [wn][128]
    if (tig == 0) {
#pragma unroll
        for (int mt = 0; mt < 2; mt++)
#pragma unroll
            for (int rr = 0; rr < 2; rr++)
                norms[wn * 128 + wm * 32 + mt * 16 + rr * 8 + g] = p[mt][rr];
    }
    __syncthreads();
#pragma unroll
    for (int mt = 0; mt < 2; mt++)
#pragma unroll
        for (int rr = 0; rr < 2; rr++) {
            int rl = wm * 32 + mt * 16 + rr * 8 + g;
            float tot = norms[rl] + norms[128 + rl];
            float rn = 1.f / fmaxf(sqrtf(tot), 1e-12f);
            int row = m0 + rl;
#pragma unroll
            for (int nt = 0; nt < 8; nt++) {
                int c = wn * 64 + nt * 8 + 2 * tig;
                float2 o = { __uint_as_float(f2tf32(acc[mt][nt][rr * 2 + 0] * rn)),
                             __uint_as_float(f2tf32(acc[mt][nt][rr * 2 + 1] * rn)) };
                *(float2*)&Z[(size_t)row * Dn + c] = o;
            }
        }
}

// ---------------- Attention: tf32 mma + cp.async double-buffered staging ----------------
#define A_LDZ 136
#define A_LDP 68
#define A_ZQW (32 * A_LDZ)
#define A_ZBW (64 * A_LDZ)
#define ATTN_SMEM ((A_ZQW + 2 * A_ZBW + 32 * A_LDP) * 4)
__global__ void __launch_bounds__(256, 1) attn_mma(const float* __restrict__ Zq, const float* __restrict__ Zr,
                                                   float* __restrict__ Rbar, float* __restrict__ ent) {
    uint32_t* smw = (uint32_t*)dynsm;
    uint32_t* zqb = smw;
    uint32_t* zbuf[2] = { smw + A_ZQW, smw + A_ZQW + A_ZBW };
    uint32_t* ps_s = smw + A_ZQW + 2 * A_ZBW;
    __shared__ float zpart[4][32];
    __shared__ float tpart[4][32];

    int tid = threadIdx.x;
    int wid = tid >> 5, lane = tid & 31;
    int wq = wid >> 2, ws = wid & 3;
    int g = lane >> 2, tig = lane & 3;
    int q0 = blockIdx.x * 32;
    int qr = wq * 16;
    const float scale = 0.08838834764831845f;  // 1/sqrt(128)

    uint32_t zq_sb = (uint32_t)__cvta_generic_to_shared(zqb);
    uint32_t zb_sb[2] = { (uint32_t)__cvta_generic_to_shared(zbuf[0]),
                          (uint32_t)__cvta_generic_to_shared(zbuf[1]) };

#pragma unroll
    for (int j = 0; j < 4; j++) {
        int i = tid + j * 256, r = i >> 5, c4 = (i & 31) * 4;
        cpa16(zq_sb + (r * A_LDZ + c4) * 4, Zq + (size_t)(q0 + r) * Dn + c4);
    }
#pragma unroll
    for (int j = 0; j < 8; j++) {
        int i = tid + j * 256, r = i >> 5, c4 = (i & 31) * 4;
        cpa16(zb_sb[0] + (r * A_LDZ + c4) * 4, Zr + (size_t)r * Dn + c4);
    }
    CP_COMMIT();
#pragma unroll
    for (int j = 0; j < 8; j++) {
        int i = tid + j * 256, r = i >> 5, c4 = (i & 31) * 4;
        cpa16(zb_sb[1] + (r * A_LDZ + c4) * 4, Zr + (size_t)(64 + r) * Dn + c4);
    }
    CP_COMMIT();
    CP_WAIT1();
    __syncthreads();

    uint32_t aq[16][4];
#pragma unroll
    for (int kt = 0; kt < 16; kt++) {
        aq[kt][0] = zqb[(qr + g) * A_LDZ + kt * 8 + tig];
        aq[kt][1] = zqb[(qr + g + 8) * A_LDZ + kt * 8 + tig];
        aq[kt][2] = zqb[(qr + g) * A_LDZ + kt * 8 + tig + 4];
        aq[kt][3] = zqb[(qr + g + 8) * A_LDZ + kt * 8 + tig + 4];
    }

    float O[4][4] = {};
    float zs0 = 0.f, zs1 = 0.f, ts0 = 0.f, ts1 = 0.f;
    const int NT = Lnn / 64;  // 64

    for (int t = 0; t < NT; t++) {
        int cur = t & 1;
        if (t > 0) {
            CP_WAIT1();
            __syncthreads();
        }
        const uint32_t* zb = zbuf[cur];

        float sc[2][2][4] = {};
#pragma unroll
        for (int kt = 0; kt < 16; kt++) {
            int par = kt & 1;
#pragma unroll
            for (int nt = 0; nt < 2; nt++) {
                int lb = ws * 16 + nt * 8 + g;
                uint32_t b0 = zb[lb * A_LDZ + kt * 8 + tig];
                uint32_t b1 = zb[lb * A_LDZ + kt * 8 + tig + 4];
                mma_tf32(sc[nt][par], aq[kt][0], aq[kt][1], aq[kt][2], aq[kt][3], b0, b1);
            }
        }

        int r0w = qr + g, r1w = qr + g + 8;
#pragma unroll
        for (int nt = 0; nt < 2; nt++) {
            int c0 = ws * 16 + nt * 8 + 2 * tig;
            float s0 = (sc[nt][0][0] + sc[nt][1][0]) * scale;
            float s1 = (sc[nt][0][1] + sc[nt][1][1]) * scale;
            float s2 = (sc[nt][0][2] + sc[nt][1][2]) * scale;
            float s3 = (sc[nt][0][3] + sc[nt][1][3]) * scale;
            float p0 = __expf(s0), p1 = __expf(s1), p2 = __expf(s2), p3 = __expf(s3);
            zs0 += p0 + p1; ts0 += p0 * s0 + p1 * s1;
            zs1 += p2 + p3; ts1 += p2 * s2 + p3 * s3;
            ps_s[r0w * A_LDP + c0] = f2tf32(p0);
            ps_s[r0w * A_LDP + c0 + 1] = f2tf32(p1);
            ps_s[r1w * A_LDP + c0] = f2tf32(p2);
            ps_s[r1w * A_LDP + c0 + 1] = f2tf32(p3);
        }
        __syncthreads();

        uint32_t ap[8][4];
#pragma unroll
        for (int kt = 0; kt < 8; kt++) {
            ap[kt][0] = ps_s[(qr + g) * A_LDP + kt * 8 + tig];
            ap[kt][1] = ps_s[(qr + g + 8) * A_LDP + kt * 8 + tig];
            ap[kt][2] = ps_s[(qr + g) * A_LDP + kt * 8 + tig + 4];
            ap[kt][3] = ps_s[(qr + g + 8) * A_LDP + kt * 8 + tig + 4];
        }
#pragma unroll
        for (int kt = 0; kt < 8; kt++) {
#pragma unroll
            for (int nt = 0; nt < 4; nt++) {
                int db = ws * 32 + nt * 8 + g;
                uint32_t b0 = zb[(kt * 8 + tig) * A_LDZ + db];
                uint32_t b1 = zb[(kt * 8 + tig + 4) * A_LDZ + db];
                mma_tf32(O[nt], ap[kt][0], ap[kt][1], ap[kt][2], ap[kt][3], b0, b1);
            }
        }
        __syncthreads();

        if (t + 2 < NT) {
            const float* src = Zr + (size_t)(t + 2) * 64 * Dn;
#pragma unroll
            for (int j = 0; j < 8; j++) {
                int i = tid + j * 256, r = i >> 5, c4 = (i & 31) * 4;
                cpa16(zb_sb[cur] + (r * A_LDZ + c4) * 4, src + (size_t)r * Dn + c4);
            }
        }
        CP_COMMIT();
    }

    zs0 += __shfl_xor_sync(~0u, zs0, 1); zs0 += __shfl_xor_sync(~0u, zs0, 2);
    zs1 += __shfl_xor_sync(~0u, zs1, 1); zs1 += __shfl_xor_sync(~0u, zs1, 2);
    ts0 += __shfl_xor_sync(~0u, ts0, 1); ts0 += __shfl_xor_sync(~0u, ts0, 2);
    ts1 += __shfl_xor_sync(~0u, ts1, 1); ts1 += __shfl_xor_sync(~0u, ts1, 2);
    if (tig == 0) {
        zpart[ws][qr + g] = zs0; zpart[ws][qr + g + 8] = zs1;
        tpart[ws][qr + g] = ts0; tpart[ws][qr + g + 8] = ts1;
    }

    float* Os = (float*)zbuf[0];
#pragma unroll
    for (int nt = 0; nt < 4; nt++) {
        int dc = ws * 32 + nt * 8 + 2 * tig;
        Os[(qr + g) * 132 + dc] = O[nt][0];
        Os[(qr + g) * 132 + dc + 1] = O[nt][1];
        Os[(qr + g + 8) * 132 + dc] = O[nt][2];
        Os[(qr + g + 8) * 132 + dc + 1] = O[nt][3];
    }
    __syncthreads();

    int row = tid >> 3, oct = tid & 7;
    float4 v[4];
    float sq = 0.f;
#pragma unroll
    for (int j = 0; j < 4; j++) {
        v[j] = *(float4*)&Os[row * 132 + oct * 16 + j * 4];
        sq += v[j].x * v[j].x + v[j].y * v[j].y + v[j].z * v[j].z + v[j].w * v[j].w;
    }
    sq += __shfl_xor_sync(~0u, sq, 1);
    sq += __shfl_xor_sync(~0u, sq, 2);
    sq += __shfl_xor_sync(~0u, sq, 4);
    float rn = 1.f / fmaxf(sqrtf(sq), 1e-12f);
    float* dst = Rbar + (size_t)(q0 + row) * Dn + oct * 16;
#pragma unroll
    for (int j = 0; j < 4; j++) {
        float4 o = {v[j].x * rn, v[j].y * rn, v[j].z * rn, v[j].w * rn};
        *(float4*)(dst + j * 4) = o;
    }
    if (oct == 0) {
        float zsum = zpart[0][row] + zpart[1][row] + zpart[2][row] + zpart[3][row];
        float tsum = tpart[0][row] + tpart[1][row] + tpart[2][row] + tpart[3][row];
        ent[q0 + row] = logf(zsum) - tsum / zsum;
    }
}

// ---------------- Final: dec MLP + scalar heads (W1 pre-transposed) ----------------
__global__ void final_kernel(const float* __restrict__ Zq, const float* __restrict__ Rbar,
                             const float* __restrict__ ent,
                             const float* __restrict__ gd, const float* __restrict__ bd,
                             const float* __restrict__ W1T, const float* __restrict__ b1d,
                             const float* __restrict__ W2d, const float* __restrict__ b2d,
                             const float* __restrict__ beta, const float* __restrict__ Wlen,
                             const float* __restrict__ blen, float* __restrict__ out) {
    __shared__ float raw[8][D2n];
    __shared__ float nrm[8][D2n];
    __shared__ float part[8][128];
    __shared__ float coss[8];
    int r0 = blockIdx.x * 8, tid = threadIdx.x;
    for (int i = tid; i < 8 * Dn; i += 128) {
        int r = i >> 7, d = i & 127;
        raw[r][d] = Zq[(size_t)(r0 + r) * Dn + d];
        raw[r][128 + d] = Rbar[(size_t)(r0 + r) * Dn + d];
    }
    __syncthreads();
    int w = tid >> 5, lane = tid & 31;
#pragma unroll
    for (int rr = 0; rr < 2; rr++) {
        int r = 2 * w + rr;
        float cs = 0.f, smv = 0.f;
        for (int k = lane; k < D2n; k += 32) smv += raw[r][k];
        for (int k = lane; k < Dn; k += 32) cs += raw[r][k] * raw[r][128 + k];
#pragma unroll
        for (int o = 16; o > 0; o >>= 1) { smv += __shfl_xor_sync(~0u, smv, o); cs += __shfl_xor_sync(~0u, cs, o); }
        float mean = smv * (1.f / D2n);
        float vq = 0.f;
        for (int k = lane; k < D2n; k += 32) { float d = raw[r][k] - mean; vq += d * d; }
#pragma unroll
        for (int o = 16; o > 0; o >>= 1) vq += __shfl_xor_sync(~0u, vq, o);
        float rstd = rsqrtf(vq * (1.f / D2n) + 1e-5f);
        for (int k = lane; k < D2n; k += 32) nrm[r][k] = (raw[r][k] - mean) * rstd * gd[k] + bd[k];
        if (lane == 0) coss[r] = cs;
    }
    __syncthreads();
    float b1 = b1d[tid];
    float acc[8] = {b1, b1, b1, b1, b1, b1, b1, b1};
    for (int k = 0; k < D2n; k += 4) {
        float wv0 = W1T[(k + 0) * 128 + tid];
        float wv1 = W1T[(k + 1) * 128 + tid];
        float wv2 = W1T[(k + 2) * 128 + tid];
        float wv3 = W1T[(k + 3) * 128 + tid];
#pragma unroll
        for (int r = 0; r < 8; r++) {
            float4 h4 = *(const float4*)&nrm[r][k];
            acc[r] += h4.x * wv0 + h4.y * wv1 + h4.z * wv2 + h4.w * wv3;
        }
    }
    float w2 = W2d[tid];
#pragma unroll
    for (int r = 0; r < 8; r++) {
        float v = acc[r];
        v = 0.5f * v * (1.f + erff(v * 0.7071067811865475f));
        part[r][tid] = v * w2;
    }
    __syncthreads();
#pragma unroll
    for (int rr = 0; rr < 2; rr++) {
        int r = 2 * w + rr;
        float s = 0.f;
        for (int k = lane; k < 128; k += 32) s += part[r][k];
#pragma unroll
        for (int o = 16; o > 0; o >>= 1) s += __shfl_xor_sync(~0u, s, o);
        if (lane == 0) {
            float raw_logit = s + b2d[0];
            float u = ent[r0 + r] * (1.f / logf((float)Lnn));
            float cs = coss[r];
            float dl = Wlen[0] * cs + Wlen[1] * u + blen[0];
            float lf = tanhf(dl);
            float dt = beta[0] * u + beta[1] * lf;
            dt = fminf(fmaxf(dt, -0.5f), 0.5f);
            out[r0 + r] = raw_logit;
            out[Bn + r0 + r] = dt;
        }
    }
}

// ---------------- host launcher ----------------
extern "C" void kernel_launch(void* const* d_in, const int* in_sizes, int n_in,
                              void* d_out, int out_size) {
    const float* q    = (const float*)d_in[0];
    const float* R    = (const float*)d_in[1];
    const float* lnqg = (const float*)d_in[2];
    const float* lnqb = (const float*)d_in[3];
    const float* W1q  = (const float*)d_in[4];
    const float* b1q  = (const float*)d_in[5];
    const float* W2q  = (const float*)d_in[6];
    const float* b2q  = (const float*)d_in[7];
    const float* lnrg = (const float*)d_in[8];
    const float* lnrb = (const float*)d_in[9];
    const float* W1r  = (const float*)d_in[10];
    const float* b1r  = (const float*)d_in[11];
    const float* W2r  = (const float*)d_in[12];
    const float* b2r  = (const float*)d_in[13];
    const float* lndg = (const float*)d_in[14];
    const float* lndb = (const float*)d_in[15];
    const float* W1d  = (const float*)d_in[16];
    const float* b1d  = (const float*)d_in[17];
    const float* W2d  = (const float*)d_in[18];
    const float* b2d  = (const float*)d_in[19];
    const float* beta = (const float*)d_in[20];
    const float* Wlen = (const float*)d_in[21];
    const float* blen = (const float*)d_in[22];
    float* out = (float*)d_out;

    float *hb, *zq, *zr, *rb, *en, *mu, *rs, *w1t;
    cudaGetSymbolAddress((void**)&hb, g_Hb);
    cudaGetSymbolAddress((void**)&zq, g_Zq);
    cudaGetSymbolAddress((void**)&zr, g_Zr);
    cudaGetSymbolAddress((void**)&rb, g_Rbar);
    cudaGetSymbolAddress((void**)&en, g_ent);
    cudaGetSymbolAddress((void**)&mu, g_mu);
    cudaGetSymbolAddress((void**)&rs, g_rs);
    cudaGetSymbolAddress((void**)&w1t, g_W1T);

    cudaFuncSetAttribute(gemm1_both, cudaFuncAttributeMaxDynamicSharedMemorySize, G1_SMEM);
    cudaFuncSetAttribute(gemm2_mma, cudaFuncAttributeMaxDynamicSharedMemorySize, G2_SMEM);
    cudaFuncSetAttribute(attn_mma, cudaFuncAttributeMaxDynamicSharedMemorySize, ATTN_SMEM);

    // LN stats + W1 transpose (independent)
    row_stats_both<<<dim3(Bn / 8, 2), 256>>>(q, R, mu, rs);
    transpose_w1<<<dim3(8, 4), dim3(32, 8)>>>(W1d, w1t);
    // both GEMM1s in one launch
    gemm1_both<<<dim3(D2n / 64, Bn / 128, 2), 256, G1_SMEM>>>(
        q, R, W1q, W1r, lnqg, lnrg, lnqb, lnrb, b1q, b1r, mu, rs, hb);
    // both GEMM2s via tf32 mma, fused l2norm (outputs tf32-rounded Z)
    gemm2_mma<<<dim3(Bn / 128, 2), 256, G2_SMEM>>>(hb, W2q, W2r, b2q, b2r, zq, zr);
    // attention + entropy + r_bar
    attn_mma<<<Bn / 32, 256, ATTN_SMEM>>>(zq, zr, rb, en);
    // decision MLP + scalar heads
    final_kernel<<<Bn / 8, 128>>>(zq, rb, en, lndg, lndb, w1t, b1d, W2d, b2d,
                                  beta, Wlen, blen, out);
}

// round 11
// speedup vs baseline: 4.9080x; 1.0411x over previous
#include <cuda_runtime.h>
#include <math.h>
#include <stdint.h>

#define Bn   4096
#define Lnn  4096
#define Hn   2048
#define Dn   128
#define D2n  256

// ---------------- scratch ----------------
__device__ float g_Hb[(size_t)2 * Bn * D2n];
__device__ float g_Zq[(size_t)Bn * Dn];
__device__ float g_Zr[(size_t)Lnn * Dn];
__device__ float g_Rbar[(size_t)Bn * Dn];
__device__ float g_ent[Bn];
__device__ float g_mu[2 * Bn];
__device__ float g_rs[2 * Bn];
__device__ float g_W1T[128 * 256];

extern __shared__ char dynsm[];

// ================= helpers =================
__device__ __forceinline__ uint32_t f2tf32(float f) {
    uint32_t r;
    asm("cvt.rna.tf32.f32 %0, %1;" : "=r"(r) : "f"(f));
    return r;
}

__device__ __forceinline__ void mma_tf32(float* c, uint32_t a0, uint32_t a1, uint32_t a2, uint32_t a3,
                                         uint32_t b0, uint32_t b1) {
    asm volatile(
        "mma.sync.aligned.m16n8k8.row.col.f32.tf32.tf32.f32 "
        "{%0,%1,%2,%3}, {%4,%5,%6,%7}, {%8,%9}, {%0,%1,%2,%3};"
        : "+f"(c[0]), "+f"(c[1]), "+f"(c[2]), "+f"(c[3])
        : "r"(a0), "r"(a1), "r"(a2), "r"(a3), "r"(b0), "r"(b1));
}

__device__ __forceinline__ void cpa16(uint32_t dst, const void* src) {
    asm volatile("cp.async.cg.shared.global [%0], [%1], 16;" :: "r"(dst), "l"(src));
}
#define CP_COMMIT() asm volatile("cp.async.commit_group;" ::: "memory")
#define CP_WAIT1()  asm volatile("cp.async.wait_group 1;" ::: "memory")

// ---------------- per-row mean/rstd, both inputs in one launch ----------------
__global__ void row_stats_both(const float* __restrict__ xq, const float* __restrict__ xr,
                               float* __restrict__ mu, float* __restrict__ rs) {
    int z = blockIdx.y;
    const float* x = z ? xr : xq;
    int wid = threadIdx.x >> 5, lane = threadIdx.x & 31;
    int row = blockIdx.x * 8 + wid;
    const float4* xrow = (const float4*)(x + (size_t)row * Hn);
    float s = 0.f, sq = 0.f;
    for (int k = lane; k < Hn / 4; k += 32) {
        float4 v = xrow[k];
        s += v.x + v.y + v.z + v.w;
        sq += v.x * v.x + v.y * v.y + v.z * v.z + v.w * v.w;
    }
#pragma unroll
    for (int o = 16; o > 0; o >>= 1) {
        s += __shfl_xor_sync(~0u, s, o);
        sq += __shfl_xor_sync(~0u, sq, o);
    }
    if (lane == 0) {
        float m = s * (1.f / Hn);
        float var = sq * (1.f / Hn) - m * m;
        mu[z * Bn + row] = m;
        rs[z * Bn + row] = rsqrtf(var + 1e-5f);
    }
}

// ---------------- W1d transpose (128x256 -> 256x128) ----------------
__global__ void transpose_w1(const float* __restrict__ W1d, float* __restrict__ W1T) {
    __shared__ float tsm[32][33];
    int bx = blockIdx.x, by = blockIdx.y;
    int x = threadIdx.x, y = threadIdx.y;
#pragma unroll
    for (int i = 0; i < 32; i += 8)
        tsm[y + i][x] = W1d[(by * 32 + y + i) * 256 + bx * 32 + x];
    __syncthreads();
#pragma unroll
    for (int i = 0; i < 32; i += 8)
        W1T[(bx * 32 + y + i) * 128 + by * 32 + x] = tsm[x][y + i];
}

// ---------------- GEMM1 (tf32 mma) + fused LN + GELU, both paths via blockIdx.z ----------------
#define G1_LD 36
#define G1_AS (128 * G1_LD)
#define G1_BS (64 * G1_LD)
#define G1_SMEM ((2 * G1_AS + 2 * G1_BS) * 4)

__global__ void __launch_bounds__(256, 2) gemm1_both(
        const float* __restrict__ Aq, const float* __restrict__ Ar,
        const float* __restrict__ Wq, const float* __restrict__ Wr,
        const float* __restrict__ gq, const float* __restrict__ gr,
        const float* __restrict__ bq, const float* __restrict__ br,
        const float* __restrict__ biasq, const float* __restrict__ biasr,
        const float* __restrict__ mean, const float* __restrict__ rstd,
        float* __restrict__ Cb) {
    int z = blockIdx.z;
    const float* A = z ? Ar : Aq;
    const float* W = z ? Wr : Wq;
    const float* gamma = z ? gr : gq;
    const float* beta = z ? br : bq;
    const float* bias = z ? biasr : biasq;
    float* C = Cb + (size_t)z * Bn * D2n;
    const float* mub = mean + z * Bn;
    const float* rsb = rstd + z * Bn;

    uint32_t* sm = (uint32_t*)dynsm;
    uint32_t* Asm[2] = { sm, sm + G1_AS };
    uint32_t* Bsm[2] = { sm + 2 * G1_AS, sm + 2 * G1_AS + G1_BS };

    int tid = threadIdx.x;
    int wid = tid >> 5, lane = tid & 31;
    int wm = wid & 3, wn = wid >> 2;
    int g = lane >> 2, tig = lane & 3;
    int m0 = blockIdx.y * 128, n0 = blockIdx.x * 64;
    int q = tid >> 3, f4 = tid & 7;

    const float4* Arow[4];
    float mu[4], rsd[4];
#pragma unroll
    for (int j = 0; j < 4; j++) {
        int r = m0 + q + 32 * j;
        Arow[j] = (const float4*)(A + (size_t)r * Hn);
        mu[j] = mub[r];
        rsd[j] = rsb[r];
    }
    const float4* Brow[2];
#pragma unroll
    for (int j = 0; j < 2; j++) Brow[j] = (const float4*)(W + (size_t)(n0 + q + 32 * j) * Hn);
    const float4* g4p = (const float4*)gamma;
    const float4* b4p = (const float4*)beta;

    float acc[2][4][4] = {};
    float4 pA[4], pB[2], pG, pBt;

    const int NT = Hn / 32;  // 64

    pG = g4p[f4]; pBt = b4p[f4];
#pragma unroll
    for (int j = 0; j < 4; j++) pA[j] = Arow[j][f4];
#pragma unroll
    for (int j = 0; j < 2; j++) pB[j] = Brow[j][f4];
#pragma unroll
    for (int j = 0; j < 4; j++) {
        float x0 = (pA[j].x - mu[j]) * rsd[j] * pG.x + pBt.x;
        float x1 = (pA[j].y - mu[j]) * rsd[j] * pG.y + pBt.y;
        float x2 = (pA[j].z - mu[j]) * rsd[j] * pG.z + pBt.z;
        float x3 = (pA[j].w - mu[j]) * rsd[j] * pG.w + pBt.w;
        uint4 u = { f2tf32(x0), f2tf32(x1), f2tf32(x2), f2tf32(x3) };
        *(uint4*)&Asm[0][(q + 32 * j) * G1_LD + f4 * 4] = u;
    }
#pragma unroll
    for (int j = 0; j < 2; j++) {
        uint4 u = { f2tf32(pB[j].x), f2tf32(pB[j].y), f2tf32(pB[j].z), f2tf32(pB[j].w) };
        *(uint4*)&Bsm[0][(q + 32 * j) * G1_LD + f4 * 4] = u;
    }
    __syncthreads();

    for (int t = 0; t < NT; t++) {
        int cur = t & 1;
        if (t + 1 < NT) {
            pG = g4p[(t + 1) * 8 + f4]; pBt = b4p[(t + 1) * 8 + f4];
#pragma unroll
            for (int j = 0; j < 4; j++) pA[j] = Arow[j][(t + 1) * 8 + f4];
#pragma unroll
            for (int j = 0; j < 2; j++) pB[j] = Brow[j][(t + 1) * 8 + f4];
        }
        const uint32_t* Ab = Asm[cur];
        const uint32_t* Bb = Bsm[cur];
#pragma unroll
        for (int ks = 0; ks < 4; ks++) {
            int k = ks * 8;
            uint32_t bf[4][2];
#pragma unroll
            for (int nt = 0; nt < 4; nt++) {
                int nc = wn * 32 + nt * 8 + g;
                bf[nt][0] = Bb[nc * G1_LD + k + tig];
                bf[nt][1] = Bb[nc * G1_LD + k + tig + 4];
            }
#pragma unroll
            for (int mt = 0; mt < 2; mt++) {
                int mr = wm * 32 + mt * 16 + g;
                uint32_t a0 = Ab[mr * G1_LD + k + tig];
                uint32_t a1 = Ab[(mr + 8) * G1_LD + k + tig];
                uint32_t a2 = Ab[mr * G1_LD + k + tig + 4];
                uint32_t a3 = Ab[(mr + 8) * G1_LD + k + tig + 4];
#pragma unroll
                for (int nt = 0; nt < 4; nt++)
                    mma_tf32(acc[mt][nt], a0, a1, a2, a3, bf[nt][0], bf[nt][1]);
            }
        }
        if (t + 1 < NT) {
            int nxt = cur ^ 1;
#pragma unroll
            for (int j = 0; j < 4; j++) {
                float x0 = (pA[j].x - mu[j]) * rsd[j] * pG.x + pBt.x;
                float x1 = (pA[j].y - mu[j]) * rsd[j] * pG.y + pBt.y;
                float x2 = (pA[j].z - mu[j]) * rsd[j] * pG.z + pBt.z;
                float x3 = (pA[j].w - mu[j]) * rsd[j] * pG.w + pBt.w;
                uint4 u = { f2tf32(x0), f2tf32(x1), f2tf32(x2), f2tf32(x3) };
                *(uint4*)&Asm[nxt][(q + 32 * j) * G1_LD + f4 * 4] = u;
            }
#pragma unroll
            for (int j = 0; j < 2; j++) {
                uint4 u = { f2tf32(pB[j].x), f2tf32(pB[j].y), f2tf32(pB[j].z), f2tf32(pB[j].w) };
                *(uint4*)&Bsm[nxt][(q + 32 * j) * G1_LD + f4 * 4] = u;
            }
        }
        __syncthreads();
    }

#pragma unroll
    for (int mt = 0; mt < 2; mt++) {
#pragma unroll
        for (int nt = 0; nt < 4; nt++) {
            int n = n0 + wn * 32 + nt * 8 + 2 * tig;
            float bv0 = bias[n], bv1 = bias[n + 1];
#pragma unroll
            for (int rr = 0; rr < 2; rr++) {
                int m = m0 + wm * 32 + mt * 16 + g + rr * 8;
                float v0 = acc[mt][nt][rr * 2 + 0] + bv0;
                float v1 = acc[mt][nt][rr * 2 + 1] + bv1;
                v0 = 0.5f * v0 * (1.f + erff(v0 * 0.7071067811865475f));
                v1 = 0.5f * v1 * (1.f + erff(v1 * 0.7071067811865475f));
                float2 o = {v0, v1};
                *(float2*)(C + (size_t)m * D2n + n) = o;
            }
        }
    }
}

// ---------------- GEMM2 via tf32 mma + fused bias + l2norm. BM=64, grid (64, 2) ----------------
#define G2_LD 36
#define G2_AW (64 * G2_LD)
#define G2_BW (128 * G2_LD)
#define G2_SMEM ((2 * G2_AW + 2 * G2_BW) * 4)

__global__ void __launch_bounds__(256, 2) gemm2_mma(
        const float* __restrict__ Hb,
        const float* __restrict__ W2q, const float* __restrict__ W2r,
        const float* __restrict__ b2q, const float* __restrict__ b2r,
        float* __restrict__ Zq, float* __restrict__ Zr) {
    int z = blockIdx.y;
    const float* Hin = Hb + (size_t)z * Bn * D2n;
    const float* W2 = z ? W2r : W2q;
    const float* b2 = z ? b2r : b2q;
    float* Z = z ? Zr : Zq;

    uint32_t* sm = (uint32_t*)dynsm;
    uint32_t* Asm[2] = { sm, sm + G2_AW };
    uint32_t* Bsm[2] = { sm + 2 * G2_AW, sm + 2 * G2_AW + G2_BW };

    int tid = threadIdx.x;
    int wid = tid >> 5, lane = tid & 31;
    int wm = wid & 1, wn = wid >> 1;         // 2 m-warps x 4 n-warps, warptile 32x32
    int g = lane >> 2, tig = lane & 3;
    int m0 = blockIdx.x * 64;
    int q8 = tid >> 3, f4 = tid & 7;

    const float4* Arow[2];
    const float4* Brow[4];
#pragma unroll
    for (int j = 0; j < 2; j++) Arow[j] = (const float4*)(Hin + (size_t)(m0 + q8 + 32 * j) * D2n);
#pragma unroll
    for (int j = 0; j < 4; j++) Brow[j] = (const float4*)(W2 + (size_t)(q8 + 32 * j) * D2n);

    float acc[2][4][4] = {};
    float4 pA[2], pB[4];
    const int NT = D2n / 32;  // 8

#pragma unroll
    for (int j = 0; j < 2; j++) pA[j] = Arow[j][f4];
#pragma unroll
    for (int j = 0; j < 4; j++) pB[j] = Brow[j][f4];
#pragma unroll
    for (int j = 0; j < 2; j++) {
        uint4 u = { f2tf32(pA[j].x), f2tf32(pA[j].y), f2tf32(pA[j].z), f2tf32(pA[j].w) };
        *(uint4*)&Asm[0][(q8 + 32 * j) * G2_LD + f4 * 4] = u;
    }
#pragma unroll
    for (int j = 0; j < 4; j++) {
        uint4 u = { f2tf32(pB[j].x), f2tf32(pB[j].y), f2tf32(pB[j].z), f2tf32(pB[j].w) };
        *(uint4*)&Bsm[0][(q8 + 32 * j) * G2_LD + f4 * 4] = u;
    }
    __syncthreads();

    for (int t = 0; t < NT; t++) {
        int cur = t & 1;
        if (t + 1 < NT) {
#pragma unroll
            for (int j = 0; j < 2; j++) pA[j] = Arow[j][(t + 1) * 8 + f4];
#pragma unroll
            for (int j = 0; j < 4; j++) pB[j] = Brow[j][(t + 1) * 8 + f4];
        }
        const uint32_t* Ab = Asm[cur];
        const uint32_t* Bb = Bsm[cur];
#pragma unroll
        for (int ks = 0; ks < 4; ks++) {
            int k = ks * 8;
            uint32_t bf[4][2];
#pragma unroll
            for (int nt = 0; nt < 4; nt++) {
                int nc = wn * 32 + nt * 8 + g;
                bf[nt][0] = Bb[nc * G2_LD + k + tig];
                bf[nt][1] = Bb[nc * G2_LD + k + tig + 4];
            }
#pragma unroll
            for (int mt = 0; mt < 2; mt++) {
                int mr = wm * 32 + mt * 16 + g;
                uint32_t a0 = Ab[mr * G2_LD + k + tig];
                uint32_t a1 = Ab[(mr + 8) * G2_LD + k + tig];
                uint32_t a2 = Ab[mr * G2_LD + k + tig + 4];
                uint32_t a3 = Ab[(mr + 8) * G2_LD + k + tig + 4];
#pragma unroll
                for (int nt = 0; nt < 4; nt++)
                    mma_tf32(acc[mt][nt], a0, a1, a2, a3, bf[nt][0], bf[nt][1]);
            }
        }
        if (t + 1 < NT) {
            int nxt = cur ^ 1;
#pragma unroll
            for (int j = 0; j < 2; j++) {
                uint4 u = { f2tf32(pA[j].x), f2tf32(pA[j].y), f2tf32(pA[j].z), f2tf32(pA[j].w) };
                *(uint4*)&Asm[nxt][(q8 + 32 * j) * G2_LD + f4 * 4] = u;
            }
#pragma unroll
            for (int j = 0; j < 4; j++) {
                uint4 u = { f2tf32(pB[j].x), f2tf32(pB[j].y), f2tf32(pB[j].z), f2tf32(pB[j].w) };
                *(uint4*)&Bsm[nxt][(q8 + 32 * j) * G2_LD + f4 * 4] = u;
            }
        }
        __syncthreads();
    }

    // epilogue: bias, per-row sum of squares across 4 n-warps, l2norm, write tf32 Z
    float p[2][2] = {};
#pragma unroll
    for (int mt = 0; mt < 2; mt++)
#pragma unroll
        for (int nt = 0; nt < 4; nt++) {
            int c = wn * 32 + nt * 8 + 2 * tig;
            float b0 = b2[c], b1 = b2[c + 1];
            acc[mt][nt][0] += b0; acc[mt][nt][1] += b1;
            acc[mt][nt][2] += b0; acc[mt][nt][3] += b1;
            p[mt][0] += acc[mt][nt][0] * acc[mt][nt][0] + acc[mt][nt][1] * acc[mt][nt][1];
            p[mt][1] += acc[mt][nt][2] * acc[mt][nt][2] + acc[mt][nt][3] * acc[mt][nt][3];
        }
#pragma unroll
    for (int mt = 0; mt < 2; mt++)
#pragma unroll
        for (int rr = 0; rr < 2; rr++) {
            p[mt][rr] += __shfl_xor_sync(~0u, p[mt][rr], 1);
            p[mt][rr] += __shfl_xor_sync(~0u, p[mt][rr], 2);
        }
    float* norms = (float*)sm;  // [wn][64]
    if (tig == 0) {
#pragma unroll
        for (int mt = 0; mt < 2; mt++)
#pragma unroll
            for (int rr = 0; rr < 2; rr++)
                norms[wn * 64 + wm * 32 + mt * 16 + rr * 8 + g] = p[mt][rr];
    }
    __syncthreads();
#pragma unroll
    for (int mt = 0; mt < 2; mt++)
#pragma unroll
        for (int rr = 0; rr < 2; rr++) {
            int rl = wm * 32 + mt * 16 + rr * 8 + g;
            float tot = norms[rl] + norms[64 + rl] + norms[128 + rl] + norms[192 + rl];
            float rn = 1.f / fmaxf(sqrtf(tot), 1e-12f);
            int row = m0 + rl;
#pragma unroll
            for (int nt = 0; nt < 4; nt++) {
                int c = wn * 32 + nt * 8 + 2 * tig;
                float2 o = { __uint_as_float(f2tf32(acc[mt][nt][rr * 2 + 0] * rn)),
                             __uint_as_float(f2tf32(acc[mt][nt][rr * 2 + 1] * rn)) };
                *(float2*)&Z[(size_t)row * Dn + c] = o;
            }
        }
}

// ---------------- Attention v3: P stays in registers (l-split = PV k-dim per warp) ----------------
// 256 threads = 8 warps: wq = wid>>2 (q-group of 16 rows), ws = wid&3 (l-subset of 16 within 64-tile).
// Each warp: scores for its 16 l-cols, exp in-register, shfl-reshape P into A-fragments,
// PV over ALL d=128 with its l-subset as k-dim. O reduced across the 4 ws warps at the end.
#define A_LDZ 136
#define A_ZQW (32 * A_LDZ)
#define A_ZBW (64 * A_LDZ)
#define ATTN_SMEM ((A_ZQW + 2 * A_ZBW) * 4)
__global__ void __launch_bounds__(256, 1) attn_mma(const float* __restrict__ Zq, const float* __restrict__ Zr,
                                                   float* __restrict__ Rbar, float* __restrict__ ent) {
    uint32_t* smw = (uint32_t*)dynsm;
    uint32_t* zqb = smw;
    uint32_t* zbuf[2] = { smw + A_ZQW, smw + A_ZQW + A_ZBW };
    __shared__ float zpart[4][32];
    __shared__ float tpart[4][32];

    int tid = threadIdx.x;
    int wid = tid >> 5, lane = tid & 31;
    int wq = wid >> 2, ws = wid & 3;
    int g = lane >> 2, tig = lane & 3;
    int q0 = blockIdx.x * 32;
    int qr = wq * 16;
    const float scale = 0.08838834764831845f;  // 1/sqrt(128)

    uint32_t zq_sb = (uint32_t)__cvta_generic_to_shared(zqb);
    uint32_t zb_sb[2] = { (uint32_t)__cvta_generic_to_shared(zbuf[0]),
                          (uint32_t)__cvta_generic_to_shared(zbuf[1]) };

#pragma unroll
    for (int j = 0; j < 4; j++) {
        int i = tid + j * 256, r = i >> 5, c4 = (i & 31) * 4;
        cpa16(zq_sb + (r * A_LDZ + c4) * 4, Zq + (size_t)(q0 + r) * Dn + c4);
    }
#pragma unroll
    for (int j = 0; j < 8; j++) {
        int i = tid + j * 256, r = i >> 5, c4 = (i & 31) * 4;
        cpa16(zb_sb[0] + (r * A_LDZ + c4) * 4, Zr + (size_t)r * Dn + c4);
    }
    CP_COMMIT();
#pragma unroll
    for (int j = 0; j < 8; j++) {
        int i = tid + j * 256, r = i >> 5, c4 = (i & 31) * 4;
        cpa16(zb_sb[1] + (r * A_LDZ + c4) * 4, Zr + (size_t)(64 + r) * Dn + c4);
    }
    CP_COMMIT();
    CP_WAIT1();
    __syncthreads();

    // A fragments of Zq for scores (persistent)
    uint32_t aq[16][4];
#pragma unroll
    for (int kt = 0; kt < 16; kt++) {
        aq[kt][0] = zqb[(qr + g) * A_LDZ + kt * 8 + tig];
        aq[kt][1] = zqb[(qr + g + 8) * A_LDZ + kt * 8 + tig];
        aq[kt][2] = zqb[(qr + g) * A_LDZ + kt * 8 + tig + 4];
        aq[kt][3] = zqb[(qr + g + 8) * A_LDZ + kt * 8 + tig + 4];
    }

    float O[16][4] = {};
    float zs0 = 0.f, zs1 = 0.f, ts0 = 0.f, ts1 = 0.f;
    const int NT = Lnn / 64;  // 64

    for (int t = 0; t < NT; t++) {
        int cur = t & 1;
        if (t > 0) {
            CP_WAIT1();
            __syncthreads();
        }
        const uint32_t* zb = zbuf[cur];

        // scores: warp's 16 l-cols, parity-split accumulators
        float sc[2][2][4] = {};
#pragma unroll
        for (int kt = 0; kt < 16; kt++) {
            int par = kt & 1;
#pragma unroll
            for (int nt = 0; nt < 2; nt++) {
                int lb = ws * 16 + nt * 8 + g;
                uint32_t b0 = zb[lb * A_LDZ + kt * 8 + tig];
                uint32_t b1 = zb[lb * A_LDZ + kt * 8 + tig + 4];
                mma_tf32(sc[nt][par], aq[kt][0], aq[kt][1], aq[kt][2], aq[kt][3], b0, b1);
            }
        }

        // exp in-register + entropy accumulation
        float pv[2][4];
#pragma unroll
        for (int nt = 0; nt < 2; nt++) {
            float s0 = (sc[nt][0][0] + sc[nt][1][0]) * scale;
            float s1 = (sc[nt][0][1] + sc[nt][1][1]) * scale;
            float s2 = (sc[nt][0][2] + sc[nt][1][2]) * scale;
            float s3 = (sc[nt][0][3] + sc[nt][1][3]) * scale;
            float p0 = __expf(s0), p1 = __expf(s1), p2 = __expf(s2), p3 = __expf(s3);
            zs0 += p0 + p1; ts0 += p0 * s0 + p1 * s1;
            zs1 += p2 + p3; ts1 += p2 * s2 + p3 * s3;
            pv[nt][0] = p0; pv[nt][1] = p1; pv[nt][2] = p2; pv[nt][3] = p3;
        }

        // shuffle P (accumulator layout) into A-fragment layout, cvt tf32
        uint32_t ap[2][4];
        int src = 4 * g + (tig >> 1);
        bool odd = (tig & 1);
#pragma unroll
        for (int j = 0; j < 2; j++) {
            float q0v = __shfl_sync(~0u, pv[j][0], src);
            float q1v = __shfl_sync(~0u, pv[j][1], src);
            float q2v = __shfl_sync(~0u, pv[j][2], src);
            float q3v = __shfl_sync(~0u, pv[j][3], src);
            float r0v = __shfl_sync(~0u, pv[j][0], src + 2);
            float r1v = __shfl_sync(~0u, pv[j][1], src + 2);
            float r2v = __shfl_sync(~0u, pv[j][2], src + 2);
            float r3v = __shfl_sync(~0u, pv[j][3], src + 2);
            ap[j][0] = f2tf32(odd ? q1v : q0v);
            ap[j][1] = f2tf32(odd ? q3v : q2v);
            ap[j][2] = f2tf32(odd ? r1v : r0v);
            ap[j][3] = f2tf32(odd ? r3v : r2v);
        }

        // PV: k-dim = warp's 16 l-cols (2 steps), all 128 d (16 n-tiles)
#pragma unroll
        for (int j = 0; j < 2; j++) {
            int lr = ws * 16 + j * 8;
#pragma unroll
            for (int nt = 0; nt < 16; nt++) {
                int db = nt * 8 + g;
                uint32_t b0 = zb[(lr + tig) * A_LDZ + db];
                uint32_t b1 = zb[(lr + tig + 4) * A_LDZ + db];
                mma_tf32(O[nt], ap[j][0], ap[j][1], ap[j][2], ap[j][3], b0, b1);
            }
        }
        __syncthreads();   // all reads of zbuf[cur] done before restaging

        if (t + 2 < NT) {
            const float* srcp = Zr + (size_t)(t + 2) * 64 * Dn;
#pragma unroll
            for (int j = 0; j < 8; j++) {
                int i = tid + j * 256, r = i >> 5, c4 = (i & 31) * 4;
                cpa16(zb_sb[cur] + (r * A_LDZ + c4) * 4, srcp + (size_t)r * Dn + c4);
            }
        }
        CP_COMMIT();
    }

    // entropy partials (per-warp l-subset)
    zs0 += __shfl_xor_sync(~0u, zs0, 1); zs0 += __shfl_xor_sync(~0u, zs0, 2);
    zs1 += __shfl_xor_sync(~0u, zs1, 1); zs1 += __shfl_xor_sync(~0u, zs1, 2);
    ts0 += __shfl_xor_sync(~0u, ts0, 1); ts0 += __shfl_xor_sync(~0u, ts0, 2);
    ts1 += __shfl_xor_sync(~0u, ts1, 1); ts1 += __shfl_xor_sync(~0u, ts1, 2);
    if (tig == 0) {
        zpart[ws][qr + g] = zs0; zpart[ws][qr + g + 8] = zs1;
        tpart[ws][qr + g] = ts0; tpart[ws][qr + g + 8] = ts1;
    }

    // dump per-warp O into smem [ws][32][132] (reuse whole dynamic smem)
    float* Osm = (float*)smw;
#pragma unroll
    for (int nt = 0; nt < 16; nt++) {
        int dc = nt * 8 + 2 * tig;
        float* base = Osm + ws * 32 * 132;
        base[(qr + g) * 132 + dc] = O[nt][0];
        base[(qr + g) * 132 + dc + 1] = O[nt][1];
        base[(qr + g + 8) * 132 + dc] = O[nt][2];
        base[(qr + g + 8) * 132 + dc + 1] = O[nt][3];
    }
    __syncthreads();

    // reduce across 4 warps, l2-normalize, write Rbar; entropy
    int row = tid >> 3, oct = tid & 7;
    float4 v[4];
    float sq = 0.f;
#pragma unroll
    for (int j = 0; j < 4; j++) {
        int off = row * 132 + oct * 16 + j * 4;
        float4 a0 = *(float4*)&Osm[off];
        float4 a1 = *(float4*)&Osm[32 * 132 + off];
        float4 a2 = *(float4*)&Osm[2 * 32 * 132 + off];
        float4 a3 = *(float4*)&Osm[3 * 32 * 132 + off];
        float4 a = { a0.x + a1.x + a2.x + a3.x, a0.y + a1.y + a2.y + a3.y,
                     a0.z + a1.z + a2.z + a3.z, a0.w + a1.w + a2.w + a3.w };
        v[j] = a;
        sq += a.x * a.x + a.y * a.y + a.z * a.z + a.w * a.w;
    }
    sq += __shfl_xor_sync(~0u, sq, 1);
    sq += __shfl_xor_sync(~0u, sq, 2);
    sq += __shfl_xor_sync(~0u, sq, 4);
    float rn = 1.f / fmaxf(sqrtf(sq), 1e-12f);
    float* dst = Rbar + (size_t)(q0 + row) * Dn + oct * 16;
#pragma unroll
    for (int j = 0; j < 4; j++) {
        float4 o = {v[j].x * rn, v[j].y * rn, v[j].z * rn, v[j].w * rn};
        *(float4*)(dst + j * 4) = o;
    }
    if (oct == 0) {
        float zsum = zpart[0][row] + zpart[1][row] + zpart[2][row] + zpart[3][row];
        float tsum = tpart[0][row] + tpart[1][row] + tpart[2][row] + tpart[3][row];
        ent[q0 + row] = logf(zsum) - tsum / zsum;
    }
}

// ---------------- Final: dec MLP + scalar heads (W1 pre-transposed) ----------------
__global__ void final_kernel(const float* __restrict__ Zq, const float* __restrict__ Rbar,
                             const float* __restrict__ ent,
                             const float* __restrict__ gd, const float* __restrict__ bd,
                             const float* __restrict__ W1T, const float* __restrict__ b1d,
                             const float* __restrict__ W2d, const float* __restrict__ b2d,
                             const float* __restrict__ beta, const float* __restrict__ Wlen,
                             const float* __restrict__ blen, float* __restrict__ out) {
    __shared__ float raw[8][D2n];
    __shared__ float nrm[8][D2n];
    __shared__ float part[8][128];
    __shared__ float coss[8];
    int r0 = blockIdx.x * 8, tid = threadIdx.x;
    for (int i = tid; i < 8 * Dn; i += 128) {
        int r = i >> 7, d = i & 127;
        raw[r][d] = Zq[(size_t)(r0 + r) * Dn + d];
        raw[r][128 + d] = Rbar[(size_t)(r0 + r) * Dn + d];
    }
    __syncthreads();
    int w = tid >> 5, lane = tid & 31;
#pragma unroll
    for (int rr = 0; rr < 2; rr++) {
        int r = 2 * w + rr;
        float cs = 0.f, smv = 0.f;
        for (int k = lane; k < D2n; k += 32) smv += raw[r][k];
        for (int k = lane; k < Dn; k += 32) cs += raw[r][k] * raw[r][128 + k];
#pragma unroll
        for (int o = 16; o > 0; o >>= 1) { smv += __shfl_xor_sync(~0u, smv, o); cs += __shfl_xor_sync(~0u, cs, o); }
        float mean = smv * (1.f / D2n);
        float vq = 0.f;
        for (int k = lane; k < D2n; k += 32) { float d = raw[r][k] - mean; vq += d * d; }
#pragma unroll
        for (int o = 16; o > 0; o >>= 1) vq += __shfl_xor_sync(~0u, vq, o);
        float rstd = rsqrtf(vq * (1.f / D2n) + 1e-5f);
        for (int k = lane; k < D2n; k += 32) nrm[r][k] = (raw[r][k] - mean) * rstd * gd[k] + bd[k];
        if (lane == 0) coss[r] = cs;
    }
    __syncthreads();
    float b1 = b1d[tid];
    float acc[8] = {b1, b1, b1, b1, b1, b1, b1, b1};
    for (int k = 0; k < D2n; k += 4) {
        float wv0 = W1T[(k + 0) * 128 + tid];
        float wv1 = W1T[(k + 1) * 128 + tid];
        float wv2 = W1T[(k + 2) * 128 + tid];
        float wv3 = W1T[(k + 3) * 128 + tid];
#pragma unroll
        for (int r = 0; r < 8; r++) {
            float4 h4 = *(const float4*)&nrm[r][k];
            acc[r] += h4.x * wv0 + h4.y * wv1 + h4.z * wv2 + h4.w * wv3;
        }
    }
    float w2 = W2d[tid];
#pragma unroll
    for (int r = 0; r < 8; r++) {
        float v = acc[r];
        v = 0.5f * v * (1.f + erff(v * 0.7071067811865475f));
        part[r][tid] = v * w2;
    }
    __syncthreads();
#pragma unroll
    for (int rr = 0; rr < 2; rr++) {
        int r = 2 * w + rr;
        float s = 0.f;
        for (int k = lane; k < 128; k += 32) s += part[r][k];
#pragma unroll
        for (int o = 16; o > 0; o >>= 1) s += __shfl_xor_sync(~0u, s, o);
        if (lane == 0) {
            float raw_logit = s + b2d[0];
            float u = ent[r0 + r] * (1.f / logf((float)Lnn));
            float cs = coss[r];
            float dl = Wlen[0] * cs + Wlen[1] * u + blen[0];
            float lf = tanhf(dl);
            float dt = beta[0] * u + beta[1] * lf;
            dt = fminf(fmaxf(dt, -0.5f), 0.5f);
            out[r0 + r] = raw_logit;
            out[Bn + r0 + r] = dt;
        }
    }
}

// ---------------- host launcher ----------------
extern "C" void kernel_launch(void* const* d_in, const int* in_sizes, int n_in,
                              void* d_out, int out_size) {
    const float* q    = (const float*)d_in[0];
    const float* R    = (const float*)d_in[1];
    const float* lnqg = (const float*)d_in[2];
    const float* lnqb = (const float*)d_in[3];
    const float* W1q  = (const float*)d_in[4];
    const float* b1q  = (const float*)d_in[5];
    const float* W2q  = (const float*)d_in[6];
    const float* b2q  = (const float*)d_in[7];
    const float* lnrg = (const float*)d_in[8];
    const float* lnrb = (const float*)d_in[9];
    const float* W1r  = (const float*)d_in[10];
    const float* b1r  = (const float*)d_in[11];
    const float* W2r  = (const float*)d_in[12];
    const float* b2r  = (const float*)d_in[13];
    const float* lndg = (const float*)d_in[14];
    const float* lndb = (const float*)d_in[15];
    const float* W1d  = (const float*)d_in[16];
    const float* b1d  = (const float*)d_in[17];
    const float* W2d  = (const float*)d_in[18];
    const float* b2d  = (const float*)d_in[19];
    const float* beta = (const float*)d_in[20];
    const float* Wlen = (const float*)d_in[21];
    const float* blen = (const float*)d_in[22];
    float* out = (float*)d_out;

    float *hb, *zq, *zr, *rb, *en, *mu, *rs, *w1t;
    cudaGetSymbolAddress((void**)&hb, g_Hb);
    cudaGetSymbolAddress((void**)&zq, g_Zq);
    cudaGetSymbolAddress((void**)&zr, g_Zr);
    cudaGetSymbolAddress((void**)&rb, g_Rbar);
    cudaGetSymbolAddress((void**)&en, g_ent);
    cudaGetSymbolAddress((void**)&mu, g_mu);
    cudaGetSymbolAddress((void**)&rs, g_rs);
    cudaGetSymbolAddress((void**)&w1t, g_W1T);

    cudaFuncSetAttribute(gemm1_both, cudaFuncAttributeMaxDynamicSharedMemorySize, G1_SMEM);
    cudaFuncSetAttribute(gemm2_mma, cudaFuncAttributeMaxDynamicSharedMemorySize, G2_SMEM);
    cudaFuncSetAttribute(attn_mma, cudaFuncAttributeMaxDynamicSharedMemorySize, ATTN_SMEM);

    row_stats_both<<<dim3(Bn / 8, 2), 256>>>(q, R, mu, rs);
    transpose_w1<<<dim3(8, 4), dim3(32, 8)>>>(W1d, w1t);
    gemm1_both<<<dim3(D2n / 64, Bn / 128, 2), 256, G1_SMEM>>>(
        q, R, W1q, W1r, lnqg, lnrg, lnqb, lnrb, b1q, b1r, mu, rs, hb);
    gemm2_mma<<<dim3(Bn / 64, 2), 256, G2_SMEM>>>(hb, W2q, W2r, b2q, b2r, zq, zr);
    attn_mma<<<Bn / 32, 256, ATTN_SMEM>>>(zq, zr, rb, en);
    final_kernel<<<Bn / 8, 128>>>(zq, rb, en, lndg, lndb, w1t, b1d, W2d, b2d,
                                  beta, Wlen, blen, out);
}